// round 1
// baseline (speedup 1.0000x reference)
#include <cuda_runtime.h>

#define NB 8
#define LQN 5440
#define CD 256
#define RR 43520          // NB*LQN
#define DFFN 1024

// ---------------- scratch (static device arrays; no allocation) ----------------
__device__ float g_V  [RR * CD];     // value projection
__device__ float g_OFF[RR * CD];     // sampling offsets (NH,NL,NP,2)
__device__ float g_AW [RR * 128];    // attention weights (NH,NL*NP) -> softmaxed
__device__ float g_ATT[RR * CD];     // deform-attn output
__device__ float g_S  [RR * CD];     // src + src2 (pre-LN1)
__device__ float g_X  [RR * CD];     // LN1 output
__device__ float g_H  [RR * DFFN];   // relu(ff1)
__device__ float g_Y  [RR * CD];     // x + ff2 (pre-LN2)

// ---------------- SGEMM: C[R,N] = op(A)[R,K] @ B[K,N] + bias (+res, relu, mask) ---
// BM=BN=128, BK=8, 256 threads, 8x8 per thread.
template<bool ADD_POS, bool RELU, bool HAS_RES, bool MASK>
__global__ __launch_bounds__(256, 2)
void sgemm_k(const float* __restrict__ A, const float* __restrict__ A2,
             const float* __restrict__ B, const float* __restrict__ bias,
             const float* __restrict__ Res, const unsigned char* __restrict__ mask,
             float* __restrict__ Cout, int K, int Nout)
{
    __shared__ float As[8][128];
    __shared__ float Bs[8][128];

    const int tid  = threadIdx.x;
    const int brow = blockIdx.x * 128;
    const int bcol = blockIdx.y * 128;

    const int arow = tid >> 1;          // 0..127
    const int acol = (tid & 1) << 2;    // 0 or 4
    const int bkr  = tid >> 5;          // 0..7
    const int bnc  = (tid & 31) << 2;   // 0..124

    const float* Ap = A + (long)(brow + arow) * K + acol;
    const float* Pp = ADD_POS ? (A2 + (long)(brow + arow) * K + acol) : nullptr;
    const float* Bp = B + (long)bkr * Nout + bcol + bnc;

    const int tx = tid & 15, ty = tid >> 4;

    float acc[8][8];
#pragma unroll
    for (int i = 0; i < 8; i++)
#pragma unroll
        for (int j = 0; j < 8; j++) acc[i][j] = 0.f;

    for (int k0 = 0; k0 < K; k0 += 8) {
        float4 av = *reinterpret_cast<const float4*>(Ap + k0);
        if (ADD_POS) {
            float4 pv = *reinterpret_cast<const float4*>(Pp + k0);
            av.x += pv.x; av.y += pv.y; av.z += pv.z; av.w += pv.w;
        }
        As[acol + 0][arow] = av.x;
        As[acol + 1][arow] = av.y;
        As[acol + 2][arow] = av.z;
        As[acol + 3][arow] = av.w;
        *reinterpret_cast<float4*>(&Bs[bkr][bnc]) =
            *reinterpret_cast<const float4*>(Bp + (long)k0 * Nout);
        __syncthreads();
#pragma unroll
        for (int k = 0; k < 8; k++) {
            float4 a0 = *reinterpret_cast<const float4*>(&As[k][ty * 8]);
            float4 a1 = *reinterpret_cast<const float4*>(&As[k][ty * 8 + 4]);
            float4 b0 = *reinterpret_cast<const float4*>(&Bs[k][tx * 8]);
            float4 b1 = *reinterpret_cast<const float4*>(&Bs[k][tx * 8 + 4]);
            float ra[8] = {a0.x, a0.y, a0.z, a0.w, a1.x, a1.y, a1.z, a1.w};
            float rb[8] = {b0.x, b0.y, b0.z, b0.w, b1.x, b1.y, b1.z, b1.w};
#pragma unroll
            for (int i = 0; i < 8; i++)
#pragma unroll
                for (int j = 0; j < 8; j++) acc[i][j] += ra[i] * rb[j];
        }
        __syncthreads();
    }

#pragma unroll
    for (int i = 0; i < 8; i++) {
        int row = brow + ty * 8 + i;
        float ms = 1.f;
        if (MASK) ms = mask[row] ? 0.f : 1.f;
#pragma unroll
        for (int j = 0; j < 8; j++) {
            int col = bcol + tx * 8 + j;
            float v = acc[i][j] + bias[col];
            if (MASK) v *= ms;
            if (RELU) v = fmaxf(v, 0.f);
            if (HAS_RES) v += Res[(long)row * Nout + col];
            Cout[(long)row * Nout + col] = v;
        }
    }
}

// ---------------- softmax over NL*NP=16 per (row, head) ----------------
__global__ void softmax16_k(float* __restrict__ aw)
{
    int i = blockIdx.x * blockDim.x + threadIdx.x;
    if (i >= RR * 8) return;
    float* p = aw + (long)i * 16;
    float e[16];
    float mx = -1e30f;
#pragma unroll
    for (int j = 0; j < 16; j++) { e[j] = p[j]; mx = fmaxf(mx, e[j]); }
    float s = 0.f;
#pragma unroll
    for (int j = 0; j < 16; j++) { e[j] = expf(e[j] - mx); s += e[j]; }
    float inv = 1.f / s;
#pragma unroll
    for (int j = 0; j < 16; j++) p[j] = e[j] * inv;
}

// ---------------- deformable sampling: block = (n,q), warp = head, lane = channel --
__global__ void deform_k(const float* __restrict__ V, const float* __restrict__ OFF,
                         const float* __restrict__ AW, const float* __restrict__ REF,
                         float* __restrict__ OUT)
{
    const int row = blockIdx.x;           // n*LQ + q
    const int h = threadIdx.x >> 5;
    const int d = threadIdx.x & 31;
    const int n = row / LQN;

    const float* off = OFF + (long)row * 256 + h * 32;
    const float* aw  = AW  + (long)row * 128 + h * 16;
    const float* ref = REF + (long)row * 8;
    const float* Vb  = V + (long)n * LQN * 256 + h * 32 + d;

    const int   Wt[4]   = {64, 32, 16, 8};
    const int   St[4]   = {0, 4096, 5120, 5376};
    const float invW[4] = {1.f/64.f, 1.f/32.f, 1.f/16.f, 1.f/8.f};

    float acc = 0.f;
#pragma unroll
    for (int l = 0; l < 4; l++) {
        const int W = Wt[l], H = Wt[l];
        const float* Vl = Vb + (long)St[l] * 256;
        const float rx = ref[l * 2 + 0], ry = ref[l * 2 + 1];
#pragma unroll
        for (int p = 0; p < 4; p++) {
            float ox = off[l * 8 + p * 2 + 0];
            float oy = off[l * 8 + p * 2 + 1];
            float lx = rx + ox * invW[l];       // /W exact (power of 2)
            float ly = ry + oy * invW[l];
            float gx = 2.f * lx - 1.f, gy = 2.f * ly - 1.f;
            float x = (gx + 1.f) * (W * 0.5f) - 0.5f;
            float y = (gy + 1.f) * (H * 0.5f) - 0.5f;
            float x0f = floorf(x), y0f = floorf(y);
            float wx = x - x0f, wy = y - y0f;
            int x0 = (int)x0f, y0 = (int)y0f;
            float a = aw[l * 4 + p];
            bool xv0 = (x0 >= 0)  && (x0 < W);
            bool xv1 = (x0 >= -1) && (x0 < W - 1);
            bool yv0 = (y0 >= 0)  && (y0 < H);
            bool yv1 = (y0 >= -1) && (y0 < H - 1);
            float w00 = (1.f - wx) * (1.f - wy) * a;
            float w10 = wx * (1.f - wy) * a;
            float w01 = (1.f - wx) * wy * a;
            float w11 = wx * wy * a;
            if (xv0 && yv0) acc += w00 * Vl[(y0 * W + x0) * 256];
            if (xv1 && yv0) acc += w10 * Vl[(y0 * W + x0 + 1) * 256];
            if (xv0 && yv1) acc += w01 * Vl[((y0 + 1) * W + x0) * 256];
            if (xv1 && yv1) acc += w11 * Vl[((y0 + 1) * W + x0 + 1) * 256];
        }
    }
    OUT[(long)row * 256 + h * 32 + d] = acc;
}

// ---------------- layernorm over C=256, block = row ----------------
__global__ void ln_k(const float* __restrict__ in, const float* __restrict__ g,
                     const float* __restrict__ b, float* __restrict__ out)
{
    const int row = blockIdx.x, c = threadIdx.x;
    float v = in[(long)row * 256 + c];
    float s = v;
#pragma unroll
    for (int o = 16; o; o >>= 1) s += __shfl_xor_sync(0xffffffffu, s, o);
    __shared__ float sm[8], sm2[8];
    if ((c & 31) == 0) sm[c >> 5] = s;
    __syncthreads();
    float tot = 0.f;
#pragma unroll
    for (int i = 0; i < 8; i++) tot += sm[i];
    float m = tot * (1.f / 256.f);
    float dd = v - m;
    float q = dd * dd;
#pragma unroll
    for (int o = 16; o; o >>= 1) q += __shfl_xor_sync(0xffffffffu, q, o);
    if ((c & 31) == 0) sm2[c >> 5] = q;
    __syncthreads();
    float tv = 0.f;
#pragma unroll
    for (int i = 0; i < 8; i++) tv += sm2[i];
    float var = tv * (1.f / 256.f);
    out[(long)row * 256 + c] = dd * rsqrtf(var + 1e-5f) * g[c] + b[c];
}

// ---------------- launch ----------------
extern "C" void kernel_launch(void* const* d_in, const int* in_sizes, int n_in,
                              void* d_out, int out_size)
{
    const float* src    = (const float*)d_in[0];
    const float* pos    = (const float*)d_in[1];
    const float* ref    = (const float*)d_in[2];
    const float* w_off  = (const float*)d_in[3];
    const float* b_off  = (const float*)d_in[4];
    const float* w_attn = (const float*)d_in[5];
    const float* b_attn = (const float*)d_in[6];
    const float* w_val  = (const float*)d_in[7];
    const float* b_val  = (const float*)d_in[8];
    const float* w_out  = (const float*)d_in[9];
    const float* b_out  = (const float*)d_in[10];
    const float* g1     = (const float*)d_in[11];
    const float* be1    = (const float*)d_in[12];
    const float* w_ff1  = (const float*)d_in[13];
    const float* b_ff1  = (const float*)d_in[14];
    const float* w_ff2  = (const float*)d_in[15];
    const float* b_ff2  = (const float*)d_in[16];
    const float* g2     = (const float*)d_in[17];
    const float* be2    = (const float*)d_in[18];
    const unsigned char* mask = (const unsigned char*)d_in[19];

    float *pV, *pOFF, *pAW, *pATT, *pS, *pX, *pH, *pY;
    cudaGetSymbolAddress((void**)&pV,   g_V);
    cudaGetSymbolAddress((void**)&pOFF, g_OFF);
    cudaGetSymbolAddress((void**)&pAW,  g_AW);
    cudaGetSymbolAddress((void**)&pATT, g_ATT);
    cudaGetSymbolAddress((void**)&pS,   g_S);
    cudaGetSymbolAddress((void**)&pX,   g_X);
    cudaGetSymbolAddress((void**)&pH,   g_H);
    cudaGetSymbolAddress((void**)&pY,   g_Y);

    dim3 blk(256);
    // value = mask0(src @ w_val + b_val)
    sgemm_k<false, false, false, true ><<<dim3(340, 2), blk>>>(src, nullptr, w_val, b_val, nullptr, mask, pV, 256, 256);
    // off = (src+pos) @ w_off + b_off
    sgemm_k<true,  false, false, false><<<dim3(340, 2), blk>>>(src, pos, w_off, b_off, nullptr, nullptr, pOFF, 256, 256);
    // attn logits = (src+pos) @ w_attn + b_attn
    sgemm_k<true,  false, false, false><<<dim3(340, 1), blk>>>(src, pos, w_attn, b_attn, nullptr, nullptr, pAW, 256, 128);
    softmax16_k<<<(RR * 8 + 255) / 256, 256>>>(pAW);
    deform_k<<<RR, 256>>>(pV, pOFF, pAW, ref, pATT);
    // S = src + (ATT @ w_out + b_out)
    sgemm_k<false, false, true,  false><<<dim3(340, 2), blk>>>(pATT, nullptr, w_out, b_out, src, nullptr, pS, 256, 256);
    ln_k<<<RR, 256>>>(pS, g1, be1, pX);
    // H = relu(X @ w_ff1 + b_ff1)
    sgemm_k<false, true,  false, false><<<dim3(340, 8), blk>>>(pX, nullptr, w_ff1, b_ff1, nullptr, nullptr, pH, 256, 1024);
    // Y = X + (H @ w_ff2 + b_ff2)
    sgemm_k<false, false, true,  false><<<dim3(340, 2), blk>>>(pH, nullptr, w_ff2, b_ff2, pX, nullptr, pY, 1024, 256);
    ln_k<<<RR, 256>>>(pY, g2, be2, (float*)d_out);
}

// round 2
// speedup vs baseline: 2.0529x; 2.0529x over previous
#include <cuda_runtime.h>
#include <cstdint>

#define NB 8
#define LQN 5440
#define CD 256
#define RR 43520          // NB*LQN
#define DFFN 1024

// ---------------- scratch (static device arrays; no allocation) ----------------
__device__ float g_V  [RR * CD];     // value projection
__device__ float g_OFF[RR * CD];     // sampling offsets (NH,NL,NP,2)
__device__ float g_AW [RR * 128];    // attention weights (NH,NL*NP) -> softmaxed
__device__ float g_ATT[RR * CD];     // deform-attn output
__device__ float g_S  [RR * CD];     // src + src2 (pre-LN1)
__device__ float g_X  [RR * CD];     // LN1 output
__device__ float g_H  [RR * DFFN];   // relu(ff1)
__device__ float g_Y  [RR * CD];     // x + ff2 (pre-LN2)

__device__ __forceinline__ uint32_t f2tf32(float x) {
    uint32_t r;
    asm("cvt.rna.tf32.f32 %0, %1;" : "=r"(r) : "f"(x));
    return r;
}

__device__ __forceinline__ void mma_tf32(float d[4], const uint32_t a[4],
                                         const uint32_t b[2]) {
    asm volatile(
        "mma.sync.aligned.m16n8k8.row.col.f32.tf32.tf32.f32 "
        "{%0,%1,%2,%3}, {%4,%5,%6,%7}, {%8,%9}, {%0,%1,%2,%3};\n"
        : "+f"(d[0]), "+f"(d[1]), "+f"(d[2]), "+f"(d[3])
        : "r"(a[0]), "r"(a[1]), "r"(a[2]), "r"(a[3]),
          "r"(b[0]), "r"(b[1]));
}

// ---------------- TF32 tensor-core GEMM ----------------
// C[R,N] = op(A)[R,K] @ B[K,N] + bias (+res, relu, mask)
// BM=BN=128, BK=32, 256 threads (8 warps, 2x4), warp tile 64x32, mma m16n8k8.
template<bool ADD_POS, bool RELU, bool HAS_RES, bool MASK>
__global__ __launch_bounds__(256, 2)
void tgemm_k(const float* __restrict__ A, const float* __restrict__ A2,
             const float* __restrict__ B, const float* __restrict__ bias,
             const float* __restrict__ Res, const unsigned char* __restrict__ mask,
             float* __restrict__ Cout, int K, int Nout)
{
    __shared__ float As[128][36];   // [row][k]   36 % 32 == 4 -> conflict-free frag LDS
    __shared__ float Bs[32][136];   // [k][n]    136 % 32 == 8 -> conflict-free frag LDS

    const int tid  = threadIdx.x;
    const int brow = blockIdx.x * 128;
    const int bcol = blockIdx.y * 128;

    const int lane = tid & 31;
    const int wid  = tid >> 5;
    const int wm   = (wid >> 2) * 64;   // warp row offset (0 / 64)
    const int wn   = (wid & 3) * 32;    // warp col offset (0/32/64/96)
    const int gr   = lane >> 2;         // 0..7
    const int gc   = lane & 3;          // 0..3

    float acc[4][4][4];
#pragma unroll
    for (int i = 0; i < 4; i++)
#pragma unroll
        for (int j = 0; j < 4; j++)
#pragma unroll
            for (int t = 0; t < 4; t++) acc[i][j][t] = 0.f;

    for (int k0 = 0; k0 < K; k0 += 32) {
        // load A chunk: 128 rows x 32 k
#pragma unroll
        for (int i = 0; i < 4; i++) {
            int t = tid + i * 256;
            int r = t >> 3, q = (t & 7) << 2;
            float4 av = *reinterpret_cast<const float4*>(A + (long)(brow + r) * K + k0 + q);
            if (ADD_POS) {
                float4 pv = *reinterpret_cast<const float4*>(A2 + (long)(brow + r) * K + k0 + q);
                av.x += pv.x; av.y += pv.y; av.z += pv.z; av.w += pv.w;
            }
            uint4 cv = make_uint4(f2tf32(av.x), f2tf32(av.y), f2tf32(av.z), f2tf32(av.w));
            *reinterpret_cast<uint4*>(&As[r][q]) = cv;
        }
        // load B chunk: 32 k x 128 n
#pragma unroll
        for (int i = 0; i < 4; i++) {
            int t = tid + i * 256;
            int kr = t >> 5, j = (t & 31) << 2;
            float4 bv = *reinterpret_cast<const float4*>(B + (long)(k0 + kr) * Nout + bcol + j);
            uint4 cv = make_uint4(f2tf32(bv.x), f2tf32(bv.y), f2tf32(bv.z), f2tf32(bv.w));
            *reinterpret_cast<uint4*>(&Bs[kr][j]) = cv;
        }
        __syncthreads();

#pragma unroll
        for (int kk = 0; kk < 4; kk++) {
            const int kb = kk * 8;
            uint32_t af[4][4];
#pragma unroll
            for (int mt = 0; mt < 4; mt++) {
                int r = wm + mt * 16 + gr;
                af[mt][0] = __float_as_uint(As[r][kb + gc]);
                af[mt][1] = __float_as_uint(As[r + 8][kb + gc]);
                af[mt][2] = __float_as_uint(As[r][kb + gc + 4]);
                af[mt][3] = __float_as_uint(As[r + 8][kb + gc + 4]);
            }
            uint32_t bf[4][2];
#pragma unroll
            for (int nt = 0; nt < 4; nt++) {
                int n = wn + nt * 8 + gr;
                bf[nt][0] = __float_as_uint(Bs[kb + gc][n]);
                bf[nt][1] = __float_as_uint(Bs[kb + gc + 4][n]);
            }
#pragma unroll
            for (int mt = 0; mt < 4; mt++)
#pragma unroll
                for (int nt = 0; nt < 4; nt++)
                    mma_tf32(acc[mt][nt], af[mt], bf[nt]);
        }
        __syncthreads();
    }

    // epilogue: c0,c1 at (r0, col..col+1); c2,c3 at (r0+8, col..col+1)
#pragma unroll
    for (int mt = 0; mt < 4; mt++) {
        int r0 = brow + wm + mt * 16 + gr;
        int r1 = r0 + 8;
        float ms0 = 1.f, ms1 = 1.f;
        if (MASK) { ms0 = mask[r0] ? 0.f : 1.f; ms1 = mask[r1] ? 0.f : 1.f; }
#pragma unroll
        for (int nt = 0; nt < 4; nt++) {
            int col = bcol + wn + nt * 8 + gc * 2;
            float2 bi = *reinterpret_cast<const float2*>(&bias[col]);
            float v0 = acc[mt][nt][0] + bi.x;
            float v1 = acc[mt][nt][1] + bi.y;
            float v2 = acc[mt][nt][2] + bi.x;
            float v3 = acc[mt][nt][3] + bi.y;
            if (MASK) { v0 *= ms0; v1 *= ms0; v2 *= ms1; v3 *= ms1; }
            if (RELU) {
                v0 = fmaxf(v0, 0.f); v1 = fmaxf(v1, 0.f);
                v2 = fmaxf(v2, 0.f); v3 = fmaxf(v3, 0.f);
            }
            if (HAS_RES) {
                float2 e0 = *reinterpret_cast<const float2*>(&Res[(long)r0 * Nout + col]);
                float2 e1 = *reinterpret_cast<const float2*>(&Res[(long)r1 * Nout + col]);
                v0 += e0.x; v1 += e0.y; v2 += e1.x; v3 += e1.y;
            }
            *reinterpret_cast<float2*>(&Cout[(long)r0 * Nout + col]) = make_float2(v0, v1);
            *reinterpret_cast<float2*>(&Cout[(long)r1 * Nout + col]) = make_float2(v2, v3);
        }
    }
}

// ---------------- softmax over NL*NP=16 per (row, head) ----------------
__global__ void softmax16_k(float* __restrict__ aw)
{
    int i = blockIdx.x * blockDim.x + threadIdx.x;
    if (i >= RR * 8) return;
    float* p = aw + (long)i * 16;
    float e[16];
    float mx = -1e30f;
#pragma unroll
    for (int j = 0; j < 16; j++) { e[j] = p[j]; mx = fmaxf(mx, e[j]); }
    float s = 0.f;
#pragma unroll
    for (int j = 0; j < 16; j++) { e[j] = expf(e[j] - mx); s += e[j]; }
    float inv = 1.f / s;
#pragma unroll
    for (int j = 0; j < 16; j++) p[j] = e[j] * inv;
}

// ---------------- deformable sampling: block = (n,q), warp = head, lane = channel --
__global__ void deform_k(const float* __restrict__ V, const float* __restrict__ OFF,
                         const float* __restrict__ AW, const float* __restrict__ REF,
                         float* __restrict__ OUT)
{
    const int row = blockIdx.x;           // n*LQ + q
    const int h = threadIdx.x >> 5;
    const int d = threadIdx.x & 31;
    const int n = row / LQN;

    const float* off = OFF + (long)row * 256 + h * 32;
    const float* aw  = AW  + (long)row * 128 + h * 16;
    const float* ref = REF + (long)row * 8;
    const float* Vb  = V + (long)n * LQN * 256 + h * 32 + d;

    const int   Wt[4]   = {64, 32, 16, 8};
    const int   St[4]   = {0, 4096, 5120, 5376};
    const float invW[4] = {1.f/64.f, 1.f/32.f, 1.f/16.f, 1.f/8.f};

    float acc = 0.f;
#pragma unroll
    for (int l = 0; l < 4; l++) {
        const int W = Wt[l], H = Wt[l];
        const float* Vl = Vb + (long)St[l] * 256;
        const float rx = ref[l * 2 + 0], ry = ref[l * 2 + 1];
#pragma unroll
        for (int p = 0; p < 4; p++) {
            float ox = off[l * 8 + p * 2 + 0];
            float oy = off[l * 8 + p * 2 + 1];
            float lx = rx + ox * invW[l];
            float ly = ry + oy * invW[l];
            float gx = 2.f * lx - 1.f, gy = 2.f * ly - 1.f;
            float x = (gx + 1.f) * (W * 0.5f) - 0.5f;
            float y = (gy + 1.f) * (H * 0.5f) - 0.5f;
            float x0f = floorf(x), y0f = floorf(y);
            float wx = x - x0f, wy = y - y0f;
            int x0 = (int)x0f, y0 = (int)y0f;
            float a = aw[l * 4 + p];
            bool xv0 = (x0 >= 0)  && (x0 < W);
            bool xv1 = (x0 >= -1) && (x0 < W - 1);
            bool yv0 = (y0 >= 0)  && (y0 < H);
            bool yv1 = (y0 >= -1) && (y0 < H - 1);
            float w00 = (1.f - wx) * (1.f - wy) * a;
            float w10 = wx * (1.f - wy) * a;
            float w01 = (1.f - wx) * wy * a;
            float w11 = wx * wy * a;
            if (xv0 && yv0) acc += w00 * Vl[(y0 * W + x0) * 256];
            if (xv1 && yv0) acc += w10 * Vl[(y0 * W + x0 + 1) * 256];
            if (xv0 && yv1) acc += w01 * Vl[((y0 + 1) * W + x0) * 256];
            if (xv1 && yv1) acc += w11 * Vl[((y0 + 1) * W + x0 + 1) * 256];
        }
    }
    OUT[(long)row * 256 + h * 32 + d] = acc;
}

// ---------------- layernorm over C=256, block = row ----------------
__global__ void ln_k(const float* __restrict__ in, const float* __restrict__ g,
                     const float* __restrict__ b, float* __restrict__ out)
{
    const int row = blockIdx.x, c = threadIdx.x;
    float v = in[(long)row * 256 + c];
    float s = v;
#pragma unroll
    for (int o = 16; o; o >>= 1) s += __shfl_xor_sync(0xffffffffu, s, o);
    __shared__ float sm[8], sm2[8];
    if ((c & 31) == 0) sm[c >> 5] = s;
    __syncthreads();
    float tot = 0.f;
#pragma unroll
    for (int i = 0; i < 8; i++) tot += sm[i];
    float m = tot * (1.f / 256.f);
    float dd = v - m;
    float q = dd * dd;
#pragma unroll
    for (int o = 16; o; o >>= 1) q += __shfl_xor_sync(0xffffffffu, q, o);
    if ((c & 31) == 0) sm2[c >> 5] = q;
    __syncthreads();
    float tv = 0.f;
#pragma unroll
    for (int i = 0; i < 8; i++) tv += sm2[i];
    float var = tv * (1.f / 256.f);
    out[(long)row * 256 + c] = dd * rsqrtf(var + 1e-5f) * g[c] + b[c];
}

// ---------------- launch ----------------
extern "C" void kernel_launch(void* const* d_in, const int* in_sizes, int n_in,
                              void* d_out, int out_size)
{
    const float* src    = (const float*)d_in[0];
    const float* pos    = (const float*)d_in[1];
    const float* ref    = (const float*)d_in[2];
    const float* w_off  = (const float*)d_in[3];
    const float* b_off  = (const float*)d_in[4];
    const float* w_attn = (const float*)d_in[5];
    const float* b_attn = (const float*)d_in[6];
    const float* w_val  = (const float*)d_in[7];
    const float* b_val  = (const float*)d_in[8];
    const float* w_out  = (const float*)d_in[9];
    const float* b_out  = (const float*)d_in[10];
    const float* g1     = (const float*)d_in[11];
    const float* be1    = (const float*)d_in[12];
    const float* w_ff1  = (const float*)d_in[13];
    const float* b_ff1  = (const float*)d_in[14];
    const float* w_ff2  = (const float*)d_in[15];
    const float* b_ff2  = (const float*)d_in[16];
    const float* g2     = (const float*)d_in[17];
    const float* be2    = (const float*)d_in[18];
    const unsigned char* mask = (const unsigned char*)d_in[19];

    float *pV, *pOFF, *pAW, *pATT, *pS, *pX, *pH, *pY;
    cudaGetSymbolAddress((void**)&pV,   g_V);
    cudaGetSymbolAddress((void**)&pOFF, g_OFF);
    cudaGetSymbolAddress((void**)&pAW,  g_AW);
    cudaGetSymbolAddress((void**)&pATT, g_ATT);
    cudaGetSymbolAddress((void**)&pS,   g_S);
    cudaGetSymbolAddress((void**)&pX,   g_X);
    cudaGetSymbolAddress((void**)&pH,   g_H);
    cudaGetSymbolAddress((void**)&pY,   g_Y);

    dim3 blk(256);
    // value = mask0(src @ w_val + b_val)
    tgemm_k<false, false, false, true ><<<dim3(340, 2), blk>>>(src, nullptr, w_val, b_val, nullptr, mask, pV, 256, 256);
    // off = (src+pos) @ w_off + b_off
    tgemm_k<true,  false, false, false><<<dim3(340, 2), blk>>>(src, pos, w_off, b_off, nullptr, nullptr, pOFF, 256, 256);
    // attn logits = (src+pos) @ w_attn + b_attn
    tgemm_k<true,  false, false, false><<<dim3(340, 1), blk>>>(src, pos, w_attn, b_attn, nullptr, nullptr, pAW, 256, 128);
    softmax16_k<<<(RR * 8 + 255) / 256, 256>>>(pAW);
    deform_k<<<RR, 256>>>(pV, pOFF, pAW, ref, pATT);
    // S = src + (ATT @ w_out + b_out)
    tgemm_k<false, false, true,  false><<<dim3(340, 2), blk>>>(pATT, nullptr, w_out, b_out, src, nullptr, pS, 256, 256);
    ln_k<<<RR, 256>>>(pS, g1, be1, pX);
    // H = relu(X @ w_ff1 + b_ff1)
    tgemm_k<false, true,  false, false><<<dim3(340, 8), blk>>>(pX, nullptr, w_ff1, b_ff1, nullptr, nullptr, pH, 256, 1024);
    // Y = X + (H @ w_ff2 + b_ff2)
    tgemm_k<false, false, true,  false><<<dim3(340, 2), blk>>>(pH, nullptr, w_ff2, b_ff2, pX, nullptr, pY, 1024, 256);
    ln_k<<<RR, 256>>>(pY, g2, be2, (float*)d_out);
}

// round 3
// speedup vs baseline: 2.5145x; 1.2248x over previous
#include <cuda_runtime.h>
#include <cstdint>

#define NB 8
#define LQN 5440
#define CD 256
#define RR 43520          // NB*LQN
#define DFFN 1024

// ---------------- scratch (static device arrays; no allocation) ----------------
__device__ float g_Q  [RR * CD];     // src + pos
__device__ float g_V  [RR * CD];     // value projection
__device__ float g_OFF[RR * CD];     // sampling offsets (NH,NL,NP,2)
__device__ float g_AW [RR * 128];    // attention logits (softmax fused into deform)
__device__ float g_ATT[RR * CD];     // deform-attn output
__device__ float g_S  [RR * CD];     // src + src2 (pre-LN1)
__device__ float g_X  [RR * CD];     // LN1 output
__device__ float g_H  [RR * DFFN];   // relu(ff1)
__device__ float g_Y  [RR * CD];     // x + ff2 (pre-LN2)

__device__ __forceinline__ void mma_tf32(float d[4], const uint32_t a[4],
                                         const uint32_t b[2]) {
    asm volatile(
        "mma.sync.aligned.m16n8k8.row.col.f32.tf32.tf32.f32 "
        "{%0,%1,%2,%3}, {%4,%5,%6,%7}, {%8,%9}, {%0,%1,%2,%3};\n"
        : "+f"(d[0]), "+f"(d[1]), "+f"(d[2]), "+f"(d[3])
        : "r"(a[0]), "r"(a[1]), "r"(a[2]), "r"(a[3]),
          "r"(b[0]), "r"(b[1]));
}

__device__ __forceinline__ void cp_async16(void* s, const void* g) {
    uint32_t sa = (uint32_t)__cvta_generic_to_shared(s);
    asm volatile("cp.async.cg.shared.global [%0], [%1], 16;\n" :: "r"(sa), "l"(g));
}
__device__ __forceinline__ void cp_commit() {
    asm volatile("cp.async.commit_group;\n");
}
template<int N> __device__ __forceinline__ void cp_wait() {
    asm volatile("cp.async.wait_group %0;\n" :: "n"(N));
}

// ---------------- TF32 tensor-core GEMM, 3-stage cp.async pipeline ------------
// C[R,N] = A[R,K] @ B[K,N] + bias (+res, relu, mask)
// BM=BN=128, BK=32, 256 threads (8 warps 2x4), warp tile 64x32, mma m16n8k8.
#define AS_STRIDE 36
#define BS_STRIDE 136
#define AS_ELEMS (128 * AS_STRIDE)
#define BS_ELEMS (32 * BS_STRIDE)
#define SMEM_FLOATS (3 * (AS_ELEMS + BS_ELEMS))

template<bool RELU, bool HAS_RES, bool MASK>
__global__ __launch_bounds__(256, 2)
void tgemm_k(const float* __restrict__ A, const float* __restrict__ B,
             const float* __restrict__ bias, const float* __restrict__ Res,
             const unsigned char* __restrict__ mask,
             float* __restrict__ Cout, int K, int Nout)
{
    extern __shared__ float smem[];
    float (*As)[128][AS_STRIDE] = reinterpret_cast<float(*)[128][AS_STRIDE]>(smem);
    float (*Bs)[32][BS_STRIDE]  = reinterpret_cast<float(*)[32][BS_STRIDE]>(smem + 3 * AS_ELEMS);

    const int tid  = threadIdx.x;
    const int brow = blockIdx.x * 128;
    const int bcol = blockIdx.y * 128;

    const int lane = tid & 31;
    const int wid  = tid >> 5;
    const int wm   = (wid >> 2) * 64;
    const int wn   = (wid & 3) * 32;
    const int gr   = lane >> 2;
    const int gc   = lane & 3;

    // A copy map: 1024 16B segs = 128 rows x 8 segs
    const int ar = tid >> 1;               // with i*128 added: rows
    // simpler: seg index t = tid + i*256 ; r=t>>3 ; q=(t&7)<<2
    // B copy map: seg t: kr=t>>5 ; j=(t&31)<<2

    float acc[4][4][4];
#pragma unroll
    for (int i = 0; i < 4; i++)
#pragma unroll
        for (int j = 0; j < 4; j++)
#pragma unroll
            for (int t = 0; t < 4; t++) acc[i][j][t] = 0.f;
    (void)ar;

    const int nch = K >> 5;

    auto issue = [&](int chunk, int stg) {
        const int k0 = chunk << 5;
#pragma unroll
        for (int i = 0; i < 4; i++) {
            int t = tid + i * 256;
            int r = t >> 3, q = (t & 7) << 2;
            cp_async16(&As[stg][r][q], A + (long)(brow + r) * K + k0 + q);
        }
#pragma unroll
        for (int i = 0; i < 4; i++) {
            int t = tid + i * 256;
            int kr = t >> 5, j = (t & 31) << 2;
            cp_async16(&Bs[stg][kr][j], B + (long)(k0 + kr) * Nout + bcol + j);
        }
        cp_commit();
    };

    issue(0, 0);
    if (nch > 1) issue(1, 1);
    else cp_commit();

    for (int c = 0; c < nch; c++) {
        const int cur = c % 3;
        if (c + 2 < nch) issue(c + 2, (c + 2) % 3);
        else cp_commit();
        cp_wait<2>();
        __syncthreads();

#pragma unroll
        for (int kk = 0; kk < 4; kk++) {
            const int kb = kk * 8;
            uint32_t af[4][4];
#pragma unroll
            for (int mt = 0; mt < 4; mt++) {
                int r = wm + mt * 16 + gr;
                af[mt][0] = __float_as_uint(As[cur][r][kb + gc]);
                af[mt][1] = __float_as_uint(As[cur][r + 8][kb + gc]);
                af[mt][2] = __float_as_uint(As[cur][r][kb + gc + 4]);
                af[mt][3] = __float_as_uint(As[cur][r + 8][kb + gc + 4]);
            }
            uint32_t bf[4][2];
#pragma unroll
            for (int nt = 0; nt < 4; nt++) {
                int n = wn + nt * 8 + gr;
                bf[nt][0] = __float_as_uint(Bs[cur][kb + gc][n]);
                bf[nt][1] = __float_as_uint(Bs[cur][kb + gc + 4][n]);
            }
#pragma unroll
            for (int mt = 0; mt < 4; mt++)
#pragma unroll
                for (int nt = 0; nt < 4; nt++)
                    mma_tf32(acc[mt][nt], af[mt], bf[nt]);
        }
        __syncthreads();
    }

#pragma unroll
    for (int mt = 0; mt < 4; mt++) {
        int r0 = brow + wm + mt * 16 + gr;
        int r1 = r0 + 8;
        float ms0 = 1.f, ms1 = 1.f;
        if (MASK) { ms0 = mask[r0] ? 0.f : 1.f; ms1 = mask[r1] ? 0.f : 1.f; }
#pragma unroll
        for (int nt = 0; nt < 4; nt++) {
            int col = bcol + wn + nt * 8 + gc * 2;
            float2 bi = *reinterpret_cast<const float2*>(&bias[col]);
            float v0 = acc[mt][nt][0] + bi.x;
            float v1 = acc[mt][nt][1] + bi.y;
            float v2 = acc[mt][nt][2] + bi.x;
            float v3 = acc[mt][nt][3] + bi.y;
            if (MASK) { v0 *= ms0; v1 *= ms0; v2 *= ms1; v3 *= ms1; }
            if (RELU) {
                v0 = fmaxf(v0, 0.f); v1 = fmaxf(v1, 0.f);
                v2 = fmaxf(v2, 0.f); v3 = fmaxf(v3, 0.f);
            }
            if (HAS_RES) {
                float2 e0 = *reinterpret_cast<const float2*>(&Res[(long)r0 * Nout + col]);
                float2 e1 = *reinterpret_cast<const float2*>(&Res[(long)r1 * Nout + col]);
                v0 += e0.x; v1 += e0.y; v2 += e1.x; v3 += e1.y;
            }
            *reinterpret_cast<float2*>(&Cout[(long)r0 * Nout + col]) = make_float2(v0, v1);
            *reinterpret_cast<float2*>(&Cout[(long)r1 * Nout + col]) = make_float2(v2, v3);
        }
    }
}

// ---------------- Q = src + pos ----------------
__global__ void addvec_k(const float* __restrict__ a, const float* __restrict__ b,
                         float* __restrict__ o)
{
    int i = blockIdx.x * blockDim.x + threadIdx.x;   // float4 index, exact: RR*CD/4
    float4 x = reinterpret_cast<const float4*>(a)[i];
    float4 y = reinterpret_cast<const float4*>(b)[i];
    x.x += y.x; x.y += y.y; x.z += y.z; x.w += y.w;
    reinterpret_cast<float4*>(o)[i] = x;
}

// ---------------- deformable sampling + fused softmax ----------------
// block = (n,q), warp = head, lane = channel; lanes 0..15 own the 16 logits.
__global__ void deform_k(const float* __restrict__ V, const float* __restrict__ OFF,
                         const float* __restrict__ LOGIT, const float* __restrict__ REF,
                         float* __restrict__ OUT)
{
    const int row = blockIdx.x;
    const int h = threadIdx.x >> 5;
    const int d = threadIdx.x & 31;
    const int n = row / LQN;

    // fused softmax over 16 (NL*NP) logits of this head
    const float* lgp = LOGIT + (long)row * 128 + h * 16;
    float lg = (d < 16) ? lgp[d] : -1e30f;
    float mx = lg;
#pragma unroll
    for (int o = 8; o; o >>= 1) mx = fmaxf(mx, __shfl_xor_sync(0xffffffffu, mx, o));
    float ev = (d < 16) ? expf(lg - mx) : 0.f;
    float sum = ev;
#pragma unroll
    for (int o = 8; o; o >>= 1) sum += __shfl_xor_sync(0xffffffffu, sum, o);
    float prob = ev / sum;

    const float* off = OFF + (long)row * 256 + h * 32;
    const float* ref = REF + (long)row * 8;
    const float* Vb  = V + (long)n * LQN * 256 + h * 32 + d;

    const int   Wt[4]   = {64, 32, 16, 8};
    const int   St[4]   = {0, 4096, 5120, 5376};
    const float invW[4] = {1.f/64.f, 1.f/32.f, 1.f/16.f, 1.f/8.f};

    float acc = 0.f;
#pragma unroll
    for (int l = 0; l < 4; l++) {
        const int W = Wt[l], H = Wt[l];
        const float* Vl = Vb + (long)St[l] * 256;
        const float rx = ref[l * 2 + 0], ry = ref[l * 2 + 1];
#pragma unroll
        for (int p = 0; p < 4; p++) {
            float ox = off[l * 8 + p * 2 + 0];
            float oy = off[l * 8 + p * 2 + 1];
            float lx = rx + ox * invW[l];
            float ly = ry + oy * invW[l];
            float gx = 2.f * lx - 1.f, gy = 2.f * ly - 1.f;
            float x = (gx + 1.f) * (W * 0.5f) - 0.5f;
            float y = (gy + 1.f) * (H * 0.5f) - 0.5f;
            float x0f = floorf(x), y0f = floorf(y);
            float wx = x - x0f, wy = y - y0f;
            int x0 = (int)x0f, y0 = (int)y0f;
            float a = __shfl_sync(0xffffffffu, prob, l * 4 + p);
            bool xv0 = (x0 >= 0)  && (x0 < W);
            bool xv1 = (x0 >= -1) && (x0 < W - 1);
            bool yv0 = (y0 >= 0)  && (y0 < H);
            bool yv1 = (y0 >= -1) && (y0 < H - 1);
            float w00 = (1.f - wx) * (1.f - wy) * a;
            float w10 = wx * (1.f - wy) * a;
            float w01 = (1.f - wx) * wy * a;
            float w11 = wx * wy * a;
            if (xv0 && yv0) acc += w00 * Vl[(y0 * W + x0) * 256];
            if (xv1 && yv0) acc += w10 * Vl[(y0 * W + x0 + 1) * 256];
            if (xv0 && yv1) acc += w01 * Vl[((y0 + 1) * W + x0) * 256];
            if (xv1 && yv1) acc += w11 * Vl[((y0 + 1) * W + x0 + 1) * 256];
        }
    }
    OUT[(long)row * 256 + h * 32 + d] = acc;
}

// ---------------- layernorm over C=256, block = row ----------------
__global__ void ln_k(const float* __restrict__ in, const float* __restrict__ g,
                     const float* __restrict__ b, float* __restrict__ out)
{
    const int row = blockIdx.x, c = threadIdx.x;
    float v = in[(long)row * 256 + c];
    float s = v;
#pragma unroll
    for (int o = 16; o; o >>= 1) s += __shfl_xor_sync(0xffffffffu, s, o);
    __shared__ float sm[8], sm2[8];
    if ((c & 31) == 0) sm[c >> 5] = s;
    __syncthreads();
    float tot = 0.f;
#pragma unroll
    for (int i = 0; i < 8; i++) tot += sm[i];
    float m = tot * (1.f / 256.f);
    float dd = v - m;
    float q = dd * dd;
#pragma unroll
    for (int o = 16; o; o >>= 1) q += __shfl_xor_sync(0xffffffffu, q, o);
    if ((c & 31) == 0) sm2[c >> 5] = q;
    __syncthreads();
    float tv = 0.f;
#pragma unroll
    for (int i = 0; i < 8; i++) tv += sm2[i];
    float var = tv * (1.f / 256.f);
    out[(long)row * 256 + c] = dd * rsqrtf(var + 1e-5f) * g[c] + b[c];
}

// ---------------- launch ----------------
extern "C" void kernel_launch(void* const* d_in, const int* in_sizes, int n_in,
                              void* d_out, int out_size)
{
    const float* src    = (const float*)d_in[0];
    const float* pos    = (const float*)d_in[1];
    const float* ref    = (const float*)d_in[2];
    const float* w_off  = (const float*)d_in[3];
    const float* b_off  = (const float*)d_in[4];
    const float* w_attn = (const float*)d_in[5];
    const float* b_attn = (const float*)d_in[6];
    const float* w_val  = (const float*)d_in[7];
    const float* b_val  = (const float*)d_in[8];
    const float* w_out  = (const float*)d_in[9];
    const float* b_out  = (const float*)d_in[10];
    const float* g1     = (const float*)d_in[11];
    const float* be1    = (const float*)d_in[12];
    const float* w_ff1  = (const float*)d_in[13];
    const float* b_ff1  = (const float*)d_in[14];
    const float* w_ff2  = (const float*)d_in[15];
    const float* b_ff2  = (const float*)d_in[16];
    const float* g2     = (const float*)d_in[17];
    const float* be2    = (const float*)d_in[18];
    const unsigned char* mask = (const unsigned char*)d_in[19];

    float *pQ, *pV, *pOFF, *pAW, *pATT, *pS, *pX, *pH, *pY;
    cudaGetSymbolAddress((void**)&pQ,   g_Q);
    cudaGetSymbolAddress((void**)&pV,   g_V);
    cudaGetSymbolAddress((void**)&pOFF, g_OFF);
    cudaGetSymbolAddress((void**)&pAW,  g_AW);
    cudaGetSymbolAddress((void**)&pATT, g_ATT);
    cudaGetSymbolAddress((void**)&pS,   g_S);
    cudaGetSymbolAddress((void**)&pX,   g_X);
    cudaGetSymbolAddress((void**)&pH,   g_H);
    cudaGetSymbolAddress((void**)&pY,   g_Y);

    const int SMEM_BYTES = SMEM_FLOATS * 4;   // 107,520 B
    cudaFuncSetAttribute(tgemm_k<false, false, true >, cudaFuncAttributeMaxDynamicSharedMemorySize, SMEM_BYTES);
    cudaFuncSetAttribute(tgemm_k<false, false, false>, cudaFuncAttributeMaxDynamicSharedMemorySize, SMEM_BYTES);
    cudaFuncSetAttribute(tgemm_k<false, true,  false>, cudaFuncAttributeMaxDynamicSharedMemorySize, SMEM_BYTES);
    cudaFuncSetAttribute(tgemm_k<true,  false, false>, cudaFuncAttributeMaxDynamicSharedMemorySize, SMEM_BYTES);

    dim3 blk(256);
    addvec_k<<<RR * CD / 4 / 256, 256>>>(src, pos, pQ);
    // value = mask0(src @ w_val + b_val)
    tgemm_k<false, false, true ><<<dim3(340, 2), blk, SMEM_BYTES>>>(src, w_val, b_val, nullptr, mask, pV, 256, 256);
    // off = Q @ w_off + b_off
    tgemm_k<false, false, false><<<dim3(340, 2), blk, SMEM_BYTES>>>(pQ, w_off, b_off, nullptr, nullptr, pOFF, 256, 256);
    // attn logits = Q @ w_attn + b_attn   (softmax fused into deform)
    tgemm_k<false, false, false><<<dim3(340, 1), blk, SMEM_BYTES>>>(pQ, w_attn, b_attn, nullptr, nullptr, pAW, 256, 128);
    deform_k<<<RR, 256>>>(pV, pOFF, pAW, ref, pATT);
    // S = src + (ATT @ w_out + b_out)
    tgemm_k<false, true,  false><<<dim3(340, 2), blk, SMEM_BYTES>>>(pATT, w_out, b_out, src, nullptr, pS, 256, 256);
    ln_k<<<RR, 256>>>(pS, g1, be1, pX);
    // H = relu(X @ w_ff1 + b_ff1)
    tgemm_k<true,  false, false><<<dim3(340, 8), blk, SMEM_BYTES>>>(pX, w_ff1, b_ff1, nullptr, nullptr, pH, 256, 1024);
    // Y = X + (H @ w_ff2 + b_ff2)
    tgemm_k<false, true,  false><<<dim3(340, 2), blk, SMEM_BYTES>>>(pH, w_ff2, b_ff2, pX, nullptr, pY, 1024, 256);
    ln_k<<<RR, 256>>>(pY, g2, be2, (float*)d_out);
}

// round 5
// speedup vs baseline: 3.0463x; 1.2115x over previous
#include <cuda_runtime.h>
#include <cuda_fp16.h>
#include <cstdint>

#define NB 8
#define LQN 5440
#define CD 256
#define RR 43520          // NB*LQN
#define DFFN 1024

typedef __half half_t;

// ---------------- scratch (static device arrays; no allocation) ----------------
__device__ half_t g_srcH[RR * CD];           // src as fp16
__device__ half_t g_QH  [RR * CD];           // (src+pos) as fp16
__device__ half_t g_ATTH[RR * CD];           // deform output fp16
__device__ half_t g_XH  [RR * CD];           // LN1 output fp16
__device__ half_t g_HH  [RR * DFFN];         // relu(ff1) fp16
// transposed fp16 weights [N][K]
__device__ half_t g_WvT [CD * CD];
__device__ half_t g_WqaT[384 * CD];          // off (256 rows) ++ attn (128 rows)
__device__ half_t g_WuT [CD * CD];
__device__ half_t g_W1T [DFFN * CD];
__device__ half_t g_W2T [CD * DFFN];
__device__ float  g_bqa [384];               // b_off ++ b_attn
// fp32 intermediates
__device__ float g_V  [RR * CD];
__device__ float g_OA [RR * 384];            // off (256) ++ logits (128)
__device__ float g_S  [RR * CD];
__device__ float g_X  [RR * CD];
__device__ float g_Y  [RR * CD];

// ---------------- PTX helpers ----------------
__device__ __forceinline__ void mma_fp16(float d[4], const uint32_t a[4],
                                         const uint32_t b[2]) {
    asm volatile(
        "mma.sync.aligned.m16n8k16.row.col.f32.f16.f16.f32 "
        "{%0,%1,%2,%3}, {%4,%5,%6,%7}, {%8,%9}, {%0,%1,%2,%3};\n"
        : "+f"(d[0]), "+f"(d[1]), "+f"(d[2]), "+f"(d[3])
        : "r"(a[0]), "r"(a[1]), "r"(a[2]), "r"(a[3]),
          "r"(b[0]), "r"(b[1]));
}
__device__ __forceinline__ void cp_async16(void* s, const void* g) {
    uint32_t sa = (uint32_t)__cvta_generic_to_shared(s);
    asm volatile("cp.async.cg.shared.global [%0], [%1], 16;\n" :: "r"(sa), "l"(g));
}
__device__ __forceinline__ void cp_commit() { asm volatile("cp.async.commit_group;\n"); }
template<int N> __device__ __forceinline__ void cp_wait() {
    asm volatile("cp.async.wait_group %0;\n" :: "n"(N));
}

// ---------------- FP16 tensor-core GEMM, 3-stage cp.async pipeline ------------
// C[R,Nout] = A[R,K] @ W[K,Nout], W stored transposed [Nout][K] fp16.
// BM=BN=128, BK=64, 256 threads (8 warps 2x4), warp tile 64x32, mma m16n8k16.
#define HS 72                          // half stride (64 + 8 pad): words = 36 -> conflict-free
#define TILE_HALFS (128 * HS)          // per matrix per stage
#define STAGE_HALFS (2 * TILE_HALFS)
#define SMEM_BYTES (3 * STAGE_HALFS * 2)   // 110,592 B

template<bool RELU, bool HAS_RES, bool MASK, bool HALF_OUT>
__global__ __launch_bounds__(256, 2)
void hgemm_k(const half_t* __restrict__ A, const half_t* __restrict__ B,
             const float* __restrict__ bias, const float* __restrict__ Res,
             const unsigned char* __restrict__ mask,
             float* __restrict__ Cf, half_t* __restrict__ Ch, int K, int Nout)
{
    extern __shared__ half_t sm[];

    const int tid  = threadIdx.x;
    const int brow = blockIdx.x * 128;
    const int bcol = blockIdx.y * 128;

    const int lane = tid & 31;
    const int wid  = tid >> 5;
    const int wm   = (wid >> 2) * 64;
    const int wn   = (wid & 3) * 32;
    const int gr   = lane >> 2;
    const int gc   = lane & 3;

    float acc[4][4][4];
#pragma unroll
    for (int i = 0; i < 4; i++)
#pragma unroll
        for (int j = 0; j < 4; j++)
#pragma unroll
            for (int t = 0; t < 4; t++) acc[i][j][t] = 0.f;

    const int nch = K >> 6;

    auto issue = [&](int chunk, int stg) {
        const int k0 = chunk << 6;
        half_t* As = sm + stg * STAGE_HALFS;
        half_t* Bs = As + TILE_HALFS;
#pragma unroll
        for (int i = 0; i < 4; i++) {
            int t = tid + i * 256;
            int r = t >> 3, q = (t & 7) << 3;          // q: half offset (8 halves = 16B)
            cp_async16(As + r * HS + q, A + (size_t)(brow + r) * K + k0 + q);
        }
#pragma unroll
        for (int i = 0; i < 4; i++) {
            int t = tid + i * 256;
            int r = t >> 3, q = (t & 7) << 3;
            cp_async16(Bs + r * HS + q, B + (size_t)(bcol + r) * K + k0 + q);
        }
        cp_commit();
    };

    issue(0, 0);
    if (nch > 1) issue(1, 1);
    else cp_commit();

    for (int c = 0; c < nch; c++) {
        const int cur = c % 3;
        if (c + 2 < nch) issue(c + 2, (c + 2) % 3);
        else cp_commit();
        cp_wait<2>();
        __syncthreads();

        const half_t* As = sm + cur * STAGE_HALFS;
        const half_t* Bs = As + TILE_HALFS;
#pragma unroll
        for (int kk = 0; kk < 4; kk++) {
            const int kb = kk * 16;
            uint32_t af[4][4];
#pragma unroll
            for (int mt = 0; mt < 4; mt++) {
                const half_t* ar0 = As + (wm + mt * 16 + gr) * HS + kb + 2 * gc;
                const half_t* ar1 = ar0 + 8 * HS;
                af[mt][0] = *reinterpret_cast<const uint32_t*>(ar0);
                af[mt][1] = *reinterpret_cast<const uint32_t*>(ar1);
                af[mt][2] = *reinterpret_cast<const uint32_t*>(ar0 + 8);
                af[mt][3] = *reinterpret_cast<const uint32_t*>(ar1 + 8);
            }
            uint32_t bf[4][2];
#pragma unroll
            for (int nt = 0; nt < 4; nt++) {
                const half_t* br = Bs + (wn + nt * 8 + gr) * HS + kb + 2 * gc;
                bf[nt][0] = *reinterpret_cast<const uint32_t*>(br);
                bf[nt][1] = *reinterpret_cast<const uint32_t*>(br + 8);
            }
#pragma unroll
            for (int mt = 0; mt < 4; mt++)
#pragma unroll
                for (int nt = 0; nt < 4; nt++)
                    mma_fp16(acc[mt][nt], af[mt], bf[nt]);
        }
        __syncthreads();
    }

#pragma unroll
    for (int mt = 0; mt < 4; mt++) {
        int r0 = brow + wm + mt * 16 + gr;
        int r1 = r0 + 8;
        float ms0 = 1.f, ms1 = 1.f;
        if (MASK) { ms0 = mask[r0] ? 0.f : 1.f; ms1 = mask[r1] ? 0.f : 1.f; }
#pragma unroll
        for (int nt = 0; nt < 4; nt++) {
            int col = bcol + wn + nt * 8 + gc * 2;
            float2 bi = *reinterpret_cast<const float2*>(&bias[col]);
            float v0 = acc[mt][nt][0] + bi.x;
            float v1 = acc[mt][nt][1] + bi.y;
            float v2 = acc[mt][nt][2] + bi.x;
            float v3 = acc[mt][nt][3] + bi.y;
            if (MASK) { v0 *= ms0; v1 *= ms0; v2 *= ms1; v3 *= ms1; }
            if (RELU) {
                v0 = fmaxf(v0, 0.f); v1 = fmaxf(v1, 0.f);
                v2 = fmaxf(v2, 0.f); v3 = fmaxf(v3, 0.f);
            }
            if (HAS_RES) {
                float2 e0 = *reinterpret_cast<const float2*>(&Res[(size_t)r0 * Nout + col]);
                float2 e1 = *reinterpret_cast<const float2*>(&Res[(size_t)r1 * Nout + col]);
                v0 += e0.x; v1 += e0.y; v2 += e1.x; v3 += e1.y;
            }
            if (HALF_OUT) {
                *reinterpret_cast<__half2*>(&Ch[(size_t)r0 * Nout + col]) = __floats2half2_rn(v0, v1);
                *reinterpret_cast<__half2*>(&Ch[(size_t)r1 * Nout + col]) = __floats2half2_rn(v2, v3);
            } else {
                *reinterpret_cast<float2*>(&Cf[(size_t)r0 * Nout + col]) = make_float2(v0, v1);
                *reinterpret_cast<float2*>(&Cf[(size_t)r1 * Nout + col]) = make_float2(v2, v3);
            }
        }
    }
}

// ---------------- weight prep: transpose fp32 [K][N] -> fp16 [N][K] ----------------
__global__ void wprep_k(const float* __restrict__ w, int K, int N, half_t* __restrict__ o)
{
    int idx = blockIdx.x * blockDim.x + threadIdx.x;
    if (idx >= K * N) return;
    int n = idx / K, k = idx % K;
    o[idx] = __float2half_rn(w[(size_t)k * N + n]);
}

// ---------------- addvec: srcH = h(src); QH = h(src+pos) ----------------
__global__ void addvec_k(const float* __restrict__ a, const float* __restrict__ b,
                         half_t* __restrict__ sh, half_t* __restrict__ qh)
{
    int i = blockIdx.x * blockDim.x + threadIdx.x;   // float4 group, exact RR*CD/4
    float4 x = reinterpret_cast<const float4*>(a)[i];
    float4 y = reinterpret_cast<const float4*>(b)[i];
    __half2 s0 = __floats2half2_rn(x.x, x.y);
    __half2 s1 = __floats2half2_rn(x.z, x.w);
    __half2 q0 = __floats2half2_rn(x.x + y.x, x.y + y.y);
    __half2 q1 = __floats2half2_rn(x.z + y.z, x.w + y.w);
    reinterpret_cast<__half2*>(sh)[i * 2 + 0] = s0;
    reinterpret_cast<__half2*>(sh)[i * 2 + 1] = s1;
    reinterpret_cast<__half2*>(qh)[i * 2 + 0] = q0;
    reinterpret_cast<__half2*>(qh)[i * 2 + 1] = q1;
}

// ---------------- deformable sampling + fused softmax -> fp16 out ----------------
__global__ void deform_k(const float* __restrict__ V, const float* __restrict__ OA,
                         const float* __restrict__ REF, half_t* __restrict__ OUT)
{
    const int row = blockIdx.x;
    const int h = threadIdx.x >> 5;
    const int d = threadIdx.x & 31;
    const int n = row / LQN;

    const float* lgp = OA + (size_t)row * 384 + 256 + h * 16;
    float lg = (d < 16) ? lgp[d] : -1e30f;
    float mx = lg;
#pragma unroll
    for (int o = 8; o; o >>= 1) mx = fmaxf(mx, __shfl_xor_sync(0xffffffffu, mx, o));
    float ev = (d < 16) ? expf(lg - mx) : 0.f;
    float sum = ev;
#pragma unroll
    for (int o = 8; o; o >>= 1) sum += __shfl_xor_sync(0xffffffffu, sum, o);
    float prob = ev / sum;

    const float* off = OA + (size_t)row * 384 + h * 32;
    const float* ref = REF + (size_t)row * 8;
    const float* Vb  = V + (size_t)n * LQN * 256 + h * 32 + d;

    const int   Wt[4]   = {64, 32, 16, 8};
    const int   St[4]   = {0, 4096, 5120, 5376};
    const float invW[4] = {1.f/64.f, 1.f/32.f, 1.f/16.f, 1.f/8.f};

    float acc = 0.f;
#pragma unroll
    for (int l = 0; l < 4; l++) {
        const int W = Wt[l], H = Wt[l];
        const float* Vl = Vb + (size_t)St[l] * 256;
        const float rx = ref[l * 2 + 0], ry = ref[l * 2 + 1];
#pragma unroll
        for (int p = 0; p < 4; p++) {
            float ox = off[l * 8 + p * 2 + 0];
            float oy = off[l * 8 + p * 2 + 1];
            float lx = rx + ox * invW[l];
            float ly = ry + oy * invW[l];
            float gx = 2.f * lx - 1.f, gy = 2.f * ly - 1.f;
            float x = (gx + 1.f) * (W * 0.5f) - 0.5f;
            float y = (gy + 1.f) * (H * 0.5f) - 0.5f;
            float x0f = floorf(x), y0f = floorf(y);
            float wx = x - x0f, wy = y - y0f;
            int x0 = (int)x0f, y0 = (int)y0f;
            float a = __shfl_sync(0xffffffffu, prob, l * 4 + p);
            bool xv0 = (x0 >= 0)  && (x0 < W);
            bool xv1 = (x0 >= -1) && (x0 < W - 1);
            bool yv0 = (y0 >= 0)  && (y0 < H);
            bool yv1 = (y0 >= -1) && (y0 < H - 1);
            float w00 = (1.f - wx) * (1.f - wy) * a;
            float w10 = wx * (1.f - wy) * a;
            float w01 = (1.f - wx) * wy * a;
            float w11 = wx * wy * a;
            if (xv0 && yv0) acc += w00 * Vl[(y0 * W + x0) * 256];
            if (xv1 && yv0) acc += w10 * Vl[(y0 * W + x0 + 1) * 256];
            if (xv0 && yv1) acc += w01 * Vl[((y0 + 1) * W + x0) * 256];
            if (xv1 && yv1) acc += w11 * Vl[((y0 + 1) * W + x0 + 1) * 256];
        }
    }
    OUT[(size_t)row * 256 + h * 32 + d] = __float2half_rn(acc);
}

// ---------------- layernorm over C=256, block = row ----------------
template<bool PAIRH>
__global__ void ln_k(const float* __restrict__ in, const float* __restrict__ g,
                     const float* __restrict__ b, float* __restrict__ out,
                     half_t* __restrict__ oh)
{
    const int row = blockIdx.x, c = threadIdx.x;
    float v = in[(size_t)row * 256 + c];
    float s = v;
#pragma unroll
    for (int o = 16; o; o >>= 1) s += __shfl_xor_sync(0xffffffffu, s, o);
    __shared__ float sm1[8], sm2[8];
    if ((c & 31) == 0) sm1[c >> 5] = s;
    __syncthreads();
    float tot = 0.f;
#pragma unroll
    for (int i = 0; i < 8; i++) tot += sm1[i];
    float m = tot * (1.f / 256.f);
    float dd = v - m;
    float q = dd * dd;
#pragma unroll
    for (int o = 16; o; o >>= 1) q += __shfl_xor_sync(0xffffffffu, q, o);
    if ((c & 31) == 0) sm2[c >> 5] = q;
    __syncthreads();
    float tv = 0.f;
#pragma unroll
    for (int i = 0; i < 8; i++) tv += sm2[i];
    float var = tv * (1.f / 256.f);
    float r = dd * rsqrtf(var + 1e-5f) * g[c] + b[c];
    out[(size_t)row * 256 + c] = r;
    if (PAIRH) oh[(size_t)row * 256 + c] = __float2half_rn(r);
}

// ---------------- launch ----------------
extern "C" void kernel_launch(void* const* d_in, const int* in_sizes, int n_in,
                              void* d_out, int out_size)
{
    const float* src    = (const float*)d_in[0];
    const float* pos    = (const float*)d_in[1];
    const float* ref    = (const float*)d_in[2];
    const float* w_off  = (const float*)d_in[3];
    const float* b_off  = (const float*)d_in[4];
    const float* w_attn = (const float*)d_in[5];
    const float* b_attn = (const float*)d_in[6];
    const float* w_val  = (const float*)d_in[7];
    const float* b_val  = (const float*)d_in[8];
    const float* w_out  = (const float*)d_in[9];
    const float* b_out  = (const float*)d_in[10];
    const float* g1     = (const float*)d_in[11];
    const float* be1    = (const float*)d_in[12];
    const float* w_ff1  = (const float*)d_in[13];
    const float* b_ff1  = (const float*)d_in[14];
    const float* w_ff2  = (const float*)d_in[15];
    const float* b_ff2  = (const float*)d_in[16];
    const float* g2     = (const float*)d_in[17];
    const float* be2    = (const float*)d_in[18];
    const unsigned char* mask = (const unsigned char*)d_in[19];

    half_t *srcH, *QH, *ATTH, *XH, *HH, *WvT, *WqaT, *WuT, *W1T, *W2T;
    float *pV, *pOA, *pS, *pX, *pY, *pbqa;
    cudaGetSymbolAddress((void**)&srcH, g_srcH);
    cudaGetSymbolAddress((void**)&QH,   g_QH);
    cudaGetSymbolAddress((void**)&ATTH, g_ATTH);
    cudaGetSymbolAddress((void**)&XH,   g_XH);
    cudaGetSymbolAddress((void**)&HH,   g_HH);
    cudaGetSymbolAddress((void**)&WvT,  g_WvT);
    cudaGetSymbolAddress((void**)&WqaT, g_WqaT);
    cudaGetSymbolAddress((void**)&WuT,  g_WuT);
    cudaGetSymbolAddress((void**)&W1T,  g_W1T);
    cudaGetSymbolAddress((void**)&W2T,  g_W2T);
    cudaGetSymbolAddress((void**)&pV,   g_V);
    cudaGetSymbolAddress((void**)&pOA,  g_OA);
    cudaGetSymbolAddress((void**)&pS,   g_S);
    cudaGetSymbolAddress((void**)&pX,   g_X);
    cudaGetSymbolAddress((void**)&pY,   g_Y);
    cudaGetSymbolAddress((void**)&pbqa, g_bqa);

    cudaFuncSetAttribute(hgemm_k<false, false, true,  false>, cudaFuncAttributeMaxDynamicSharedMemorySize, SMEM_BYTES);
    cudaFuncSetAttribute(hgemm_k<false, false, false, false>, cudaFuncAttributeMaxDynamicSharedMemorySize, SMEM_BYTES);
    cudaFuncSetAttribute(hgemm_k<false, true,  false, false>, cudaFuncAttributeMaxDynamicSharedMemorySize, SMEM_BYTES);
    cudaFuncSetAttribute(hgemm_k<true,  false, false, true >, cudaFuncAttributeMaxDynamicSharedMemorySize, SMEM_BYTES);

    // weight prep: transpose to [N][K] fp16; off+attn concatenated
    wprep_k<<<(CD * CD   + 255) / 256, 256>>>(w_val,  CD,   CD,   WvT);
    wprep_k<<<(CD * CD   + 255) / 256, 256>>>(w_off,  CD,   CD,   WqaT);
    wprep_k<<<(CD * 128  + 255) / 256, 256>>>(w_attn, CD,   128,  WqaT + 256 * CD);
    wprep_k<<<(CD * CD   + 255) / 256, 256>>>(w_out,  CD,   CD,   WuT);
    wprep_k<<<(CD * DFFN + 255) / 256, 256>>>(w_ff1,  CD,   DFFN, W1T);
    wprep_k<<<(DFFN * CD + 255) / 256, 256>>>(w_ff2,  DFFN, CD,   W2T);
    cudaMemcpyAsync(pbqa,       b_off,  256 * sizeof(float), cudaMemcpyDeviceToDevice);
    cudaMemcpyAsync(pbqa + 256, b_attn, 128 * sizeof(float), cudaMemcpyDeviceToDevice);

    addvec_k<<<RR * CD / 4 / 256, 256>>>(src, pos, srcH, QH);

    // value = mask0(src @ w_val + b_val)
    hgemm_k<false, false, true,  false><<<dim3(340, 2), 256, SMEM_BYTES>>>(
        srcH, WvT, b_val, nullptr, mask, pV, nullptr, 256, 256);
    // [off | attn logits] = Q @ [w_off | w_attn] + [b_off | b_attn]
    hgemm_k<false, false, false, false><<<dim3(340, 3), 256, SMEM_BYTES>>>(
        QH, WqaT, pbqa, nullptr, nullptr, pOA, nullptr, 256, 384);
    deform_k<<<RR, 256>>>(pV, pOA, ref, ATTH);
    // S = src + (ATT @ w_out + b_out)
    hgemm_k<false, true,  false, false><<<dim3(340, 2), 256, SMEM_BYTES>>>(
        ATTH, WuT, b_out, src, nullptr, pS, nullptr, 256, 256);
    ln_k<true ><<<RR, 256>>>(pS, g1, be1, pX, XH);
    // H = relu(X @ w_ff1 + b_ff1) -> fp16
    hgemm_k<true,  false, false, true ><<<dim3(340, 8), 256, SMEM_BYTES>>>(
        XH, W1T, b_ff1, nullptr, nullptr, nullptr, HH, 256, 1024);
    // Y = X + (H @ w_ff2 + b_ff2)
    hgemm_k<false, true,  false, false><<<dim3(340, 2), 256, SMEM_BYTES>>>(
        HH, W2T, b_ff2, pX, nullptr, pY, nullptr, 1024, 256);
    ln_k<false><<<RR, 256>>>(pY, g2, be2, (float*)d_out, nullptr);
}

// round 6
// speedup vs baseline: 3.1325x; 1.0283x over previous
#include <cuda_runtime.h>
#include <cuda_fp16.h>
#include <cstdint>

#define NB 8
#define LQN 5440
#define CD 256
#define RR 43520          // NB*LQN
#define DFFN 1024

typedef __half half_t;

// ---------------- scratch (static device arrays; no allocation) ----------------
__device__ half_t g_srcH[RR * CD];
__device__ half_t g_QH  [RR * CD];
__device__ half_t g_VH  [RR * CD];           // value projection fp16
__device__ half_t g_ATTH[RR * CD];
__device__ half_t g_XH  [RR * CD];
__device__ half_t g_HH  [RR * DFFN];
// transposed fp16 weights [N][K]
__device__ half_t g_WvT [CD * CD];
__device__ half_t g_WqaT[384 * CD];
__device__ half_t g_WuT [CD * CD];
__device__ half_t g_W1T [DFFN * CD];
__device__ half_t g_W2T [CD * DFFN];
__device__ float  g_bqa [384];
// fp32 intermediates
__device__ float g_OA [RR * 384];            // off (256) ++ logits (128)
__device__ float g_S  [RR * CD];
__device__ float g_X  [RR * CD];
__device__ float g_Y  [RR * CD];

// ---------------- PTX helpers ----------------
__device__ __forceinline__ void mma_fp16(float d[4], const uint32_t a[4],
                                         const uint32_t b[2]) {
    asm volatile(
        "mma.sync.aligned.m16n8k16.row.col.f32.f16.f16.f32 "
        "{%0,%1,%2,%3}, {%4,%5,%6,%7}, {%8,%9}, {%0,%1,%2,%3};\n"
        : "+f"(d[0]), "+f"(d[1]), "+f"(d[2]), "+f"(d[3])
        : "r"(a[0]), "r"(a[1]), "r"(a[2]), "r"(a[3]),
          "r"(b[0]), "r"(b[1]));
}
__device__ __forceinline__ void ldsm4(uint32_t& r0, uint32_t& r1, uint32_t& r2,
                                      uint32_t& r3, uint32_t addr) {
    asm volatile("ldmatrix.sync.aligned.m8n8.x4.shared.b16 {%0,%1,%2,%3}, [%4];"
                 : "=r"(r0), "=r"(r1), "=r"(r2), "=r"(r3) : "r"(addr));
}
__device__ __forceinline__ void cp_async16(void* s, const void* g) {
    uint32_t sa = (uint32_t)__cvta_generic_to_shared(s);
    asm volatile("cp.async.cg.shared.global [%0], [%1], 16;\n" :: "r"(sa), "l"(g));
}
__device__ __forceinline__ void cp_commit() { asm volatile("cp.async.commit_group;\n"); }
template<int N> __device__ __forceinline__ void cp_wait() {
    asm volatile("cp.async.wait_group %0;\n" :: "n"(N));
}

// ---------------- FP16 tensor-core GEMM, 3-stage cp.async + ldmatrix ------------
// C[R,Nout] = A[R,K] @ W[K,Nout], W stored transposed [Nout][K] fp16.
// BM=BN=128, BK=64, 256 threads (8 warps 2x4), warp tile 64x32, mma m16n8k16.
#define HS 72                           // half stride (64 + 8 pad)
#define TILE_HALFS (128 * HS)
#define STAGE_HALFS (2 * TILE_HALFS)
#define TILE_BYTES (TILE_HALFS * 2)
#define STAGE_BYTES (STAGE_HALFS * 2)
#define SMEM_BYTES (3 * STAGE_BYTES)    // 110,592 B

template<bool RELU, bool HAS_RES, bool MASK, bool HALF_OUT>
__global__ __launch_bounds__(256, 2)
void hgemm_k(const half_t* __restrict__ A, const half_t* __restrict__ B,
             const float* __restrict__ bias, const float* __restrict__ Res,
             const unsigned char* __restrict__ mask,
             float* __restrict__ Cf, half_t* __restrict__ Ch, int K, int Nout)
{
    extern __shared__ half_t sm[];

    const int tid  = threadIdx.x;
    const int brow = blockIdx.x * 128;
    const int bcol = blockIdx.y * 128;

    const int lane = tid & 31;
    const int wid  = tid >> 5;
    const int wm   = (wid >> 2) * 64;
    const int wn   = (wid & 3) * 32;
    const int gr   = lane >> 2;
    const int gc   = lane & 3;

    // ldmatrix per-lane byte offsets
    const uint32_t smemU = (uint32_t)__cvta_generic_to_shared(sm);
    const uint32_t aOff = ((wm + (lane & 7) + ((lane >> 3) & 1) * 8) * HS
                           + ((lane >> 4) & 1) * 8) * 2;
    const uint32_t bOff = ((wn + (lane & 7) + ((lane >> 4) & 1) * 8) * HS
                           + ((lane >> 3) & 1) * 8) * 2;

    float acc[4][4][4];
#pragma unroll
    for (int i = 0; i < 4; i++)
#pragma unroll
        for (int j = 0; j < 4; j++)
#pragma unroll
            for (int t = 0; t < 4; t++) acc[i][j][t] = 0.f;

    const int nch = K >> 6;

    auto issue = [&](int chunk, int stg) {
        const int k0 = chunk << 6;
        half_t* As = sm + stg * STAGE_HALFS;
        half_t* Bs = As + TILE_HALFS;
#pragma unroll
        for (int i = 0; i < 4; i++) {
            int t = tid + i * 256;
            int r = t >> 3, q = (t & 7) << 3;
            cp_async16(As + r * HS + q, A + (size_t)(brow + r) * K + k0 + q);
        }
#pragma unroll
        for (int i = 0; i < 4; i++) {
            int t = tid + i * 256;
            int r = t >> 3, q = (t & 7) << 3;
            cp_async16(Bs + r * HS + q, B + (size_t)(bcol + r) * K + k0 + q);
        }
        cp_commit();
    };

    issue(0, 0);
    if (nch > 1) issue(1, 1);
    else cp_commit();

    for (int c = 0; c < nch; c++) {
        const int cur = c % 3;
        if (c + 2 < nch) issue(c + 2, (c + 2) % 3);
        else cp_commit();
        cp_wait<2>();
        __syncthreads();

        const uint32_t aBase = smemU + cur * STAGE_BYTES + aOff;
        const uint32_t bBase = smemU + cur * STAGE_BYTES + TILE_BYTES + bOff;
#pragma unroll
        for (int kk = 0; kk < 4; kk++) {
            uint32_t af[4][4], bf[4][2];
#pragma unroll
            for (int mt = 0; mt < 4; mt++)
                ldsm4(af[mt][0], af[mt][1], af[mt][2], af[mt][3],
                      aBase + mt * (16 * HS * 2) + kk * 32);
#pragma unroll
            for (int ntp = 0; ntp < 2; ntp++)
                ldsm4(bf[2 * ntp][0], bf[2 * ntp][1], bf[2 * ntp + 1][0], bf[2 * ntp + 1][1],
                      bBase + ntp * (16 * HS * 2) + kk * 32);
#pragma unroll
            for (int mt = 0; mt < 4; mt++)
#pragma unroll
                for (int nt = 0; nt < 4; nt++)
                    mma_fp16(acc[mt][nt], af[mt], bf[nt]);
        }
        __syncthreads();
    }

#pragma unroll
    for (int mt = 0; mt < 4; mt++) {
        int r0 = brow + wm + mt * 16 + gr;
        int r1 = r0 + 8;
        float ms0 = 1.f, ms1 = 1.f;
        if (MASK) { ms0 = mask[r0] ? 0.f : 1.f; ms1 = mask[r1] ? 0.f : 1.f; }
#pragma unroll
        for (int nt = 0; nt < 4; nt++) {
            int col = bcol + wn + nt * 8 + gc * 2;
            float2 bi = *reinterpret_cast<const float2*>(&bias[col]);
            float v0 = acc[mt][nt][0] + bi.x;
            float v1 = acc[mt][nt][1] + bi.y;
            float v2 = acc[mt][nt][2] + bi.x;
            float v3 = acc[mt][nt][3] + bi.y;
            if (MASK) { v0 *= ms0; v1 *= ms0; v2 *= ms1; v3 *= ms1; }
            if (RELU) {
                v0 = fmaxf(v0, 0.f); v1 = fmaxf(v1, 0.f);
                v2 = fmaxf(v2, 0.f); v3 = fmaxf(v3, 0.f);
            }
            if (HAS_RES) {
                float2 e0 = *reinterpret_cast<const float2*>(&Res[(size_t)r0 * Nout + col]);
                float2 e1 = *reinterpret_cast<const float2*>(&Res[(size_t)r1 * Nout + col]);
                v0 += e0.x; v1 += e0.y; v2 += e1.x; v3 += e1.y;
            }
            if (HALF_OUT) {
                *reinterpret_cast<__half2*>(&Ch[(size_t)r0 * Nout + col]) = __floats2half2_rn(v0, v1);
                *reinterpret_cast<__half2*>(&Ch[(size_t)r1 * Nout + col]) = __floats2half2_rn(v2, v3);
            } else {
                *reinterpret_cast<float2*>(&Cf[(size_t)r0 * Nout + col]) = make_float2(v0, v1);
                *reinterpret_cast<float2*>(&Cf[(size_t)r1 * Nout + col]) = make_float2(v2, v3);
            }
        }
    }
}

// ---------------- merged prep: all weight transposes + bias concat ----------------
// segments (element-transpose to [N][K] fp16)
__global__ void prep_k(const float* __restrict__ w_val, const float* __restrict__ w_off,
                       const float* __restrict__ w_attn, const float* __restrict__ w_out,
                       const float* __restrict__ w_ff1, const float* __restrict__ w_ff2,
                       const float* __restrict__ b_off, const float* __restrict__ b_attn,
                       half_t* __restrict__ WvT, half_t* __restrict__ WqaT,
                       half_t* __restrict__ WuT, half_t* __restrict__ W1T,
                       half_t* __restrict__ W2T, float* __restrict__ bqa)
{
    int idx = blockIdx.x * blockDim.x + threadIdx.x;
    auto tr = [](const float* w, half_t* o, int i, int K, int N) {
        int n = i / K, k = i % K;
        o[i] = __float2half_rn(w[(size_t)k * N + n]);
    };
    if (idx < 65536)                { tr(w_val,  WvT,              idx,           256,  256);  return; }
    if ((idx -= 65536) < 65536)     { tr(w_off,  WqaT,             idx,           256,  256);  return; }
    if ((idx -= 65536) < 32768)     { tr(w_attn, WqaT + 256 * CD,  idx,           256,  128);  return; }
    if ((idx -= 32768) < 65536)     { tr(w_out,  WuT,              idx,           256,  256);  return; }
    if ((idx -= 65536) < 262144)    { tr(w_ff1,  W1T,              idx,           256,  1024); return; }
    if ((idx -= 262144) < 262144)   { tr(w_ff2,  W2T,              idx,           1024, 256);  return; }
    idx -= 262144;
    if (idx < 256)      bqa[idx] = b_off[idx];
    else if (idx < 384) bqa[idx] = b_attn[idx - 256];
}

// ---------------- addvec: srcH = h(src); QH = h(src+pos) ----------------
__global__ void addvec_k(const float* __restrict__ a, const float* __restrict__ b,
                         half_t* __restrict__ sh, half_t* __restrict__ qh)
{
    int i = blockIdx.x * blockDim.x + threadIdx.x;
    float4 x = reinterpret_cast<const float4*>(a)[i];
    float4 y = reinterpret_cast<const float4*>(b)[i];
    __half2 s0 = __floats2half2_rn(x.x, x.y);
    __half2 s1 = __floats2half2_rn(x.z, x.w);
    __half2 q0 = __floats2half2_rn(x.x + y.x, x.y + y.y);
    __half2 q1 = __floats2half2_rn(x.z + y.z, x.w + y.w);
    reinterpret_cast<__half2*>(sh)[i * 2 + 0] = s0;
    reinterpret_cast<__half2*>(sh)[i * 2 + 1] = s1;
    reinterpret_cast<__half2*>(qh)[i * 2 + 0] = q0;
    reinterpret_cast<__half2*>(qh)[i * 2 + 1] = q1;
}

// ---------------- deformable sampling + fused softmax (V fp16) ----------------
__global__ void deform_k(const half_t* __restrict__ V, const float* __restrict__ OA,
                         const float* __restrict__ REF, half_t* __restrict__ OUT)
{
    const int row = blockIdx.x;
    const int h = threadIdx.x >> 5;
    const int d = threadIdx.x & 31;
    const int n = row / LQN;

    const float* lgp = OA + (size_t)row * 384 + 256 + h * 16;
    float lg = (d < 16) ? lgp[d] : -1e30f;
    float mx = lg;
#pragma unroll
    for (int o = 8; o; o >>= 1) mx = fmaxf(mx, __shfl_xor_sync(0xffffffffu, mx, o));
    float ev = (d < 16) ? expf(lg - mx) : 0.f;
    float sum = ev;
#pragma unroll
    for (int o = 8; o; o >>= 1) sum += __shfl_xor_sync(0xffffffffu, sum, o);
    float prob = ev / sum;

    const float* off = OA + (size_t)row * 384 + h * 32;
    const float* ref = REF + (size_t)row * 8;
    const half_t* Vb = V + (size_t)n * LQN * 256 + h * 32 + d;

    const int   Wt[4]   = {64, 32, 16, 8};
    const int   St[4]   = {0, 4096, 5120, 5376};
    const float invW[4] = {1.f/64.f, 1.f/32.f, 1.f/16.f, 1.f/8.f};

    float acc = 0.f;
#pragma unroll
    for (int l = 0; l < 4; l++) {
        const int W = Wt[l], H = Wt[l];
        const half_t* Vl = Vb + (size_t)St[l] * 256;
        const float rx = ref[l * 2 + 0], ry = ref[l * 2 + 1];
#pragma unroll
        for (int p = 0; p < 4; p++) {
            float ox = off[l * 8 + p * 2 + 0];
            float oy = off[l * 8 + p * 2 + 1];
            float lx = rx + ox * invW[l];
            float ly = ry + oy * invW[l];
            float gx = 2.f * lx - 1.f, gy = 2.f * ly - 1.f;
            float x = (gx + 1.f) * (W * 0.5f) - 0.5f;
            float y = (gy + 1.f) * (H * 0.5f) - 0.5f;
            float x0f = floorf(x), y0f = floorf(y);
            float wx = x - x0f, wy = y - y0f;
            int x0 = (int)x0f, y0 = (int)y0f;
            float a = __shfl_sync(0xffffffffu, prob, l * 4 + p);
            bool xv0 = (x0 >= 0)  && (x0 < W);
            bool xv1 = (x0 >= -1) && (x0 < W - 1);
            bool yv0 = (y0 >= 0)  && (y0 < H);
            bool yv1 = (y0 >= -1) && (y0 < H - 1);
            float w00 = (1.f - wx) * (1.f - wy) * a;
            float w10 = wx * (1.f - wy) * a;
            float w01 = (1.f - wx) * wy * a;
            float w11 = wx * wy * a;
            if (xv0 && yv0) acc += w00 * __half2float(Vl[(y0 * W + x0) * 256]);
            if (xv1 && yv0) acc += w10 * __half2float(Vl[(y0 * W + x0 + 1) * 256]);
            if (xv0 && yv1) acc += w01 * __half2float(Vl[((y0 + 1) * W + x0) * 256]);
            if (xv1 && yv1) acc += w11 * __half2float(Vl[((y0 + 1) * W + x0 + 1) * 256]);
        }
    }
    OUT[(size_t)row * 256 + h * 32 + d] = __float2half_rn(acc);
}

// ---------------- layernorm over C=256, block = row ----------------
template<bool PAIRH>
__global__ void ln_k(const float* __restrict__ in, const float* __restrict__ g,
                     const float* __restrict__ b, float* __restrict__ out,
                     half_t* __restrict__ oh)
{
    const int row = blockIdx.x, c = threadIdx.x;
    float v = in[(size_t)row * 256 + c];
    float s = v;
#pragma unroll
    for (int o = 16; o; o >>= 1) s += __shfl_xor_sync(0xffffffffu, s, o);
    __shared__ float sm1[8], sm2[8];
    if ((c & 31) == 0) sm1[c >> 5] = s;
    __syncthreads();
    float tot = 0.f;
#pragma unroll
    for (int i = 0; i < 8; i++) tot += sm1[i];
    float m = tot * (1.f / 256.f);
    float dd = v - m;
    float q = dd * dd;
#pragma unroll
    for (int o = 16; o; o >>= 1) q += __shfl_xor_sync(0xffffffffu, q, o);
    if ((c & 31) == 0) sm2[c >> 5] = q;
    __syncthreads();
    float tv = 0.f;
#pragma unroll
    for (int i = 0; i < 8; i++) tv += sm2[i];
    float var = tv * (1.f / 256.f);
    float r = dd * rsqrtf(var + 1e-5f) * g[c] + b[c];
    out[(size_t)row * 256 + c] = r;
    if (PAIRH) oh[(size_t)row * 256 + c] = __float2half_rn(r);
}

// ---------------- launch ----------------
extern "C" void kernel_launch(void* const* d_in, const int* in_sizes, int n_in,
                              void* d_out, int out_size)
{
    const float* src    = (const float*)d_in[0];
    const float* pos    = (const float*)d_in[1];
    const float* ref    = (const float*)d_in[2];
    const float* w_off  = (const float*)d_in[3];
    const float* b_off  = (const float*)d_in[4];
    const float* w_attn = (const float*)d_in[5];
    const float* b_attn = (const float*)d_in[6];
    const float* w_val  = (const float*)d_in[7];
    const float* b_val  = (const float*)d_in[8];
    const float* w_out  = (const float*)d_in[9];
    const float* b_out  = (const float*)d_in[10];
    const float* g1     = (const float*)d_in[11];
    const float* be1    = (const float*)d_in[12];
    const float* w_ff1  = (const float*)d_in[13];
    const float* b_ff1  = (const float*)d_in[14];
    const float* w_ff2  = (const float*)d_in[15];
    const float* b_ff2  = (const float*)d_in[16];
    const float* g2     = (const float*)d_in[17];
    const float* be2    = (const float*)d_in[18];
    const unsigned char* mask = (const unsigned char*)d_in[19];

    half_t *srcH, *QH, *VH, *ATTH, *XH, *HH, *WvT, *WqaT, *WuT, *W1T, *W2T;
    float *pOA, *pS, *pX, *pY, *pbqa;
    cudaGetSymbolAddress((void**)&srcH, g_srcH);
    cudaGetSymbolAddress((void**)&QH,   g_QH);
    cudaGetSymbolAddress((void**)&VH,   g_VH);
    cudaGetSymbolAddress((void**)&ATTH, g_ATTH);
    cudaGetSymbolAddress((void**)&XH,   g_XH);
    cudaGetSymbolAddress((void**)&HH,   g_HH);
    cudaGetSymbolAddress((void**)&WvT,  g_WvT);
    cudaGetSymbolAddress((void**)&WqaT, g_WqaT);
    cudaGetSymbolAddress((void**)&WuT,  g_WuT);
    cudaGetSymbolAddress((void**)&W1T,  g_W1T);
    cudaGetSymbolAddress((void**)&W2T,  g_W2T);
    cudaGetSymbolAddress((void**)&pOA,  g_OA);
    cudaGetSymbolAddress((void**)&pS,   g_S);
    cudaGetSymbolAddress((void**)&pX,   g_X);
    cudaGetSymbolAddress((void**)&pY,   g_Y);
    cudaGetSymbolAddress((void**)&pbqa, g_bqa);

    cudaFuncSetAttribute(hgemm_k<false, false, true,  true >, cudaFuncAttributeMaxDynamicSharedMemorySize, SMEM_BYTES);
    cudaFuncSetAttribute(hgemm_k<false, false, false, false>, cudaFuncAttributeMaxDynamicSharedMemorySize, SMEM_BYTES);
    cudaFuncSetAttribute(hgemm_k<false, true,  false, false>, cudaFuncAttributeMaxDynamicSharedMemorySize, SMEM_BYTES);
    cudaFuncSetAttribute(hgemm_k<true,  false, false, true >, cudaFuncAttributeMaxDynamicSharedMemorySize, SMEM_BYTES);

    addvec_k<<<RR * CD / 4 / 256, 256>>>(src, pos, srcH, QH);
    prep_k<<<(754048 + 255) / 256, 256>>>(w_val, w_off, w_attn, w_out, w_ff1, w_ff2,
                                          b_off, b_attn, WvT, WqaT, WuT, W1T, W2T, pbqa);

    // value = mask0(src @ w_val + b_val) -> fp16
    hgemm_k<false, false, true,  true ><<<dim3(340, 2), 256, SMEM_BYTES>>>(
        srcH, WvT, b_val, nullptr, mask, nullptr, VH, 256, 256);
    // [off | attn logits] = Q @ [w_off | w_attn] + [b_off | b_attn]
    hgemm_k<false, false, false, false><<<dim3(340, 3), 256, SMEM_BYTES>>>(
        QH, WqaT, pbqa, nullptr, nullptr, pOA, nullptr, 256, 384);
    deform_k<<<RR, 256>>>(VH, pOA, ref, ATTH);
    // S = src + (ATT @ w_out + b_out)
    hgemm_k<false, true,  false, false><<<dim3(340, 2), 256, SMEM_BYTES>>>(
        ATTH, WuT, b_out, src, nullptr, pS, nullptr, 256, 256);
    ln_k<true ><<<RR, 256>>>(pS, g1, be1, pX, XH);
    // H = relu(X @ w_ff1 + b_ff1) -> fp16
    hgemm_k<true,  false, false, true ><<<dim3(340, 8), 256, SMEM_BYTES>>>(
        XH, W1T, b_ff1, nullptr, nullptr, nullptr, HH, 256, 1024);
    // Y = X + (H @ w_ff2 + b_ff2)
    hgemm_k<false, true,  false, false><<<dim3(340, 2), 256, SMEM_BYTES>>>(
        HH, W2T, b_ff2, pX, nullptr, pY, nullptr, 1024, 256);
    ln_k<false><<<RR, 256>>>(pY, g2, be2, (float*)d_out, nullptr);
}

// round 9
// speedup vs baseline: 3.4666x; 1.1066x over previous
#include <cuda_runtime.h>
#include <cuda_fp16.h>
#include <cstdint>

#define NB 8
#define LQN 5440
#define CD 256
#define RR 43520          // NB*LQN
#define DFFN 1024

typedef __half half_t;

// ---------------- scratch (static device arrays; no allocation) ----------------
__device__ half_t g_srcH[RR * CD];
__device__ half_t g_QH  [RR * CD];
__device__ half_t g_VH  [RR * CD];
__device__ half_t g_ATTH[RR * CD];
__device__ half_t g_XH  [RR * CD];
__device__ half_t g_HH  [RR * DFFN];
// transposed fp16 weights [N][K]
__device__ half_t g_WvT [CD * CD];
__device__ half_t g_WqaT[384 * CD];
__device__ half_t g_WuT [CD * CD];
__device__ half_t g_W1T [DFFN * CD];
__device__ half_t g_W2T [CD * DFFN];
__device__ float  g_bqa [384];
// fp32 intermediates
__device__ float g_OA [RR * 384];            // off (256) ++ logits (128)
__device__ float g_X  [RR * CD];             // LN1 output fp32 (residual for LN2)

// ---------------- PTX helpers ----------------
__device__ __forceinline__ void mma_fp16(float d[4], const uint32_t a[4],
                                         const uint32_t b[2]) {
    asm volatile(
        "mma.sync.aligned.m16n8k16.row.col.f32.f16.f16.f32 "
        "{%0,%1,%2,%3}, {%4,%5,%6,%7}, {%8,%9}, {%0,%1,%2,%3};\n"
        : "+f"(d[0]), "+f"(d[1]), "+f"(d[2]), "+f"(d[3])
        : "r"(a[0]), "r"(a[1]), "r"(a[2]), "r"(a[3]),
          "r"(b[0]), "r"(b[1]));
}
__device__ __forceinline__ void ldsm4(uint32_t& r0, uint32_t& r1, uint32_t& r2,
                                      uint32_t& r3, uint32_t addr) {
    asm volatile("ldmatrix.sync.aligned.m8n8.x4.shared.b16 {%0,%1,%2,%3}, [%4];"
                 : "=r"(r0), "=r"(r1), "=r"(r2), "=r"(r3) : "r"(addr));
}
__device__ __forceinline__ void cp_async16(void* s, const void* g) {
    uint32_t sa = (uint32_t)__cvta_generic_to_shared(s);
    asm volatile("cp.async.cg.shared.global [%0], [%1], 16;\n" :: "r"(sa), "l"(g));
}
__device__ __forceinline__ void cp_commit() { asm volatile("cp.async.commit_group;\n"); }
template<int N> __device__ __forceinline__ void cp_wait() {
    asm volatile("cp.async.wait_group %0;\n" :: "n"(N));
}

#define HS 72                           // half stride (64 + 8 pad)

// ================= generic FP16 GEMM (BM=BN=128, 3-stage) =================
#define TILE_HALFS (128 * HS)
#define STAGE_HALFS (2 * TILE_HALFS)
#define TILE_BYTES (TILE_HALFS * 2)
#define STAGE_BYTES (STAGE_HALFS * 2)
#define SMEM_BYTES (3 * STAGE_BYTES)    // 110,592 B

template<bool RELU, bool MASK, bool HALF_OUT>
__global__ __launch_bounds__(256, 2)
void hgemm_k(const half_t* __restrict__ A, const half_t* __restrict__ B,
             const float* __restrict__ bias, const unsigned char* __restrict__ mask,
             float* __restrict__ Cf, half_t* __restrict__ Ch, int K, int Nout)
{
    extern __shared__ half_t sm[];

    const int tid  = threadIdx.x;
    const int brow = blockIdx.x * 128;
    const int bcol = blockIdx.y * 128;

    const int lane = tid & 31;
    const int wid  = tid >> 5;
    const int wm   = (wid >> 2) * 64;
    const int wn   = (wid & 3) * 32;
    const int gr   = lane >> 2;
    const int gc   = lane & 3;

    const uint32_t smemU = (uint32_t)__cvta_generic_to_shared(sm);
    const uint32_t aOff = ((wm + (lane & 7) + ((lane >> 3) & 1) * 8) * HS
                           + ((lane >> 4) & 1) * 8) * 2;
    const uint32_t bOff = ((wn + (lane & 7) + ((lane >> 4) & 1) * 8) * HS
                           + ((lane >> 3) & 1) * 8) * 2;

    float acc[4][4][4];
#pragma unroll
    for (int i = 0; i < 4; i++)
#pragma unroll
        for (int j = 0; j < 4; j++)
#pragma unroll
            for (int t = 0; t < 4; t++) acc[i][j][t] = 0.f;

    const int nch = K >> 6;

    auto issue = [&](int chunk, int stg) {
        const int k0 = chunk << 6;
        half_t* As = sm + stg * STAGE_HALFS;
        half_t* Bs = As + TILE_HALFS;
#pragma unroll
        for (int i = 0; i < 4; i++) {
            int t = tid + i * 256;
            int r = t >> 3, q = (t & 7) << 3;
            cp_async16(As + r * HS + q, A + (size_t)(brow + r) * K + k0 + q);
        }
#pragma unroll
        for (int i = 0; i < 4; i++) {
            int t = tid + i * 256;
            int r = t >> 3, q = (t & 7) << 3;
            cp_async16(Bs + r * HS + q, B + (size_t)(bcol + r) * K + k0 + q);
        }
        cp_commit();
    };

    issue(0, 0);
    if (nch > 1) issue(1, 1);
    else cp_commit();

    for (int c = 0; c < nch; c++) {
        const int cur = c % 3;
        if (c + 2 < nch) issue(c + 2, (c + 2) % 3);
        else cp_commit();
        cp_wait<2>();
        __syncthreads();

        const uint32_t aBase = smemU + cur * STAGE_BYTES + aOff;
        const uint32_t bBase = smemU + cur * STAGE_BYTES + TILE_BYTES + bOff;
#pragma unroll
        for (int kk = 0; kk < 4; kk++) {
            uint32_t af[4][4], bf[4][2];
#pragma unroll
            for (int mt = 0; mt < 4; mt++)
                ldsm4(af[mt][0], af[mt][1], af[mt][2], af[mt][3],
                      aBase + mt * (16 * HS * 2) + kk * 32);
#pragma unroll
            for (int ntp = 0; ntp < 2; ntp++)
                ldsm4(bf[2 * ntp][0], bf[2 * ntp][1], bf[2 * ntp + 1][0], bf[2 * ntp + 1][1],
                      bBase + ntp * (16 * HS * 2) + kk * 32);
#pragma unroll
            for (int mt = 0; mt < 4; mt++)
#pragma unroll
                for (int nt = 0; nt < 4; nt++)
                    mma_fp16(acc[mt][nt], af[mt], bf[nt]);
        }
        __syncthreads();
    }

#pragma unroll
    for (int mt = 0; mt < 4; mt++) {
        int r0 = brow + wm + mt * 16 + gr;
        int r1 = r0 + 8;
        float ms0 = 1.f, ms1 = 1.f;
        if (MASK) { ms0 = mask[r0] ? 0.f : 1.f; ms1 = mask[r1] ? 0.f : 1.f; }
#pragma unroll
        for (int nt = 0; nt < 4; nt++) {
            int col = bcol + wn + nt * 8 + gc * 2;
            float2 bi = *reinterpret_cast<const float2*>(&bias[col]);
            float v0 = acc[mt][nt][0] + bi.x;
            float v1 = acc[mt][nt][1] + bi.y;
            float v2 = acc[mt][nt][2] + bi.x;
            float v3 = acc[mt][nt][3] + bi.y;
            if (MASK) { v0 *= ms0; v1 *= ms0; v2 *= ms1; v3 *= ms1; }
            if (RELU) {
                v0 = fmaxf(v0, 0.f); v1 = fmaxf(v1, 0.f);
                v2 = fmaxf(v2, 0.f); v3 = fmaxf(v3, 0.f);
            }
            if (HALF_OUT) {
                *reinterpret_cast<__half2*>(&Ch[(size_t)r0 * Nout + col]) = __floats2half2_rn(v0, v1);
                *reinterpret_cast<__half2*>(&Ch[(size_t)r1 * Nout + col]) = __floats2half2_rn(v2, v3);
            } else {
                *reinterpret_cast<float2*>(&Cf[(size_t)r0 * Nout + col]) = make_float2(v0, v1);
                *reinterpret_cast<float2*>(&Cf[(size_t)r1 * Nout + col]) = make_float2(v2, v3);
            }
        }
    }
}

// ============ fused GEMM + residual + LayerNorm (BM=64, BN=256, 2-stage) ============
// out = LN(Res + A@W + bias) * g + be ;  Nout fixed at 256.
#define LN_A_HALFS (64 * HS)
#define LN_B_HALFS (256 * HS)
#define LN_STAGE_HALFS (LN_A_HALFS + LN_B_HALFS)
#define LN_RED_FLOATS (2 * 64 * 8 + 64 * 2)
#define LN_SMEM_BYTES (2 * LN_STAGE_HALFS * 2 + LN_RED_FLOATS * 4)

template<bool WRITE_H>
__global__ __launch_bounds__(256, 2)
void hgemm_ln_k(const half_t* __restrict__ A, const half_t* __restrict__ B,
                const float* __restrict__ bias, const float* __restrict__ Res,
                const float* __restrict__ gam, const float* __restrict__ bet,
                float* __restrict__ Of, half_t* __restrict__ Oh, int K)
{
    extern __shared__ half_t sm[];
    float* red  = reinterpret_cast<float*>(sm + 2 * LN_STAGE_HALFS);   // [64][8] sum, [64][8] sq
    float* stat = red + 2 * 64 * 8;                                     // [64][2]

    const int tid  = threadIdx.x;
    const int brow = blockIdx.x * 64;

    const int lane = tid & 31;
    const int wid  = tid >> 5;
    const int wn   = wid * 32;
    const int gr   = lane >> 2;
    const int gc   = lane & 3;

    const uint32_t smemU = (uint32_t)__cvta_generic_to_shared(sm);
    const uint32_t aOff = (((lane & 7) + ((lane >> 3) & 1) * 8) * HS
                           + ((lane >> 4) & 1) * 8) * 2;
    const uint32_t bOff = ((wn + (lane & 7) + ((lane >> 4) & 1) * 8) * HS
                           + ((lane >> 3) & 1) * 8) * 2;

    float acc[4][4][4];
#pragma unroll
    for (int i = 0; i < 4; i++)
#pragma unroll
        for (int j = 0; j < 4; j++)
#pragma unroll
            for (int t = 0; t < 4; t++) acc[i][j][t] = 0.f;

    const int nch = K >> 6;

    auto issue = [&](int chunk, int stg) {
        const int k0 = chunk << 6;
        half_t* As = sm + stg * LN_STAGE_HALFS;
        half_t* Bs = As + LN_A_HALFS;
#pragma unroll
        for (int i = 0; i < 2; i++) {
            int t = tid + i * 256;
            int r = t >> 3, q = (t & 7) << 3;
            cp_async16(As + r * HS + q, A + (size_t)(brow + r) * K + k0 + q);
        }
#pragma unroll
        for (int i = 0; i < 8; i++) {
            int t = tid + i * 256;
            int r = t >> 3, q = (t & 7) << 3;
            cp_async16(Bs + r * HS + q, B + (size_t)r * K + k0 + q);
        }
        cp_commit();
    };

    issue(0, 0);

    for (int c = 0; c < nch; c++) {
        const int cur = c & 1;
        if (c + 1 < nch) { issue(c + 1, cur ^ 1); cp_wait<1>(); }
        else cp_wait<0>();
        __syncthreads();

        const uint32_t aBase = smemU + cur * (LN_STAGE_HALFS * 2) + aOff;
        const uint32_t bBase = smemU + cur * (LN_STAGE_HALFS * 2) + LN_A_HALFS * 2 + bOff;
#pragma unroll
        for (int kk = 0; kk < 4; kk++) {
            uint32_t af[4][4], bf[4][2];
#pragma unroll
            for (int mt = 0; mt < 4; mt++)
                ldsm4(af[mt][0], af[mt][1], af[mt][2], af[mt][3],
                      aBase + mt * (16 * HS * 2) + kk * 32);
#pragma unroll
            for (int ntp = 0; ntp < 2; ntp++)
                ldsm4(bf[2 * ntp][0], bf[2 * ntp][1], bf[2 * ntp + 1][0], bf[2 * ntp + 1][1],
                      bBase + ntp * (16 * HS * 2) + kk * 32);
#pragma unroll
            for (int mt = 0; mt < 4; mt++)
#pragma unroll
                for (int nt = 0; nt < 4; nt++)
                    mma_fp16(acc[mt][nt], af[mt], bf[nt]);
        }
        __syncthreads();
    }

    // s = acc + bias + Res ; accumulate per-row partials
#pragma unroll
    for (int mt = 0; mt < 4; mt++) {
        int r0 = mt * 16 + gr, r1 = r0 + 8;
        float s0 = 0.f, q0 = 0.f, s1 = 0.f, q1 = 0.f;
#pragma unroll
        for (int nt = 0; nt < 4; nt++) {
            int col = wn + nt * 8 + gc * 2;
            float2 bi = *reinterpret_cast<const float2*>(&bias[col]);
            float2 e0 = *reinterpret_cast<const float2*>(&Res[(size_t)(brow + r0) * 256 + col]);
            float2 e1 = *reinterpret_cast<const float2*>(&Res[(size_t)(brow + r1) * 256 + col]);
            float v0 = acc[mt][nt][0] + bi.x + e0.x;
            float v1 = acc[mt][nt][1] + bi.y + e0.y;
            float v2 = acc[mt][nt][2] + bi.x + e1.x;
            float v3 = acc[mt][nt][3] + bi.y + e1.y;
            acc[mt][nt][0] = v0; acc[mt][nt][1] = v1;
            acc[mt][nt][2] = v2; acc[mt][nt][3] = v3;
            s0 += v0 + v1; q0 += v0 * v0 + v1 * v1;
            s1 += v2 + v3; q1 += v2 * v2 + v3 * v3;
        }
        // reduce over the 4 gc lanes (lane ^1, ^2)
#pragma unroll
        for (int o = 1; o <= 2; o <<= 1) {
            s0 += __shfl_xor_sync(0xffffffffu, s0, o);
            q0 += __shfl_xor_sync(0xffffffffu, q0, o);
            s1 += __shfl_xor_sync(0xffffffffu, s1, o);
            q1 += __shfl_xor_sync(0xffffffffu, q1, o);
        }
        if (gc == 0) {
            red[r0 * 8 + wid] = s0;  red[512 + r0 * 8 + wid] = q0;
            red[r1 * 8 + wid] = s1;  red[512 + r1 * 8 + wid] = q1;
        }
    }
    __syncthreads();
    if (tid < 64) {
        float s = 0.f, q = 0.f;
#pragma unroll
        for (int w = 0; w < 8; w++) { s += red[tid * 8 + w]; q += red[512 + tid * 8 + w]; }
        float m = s * (1.f / 256.f);
        float var = q * (1.f / 256.f) - m * m;
        stat[tid * 2 + 0] = m;
        stat[tid * 2 + 1] = rsqrtf(var + 1e-5f);
    }
    __syncthreads();

#pragma unroll
    for (int mt = 0; mt < 4; mt++) {
        int r0 = mt * 16 + gr, r1 = r0 + 8;
        float m0 = stat[r0 * 2], iv0 = stat[r0 * 2 + 1];
        float m1 = stat[r1 * 2], iv1 = stat[r1 * 2 + 1];
#pragma unroll
        for (int nt = 0; nt < 4; nt++) {
            int col = wn + nt * 8 + gc * 2;
            float2 gm = *reinterpret_cast<const float2*>(&gam[col]);
            float2 bt = *reinterpret_cast<const float2*>(&bet[col]);
            float o0 = (acc[mt][nt][0] - m0) * iv0 * gm.x + bt.x;
            float o1 = (acc[mt][nt][1] - m0) * iv0 * gm.y + bt.y;
            float o2 = (acc[mt][nt][2] - m1) * iv1 * gm.x + bt.x;
            float o3 = (acc[mt][nt][3] - m1) * iv1 * gm.y + bt.y;
            *reinterpret_cast<float2*>(&Of[(size_t)(brow + r0) * 256 + col]) = make_float2(o0, o1);
            *reinterpret_cast<float2*>(&Of[(size_t)(brow + r1) * 256 + col]) = make_float2(o2, o3);
            if (WRITE_H) {
                *reinterpret_cast<__half2*>(&Oh[(size_t)(brow + r0) * 256 + col]) = __floats2half2_rn(o0, o1);
                *reinterpret_cast<__half2*>(&Oh[(size_t)(brow + r1) * 256 + col]) = __floats2half2_rn(o2, o3);
            }
        }
    }
}

// ---------------- merged prep: all weight transposes + bias concat ----------------
__global__ void prep_k(const float* __restrict__ w_val, const float* __restrict__ w_off,
                       const float* __restrict__ w_attn, const float* __restrict__ w_out,
                       const float* __restrict__ w_ff1, const float* __restrict__ w_ff2,
                       const float* __restrict__ b_off, const float* __restrict__ b_attn,
                       half_t* __restrict__ WvT, half_t* __restrict__ WqaT,
                       half_t* __restrict__ WuT, half_t* __restrict__ W1T,
                       half_t* __restrict__ W2T, float* __restrict__ bqa)
{
    int idx = blockIdx.x * blockDim.x + threadIdx.x;
    auto tr = [](const float* w, half_t* o, int i, int K, int N) {
        int n = i / K, k = i % K;
        o[i] = __float2half_rn(w[(size_t)k * N + n]);
    };
    if (idx < 65536)                { tr(w_val,  WvT,              idx, 256,  256);  return; }
    if ((idx -= 65536) < 65536)     { tr(w_off,  WqaT,             idx, 256,  256);  return; }
    if ((idx -= 65536) < 32768)     { tr(w_attn, WqaT + 256 * CD,  idx, 256,  128);  return; }
    if ((idx -= 32768) < 65536)     { tr(w_out,  WuT,              idx, 256,  256);  return; }
    if ((idx -= 65536) < 262144)    { tr(w_ff1,  W1T,              idx, 256,  1024); return; }
    if ((idx -= 262144) < 262144)   { tr(w_ff2,  W2T,              idx, 1024, 256);  return; }
    idx -= 262144;
    if (idx < 256)      bqa[idx] = b_off[idx];
    else if (idx < 384) bqa[idx] = b_attn[idx - 256];
}

// ---------------- addvec: srcH = h(src); QH = h(src+pos) ----------------
__global__ void addvec_k(const float* __restrict__ a, const float* __restrict__ b,
                         half_t* __restrict__ sh, half_t* __restrict__ qh)
{
    int i = blockIdx.x * blockDim.x + threadIdx.x;
    float4 x = reinterpret_cast<const float4*>(a)[i];
    float4 y = reinterpret_cast<const float4*>(b)[i];
    __half2 s0 = __floats2half2_rn(x.x, x.y);
    __half2 s1 = __floats2half2_rn(x.z, x.w);
    __half2 q0 = __floats2half2_rn(x.x + y.x, x.y + y.y);
    __half2 q1 = __floats2half2_rn(x.z + y.z, x.w + y.w);
    reinterpret_cast<__half2*>(sh)[i * 2 + 0] = s0;
    reinterpret_cast<__half2*>(sh)[i * 2 + 1] = s1;
    reinterpret_cast<__half2*>(qh)[i * 2 + 0] = q0;
    reinterpret_cast<__half2*>(qh)[i * 2 + 1] = q1;
}

// ---------------- deformable sampling + fused softmax (V fp16) ----------------
__global__ void deform_k(const half_t* __restrict__ V, const float* __restrict__ OA,
                         const float* __restrict__ REF, half_t* __restrict__ OUT)
{
    const int row = blockIdx.x;
    const int h = threadIdx.x >> 5;
    const int d = threadIdx.x & 31;
    const int n = row / LQN;

    const float* lgp = OA + (size_t)row * 384 + 256 + h * 16;
    float lg = (d < 16) ? lgp[d] : -1e30f;
    float mx = lg;
#pragma unroll
    for (int o = 8; o; o >>= 1) mx = fmaxf(mx, __shfl_xor_sync(0xffffffffu, mx, o));
    float ev = (d < 16) ? expf(lg - mx) : 0.f;
    float sum = ev;
#pragma unroll
    for (int o = 8; o; o >>= 1) sum += __shfl_xor_sync(0xffffffffu, sum, o);
    float prob = ev / sum;

    const float* off = OA + (size_t)row * 384 + h * 32;
    const float* ref = REF + (size_t)row * 8;
    const half_t* Vb = V + (size_t)n * LQN * 256 + h * 32 + d;

    const int   Wt[4]   = {64, 32, 16, 8};
    const int   St[4]   = {0, 4096, 5120, 5376};
    const float invW[4] = {1.f/64.f, 1.f/32.f, 1.f/16.f, 1.f/8.f};

    float acc = 0.f;
#pragma unroll
    for (int l = 0; l < 4; l++) {
        const int W = Wt[l], H = Wt[l];
        const half_t* Vl = Vb + (size_t)St[l] * 256;
        const float rx = ref[l * 2 + 0], ry = ref[l * 2 + 1];
#pragma unroll
        for (int p = 0; p < 4; p++) {
            float ox = off[l * 8 + p * 2 + 0];
            float oy = off[l * 8 + p * 2 + 1];
            float lx = rx + ox * invW[l];
            float ly = ry + oy * invW[l];
            float gx = 2.f * lx - 1.f, gy = 2.f * ly - 1.f;
            float x = (gx + 1.f) * (W * 0.5f) - 0.5f;
            float y = (gy + 1.f) * (H * 0.5f) - 0.5f;
            float x0f = floorf(x), y0f = floorf(y);
            float wx = x - x0f, wy = y - y0f;
            int x0 = (int)x0f, y0 = (int)y0f;
            float a = __shfl_sync(0xffffffffu, prob, l * 4 + p);
            bool xv0 = (x0 >= 0)  && (x0 < W);
            bool xv1 = (x0 >= -1) && (x0 < W - 1);
            bool yv0 = (y0 >= 0)  && (y0 < H);
            bool yv1 = (y0 >= -1) && (y0 < H - 1);
            float w00 = (1.f - wx) * (1.f - wy) * a;
            float w10 = wx * (1.f - wy) * a;
            float w01 = (1.f - wx) * wy * a;
            float w11 = wx * wy * a;
            if (xv0 && yv0) acc += w00 * __half2float(Vl[(y0 * W + x0) * 256]);
            if (xv1 && yv0) acc += w10 * __half2float(Vl[(y0 * W + x0 + 1) * 256]);
            if (xv0 && yv1) acc += w01 * __half2float(Vl[((y0 + 1) * W + x0) * 256]);
            if (xv1 && yv1) acc += w11 * __half2float(Vl[((y0 + 1) * W + x0 + 1) * 256]);
        }
    }
    OUT[(size_t)row * 256 + h * 32 + d] = __float2half_rn(acc);
}

// ---------------- launch ----------------
extern "C" void kernel_launch(void* const* d_in, const int* in_sizes, int n_in,
                              void* d_out, int out_size)
{
    const float* src    = (const float*)d_in[0];
    const float* pos    = (const float*)d_in[1];
    const float* ref    = (const float*)d_in[2];
    const float* w_off  = (const float*)d_in[3];
    const float* b_off  = (const float*)d_in[4];
    const float* w_attn = (const float*)d_in[5];
    const float* b_attn = (const float*)d_in[6];
    const float* w_val  = (const float*)d_in[7];
    const float* b_val  = (const float*)d_in[8];
    const float* w_out  = (const float*)d_in[9];
    const float* b_out  = (const float*)d_in[10];
    const float* g1     = (const float*)d_in[11];
    const float* be1    = (const float*)d_in[12];
    const float* w_ff1  = (const float*)d_in[13];
    const float* b_ff1  = (const float*)d_in[14];
    const float* w_ff2  = (const float*)d_in[15];
    const float* b_ff2  = (const float*)d_in[16];
    const float* g2     = (const float*)d_in[17];
    const float* be2    = (const float*)d_in[18];
    const unsigned char* mask = (const unsigned char*)d_in[19];

    half_t *srcH, *QH, *VH, *ATTH, *XH, *HH, *WvT, *WqaT, *WuT, *W1T, *W2T;
    float *pOA, *pX, *pbqa;
    cudaGetSymbolAddress((void**)&srcH, g_srcH);
    cudaGetSymbolAddress((void**)&QH,   g_QH);
    cudaGetSymbolAddress((void**)&VH,   g_VH);
    cudaGetSymbolAddress((void**)&ATTH, g_ATTH);
    cudaGetSymbolAddress((void**)&XH,   g_XH);
    cudaGetSymbolAddress((void**)&HH,   g_HH);
    cudaGetSymbolAddress((void**)&WvT,  g_WvT);
    cudaGetSymbolAddress((void**)&WqaT, g_WqaT);
    cudaGetSymbolAddress((void**)&WuT,  g_WuT);
    cudaGetSymbolAddress((void**)&W1T,  g_W1T);
    cudaGetSymbolAddress((void**)&W2T,  g_W2T);
    cudaGetSymbolAddress((void**)&pOA,  g_OA);
    cudaGetSymbolAddress((void**)&pX,   g_X);
    cudaGetSymbolAddress((void**)&pbqa, g_bqa);

    cudaFuncSetAttribute(hgemm_k<false, true,  true >, cudaFuncAttributeMaxDynamicSharedMemorySize, SMEM_BYTES);
    cudaFuncSetAttribute(hgemm_k<false, false, false>, cudaFuncAttributeMaxDynamicSharedMemorySize, SMEM_BYTES);
    cudaFuncSetAttribute(hgemm_k<true,  false, true >, cudaFuncAttributeMaxDynamicSharedMemorySize, SMEM_BYTES);
    cudaFuncSetAttribute(hgemm_ln_k<true >, cudaFuncAttributeMaxDynamicSharedMemorySize, LN_SMEM_BYTES);
    cudaFuncSetAttribute(hgemm_ln_k<false>, cudaFuncAttributeMaxDynamicSharedMemorySize, LN_SMEM_BYTES);

    addvec_k<<<RR * CD / 4 / 256, 256>>>(src, pos, srcH, QH);
    prep_k<<<(754048 + 255) / 256, 256>>>(w_val, w_off, w_attn, w_out, w_ff1, w_ff2,
                                          b_off, b_attn, WvT, WqaT, WuT, W1T, W2T, pbqa);

    // value = mask0(src @ w_val + b_val) -> fp16
    hgemm_k<false, true,  true ><<<dim3(340, 2), 256, SMEM_BYTES>>>(
        srcH, WvT, b_val, mask, nullptr, VH, 256, 256);
    // [off | attn logits] = Q @ [w_off | w_attn] + bqa
    hgemm_k<false, false, false><<<dim3(340, 3), 256, SMEM_BYTES>>>(
        QH, WqaT, pbqa, nullptr, pOA, nullptr, 256, 384);
    deform_k<<<RR, 256>>>(VH, pOA, ref, ATTH);
    // X = LN1(src + ATT @ w_out + b_out)  -> pX fp32 + XH fp16
    hgemm_ln_k<true ><<<680, 256, LN_SMEM_BYTES>>>(
        ATTH, WuT, b_out, src, g1, be1, pX, XH, 256);
    // H = relu(X @ w_ff1 + b_ff1) -> fp16
    hgemm_k<true,  false, true ><<<dim3(340, 8), 256, SMEM_BYTES>>>(
        XH, W1T, b_ff1, nullptr, nullptr, HH, 256, 1024);
    // out = LN2(X + H @ w_ff2 + b_ff2)
    hgemm_ln_k<false><<<680, 256, LN_SMEM_BYTES>>>(
        HH, W2T, b_ff2, pX, g2, be2, (float*)d_out, nullptr, 1024);
}

// round 10
// speedup vs baseline: 4.5971x; 1.3261x over previous
#include <cuda_runtime.h>
#include <cuda_fp16.h>
#include <cstdint>

#define NB 8
#define LQN 5440
#define CD 256
#define RR 43520          // NB*LQN
#define DFFN 1024

typedef __half half_t;

// ---------------- scratch (static device arrays; no allocation) ----------------
__device__ half_t g_srcH[RR * CD];
__device__ half_t g_QH  [RR * CD];
__device__ half_t g_VH  [RR * CD];
__device__ half_t g_ATTH[RR * CD];
__device__ half_t g_XH  [RR * CD];
__device__ half_t g_HH  [RR * DFFN];
// transposed fp16 weights [N][K]
__device__ half_t g_WvT [CD * CD];
__device__ half_t g_WqaT[384 * CD];
__device__ half_t g_WuT [CD * CD];
__device__ half_t g_W1T [DFFN * CD];
__device__ half_t g_W2T [CD * DFFN];
__device__ float  g_bqa [384];
// fp32 intermediates
__device__ float g_OA [RR * 384];            // off (256) ++ logits (128)
__device__ float g_X  [RR * CD];             // LN1 output fp32 (residual for LN2)

// ---------------- PTX helpers ----------------
__device__ __forceinline__ void mma_fp16(float d[4], const uint32_t a[4],
                                         const uint32_t b[2]) {
    asm volatile(
        "mma.sync.aligned.m16n8k16.row.col.f32.f16.f16.f32 "
        "{%0,%1,%2,%3}, {%4,%5,%6,%7}, {%8,%9}, {%0,%1,%2,%3};\n"
        : "+f"(d[0]), "+f"(d[1]), "+f"(d[2]), "+f"(d[3])
        : "r"(a[0]), "r"(a[1]), "r"(a[2]), "r"(a[3]),
          "r"(b[0]), "r"(b[1]));
}
__device__ __forceinline__ void ldsm4(uint32_t& r0, uint32_t& r1, uint32_t& r2,
                                      uint32_t& r3, uint32_t addr) {
    asm volatile("ldmatrix.sync.aligned.m8n8.x4.shared.b16 {%0,%1,%2,%3}, [%4];"
                 : "=r"(r0), "=r"(r1), "=r"(r2), "=r"(r3) : "r"(addr));
}
__device__ __forceinline__ void cp_async16(void* s, const void* g) {
    uint32_t sa = (uint32_t)__cvta_generic_to_shared(s);
    asm volatile("cp.async.cg.shared.global [%0], [%1], 16;\n" :: "r"(sa), "l"(g));
}
__device__ __forceinline__ void cp_commit() { asm volatile("cp.async.commit_group;\n"); }
template<int N> __device__ __forceinline__ void cp_wait() {
    asm volatile("cp.async.wait_group %0;\n" :: "n"(N));
}

#define HS 72                           // half stride (64 + 8 pad)

// ================= generic FP16 GEMM (BM=BN=128, 3-stage) =================
#define TILE_HALFS (128 * HS)
#define STAGE_HALFS (2 * TILE_HALFS)
#define TILE_BYTES (TILE_HALFS * 2)
#define STAGE_BYTES (STAGE_HALFS * 2)
#define SMEM_BYTES (3 * STAGE_BYTES)    // 110,592 B

template<bool RELU, bool MASK, bool HALF_OUT>
__global__ __launch_bounds__(256, 2)
void hgemm_k(const half_t* __restrict__ A, const half_t* __restrict__ B,
             const float* __restrict__ bias, const unsigned char* __restrict__ mask,
             float* __restrict__ Cf, half_t* __restrict__ Ch, int K, int Nout)
{
    extern __shared__ half_t sm[];

    const int tid  = threadIdx.x;
    const int brow = blockIdx.x * 128;
    const int bcol = blockIdx.y * 128;

    const int lane = tid & 31;
    const int wid  = tid >> 5;
    const int wm   = (wid >> 2) * 64;
    const int wn   = (wid & 3) * 32;
    const int gr   = lane >> 2;
    const int gc   = lane & 3;

    const uint32_t smemU = (uint32_t)__cvta_generic_to_shared(sm);
    const uint32_t aOff = ((wm + (lane & 7) + ((lane >> 3) & 1) * 8) * HS
                           + ((lane >> 4) & 1) * 8) * 2;
    const uint32_t bOff = ((wn + (lane & 7) + ((lane >> 4) & 1) * 8) * HS
                           + ((lane >> 3) & 1) * 8) * 2;

    float acc[4][4][4];
#pragma unroll
    for (int i = 0; i < 4; i++)
#pragma unroll
        for (int j = 0; j < 4; j++)
#pragma unroll
            for (int t = 0; t < 4; t++) acc[i][j][t] = 0.f;

    const int nch = K >> 6;

    auto issue = [&](int chunk, int stg) {
        const int k0 = chunk << 6;
        half_t* As = sm + stg * STAGE_HALFS;
        half_t* Bs = As + TILE_HALFS;
#pragma unroll
        for (int i = 0; i < 4; i++) {
            int t = tid + i * 256;
            int r = t >> 3, q = (t & 7) << 3;
            cp_async16(As + r * HS + q, A + (size_t)(brow + r) * K + k0 + q);
        }
#pragma unroll
        for (int i = 0; i < 4; i++) {
            int t = tid + i * 256;
            int r = t >> 3, q = (t & 7) << 3;
            cp_async16(Bs + r * HS + q, B + (size_t)(bcol + r) * K + k0 + q);
        }
        cp_commit();
    };

    issue(0, 0);
    if (nch > 1) issue(1, 1);
    else cp_commit();

    for (int c = 0; c < nch; c++) {
        const int cur = c % 3;
        if (c + 2 < nch) issue(c + 2, (c + 2) % 3);
        else cp_commit();
        cp_wait<2>();
        __syncthreads();

        const uint32_t aBase = smemU + cur * STAGE_BYTES + aOff;
        const uint32_t bBase = smemU + cur * STAGE_BYTES + TILE_BYTES + bOff;
#pragma unroll
        for (int kk = 0; kk < 4; kk++) {
            uint32_t af[4][4], bf[4][2];
#pragma unroll
            for (int mt = 0; mt < 4; mt++)
                ldsm4(af[mt][0], af[mt][1], af[mt][2], af[mt][3],
                      aBase + mt * (16 * HS * 2) + kk * 32);
#pragma unroll
            for (int ntp = 0; ntp < 2; ntp++)
                ldsm4(bf[2 * ntp][0], bf[2 * ntp][1], bf[2 * ntp + 1][0], bf[2 * ntp + 1][1],
                      bBase + ntp * (16 * HS * 2) + kk * 32);
#pragma unroll
            for (int mt = 0; mt < 4; mt++)
#pragma unroll
                for (int nt = 0; nt < 4; nt++)
                    mma_fp16(acc[mt][nt], af[mt], bf[nt]);
        }
        __syncthreads();
    }

#pragma unroll
    for (int mt = 0; mt < 4; mt++) {
        int r0 = brow + wm + mt * 16 + gr;
        int r1 = r0 + 8;
        float ms0 = 1.f, ms1 = 1.f;
        if (MASK) { ms0 = mask[r0] ? 0.f : 1.f; ms1 = mask[r1] ? 0.f : 1.f; }
#pragma unroll
        for (int nt = 0; nt < 4; nt++) {
            int col = bcol + wn + nt * 8 + gc * 2;
            float2 bi = *reinterpret_cast<const float2*>(&bias[col]);
            float v0 = acc[mt][nt][0] + bi.x;
            float v1 = acc[mt][nt][1] + bi.y;
            float v2 = acc[mt][nt][2] + bi.x;
            float v3 = acc[mt][nt][3] + bi.y;
            if (MASK) { v0 *= ms0; v1 *= ms0; v2 *= ms1; v3 *= ms1; }
            if (RELU) {
                v0 = fmaxf(v0, 0.f); v1 = fmaxf(v1, 0.f);
                v2 = fmaxf(v2, 0.f); v3 = fmaxf(v3, 0.f);
            }
            if (HALF_OUT) {
                *reinterpret_cast<__half2*>(&Ch[(size_t)r0 * Nout + col]) = __floats2half2_rn(v0, v1);
                *reinterpret_cast<__half2*>(&Ch[(size_t)r1 * Nout + col]) = __floats2half2_rn(v2, v3);
            } else {
                *reinterpret_cast<float2*>(&Cf[(size_t)r0 * Nout + col]) = make_float2(v0, v1);
                *reinterpret_cast<float2*>(&Cf[(size_t)r1 * Nout + col]) = make_float2(v2, v3);
            }
        }
    }
}

// ============ fused GEMM + residual + LayerNorm (BM=64, BN=256, 2-stage) ============
#define LN_A_HALFS (64 * HS)
#define LN_B_HALFS (256 * HS)
#define LN_STAGE_HALFS (LN_A_HALFS + LN_B_HALFS)
#define LN_RED_FLOATS (2 * 64 * 8 + 64 * 2)
#define LN_SMEM_BYTES (2 * LN_STAGE_HALFS * 2 + LN_RED_FLOATS * 4)

template<bool WRITE_H>
__global__ __launch_bounds__(256, 2)
void hgemm_ln_k(const half_t* __restrict__ A, const half_t* __restrict__ B,
                const float* __restrict__ bias, const float* __restrict__ Res,
                const float* __restrict__ gam, const float* __restrict__ bet,
                float* __restrict__ Of, half_t* __restrict__ Oh, int K)
{
    extern __shared__ half_t sm[];
    float* red  = reinterpret_cast<float*>(sm + 2 * LN_STAGE_HALFS);
    float* stat = red + 2 * 64 * 8;

    const int tid  = threadIdx.x;
    const int brow = blockIdx.x * 64;

    const int lane = tid & 31;
    const int wid  = tid >> 5;
    const int wn   = wid * 32;
    const int gr   = lane >> 2;
    const int gc   = lane & 3;

    const uint32_t smemU = (uint32_t)__cvta_generic_to_shared(sm);
    const uint32_t aOff = (((lane & 7) + ((lane >> 3) & 1) * 8) * HS
                           + ((lane >> 4) & 1) * 8) * 2;
    const uint32_t bOff = ((wn + (lane & 7) + ((lane >> 4) & 1) * 8) * HS
                           + ((lane >> 3) & 1) * 8) * 2;

    float acc[4][4][4];
#pragma unroll
    for (int i = 0; i < 4; i++)
#pragma unroll
        for (int j = 0; j < 4; j++)
#pragma unroll
            for (int t = 0; t < 4; t++) acc[i][j][t] = 0.f;

    const int nch = K >> 6;

    auto issue = [&](int chunk, int stg) {
        const int k0 = chunk << 6;
        half_t* As = sm + stg * LN_STAGE_HALFS;
        half_t* Bs = As + LN_A_HALFS;
#pragma unroll
        for (int i = 0; i < 2; i++) {
            int t = tid + i * 256;
            int r = t >> 3, q = (t & 7) << 3;
            cp_async16(As + r * HS + q, A + (size_t)(brow + r) * K + k0 + q);
        }
#pragma unroll
        for (int i = 0; i < 8; i++) {
            int t = tid + i * 256;
            int r = t >> 3, q = (t & 7) << 3;
            cp_async16(Bs + r * HS + q, B + (size_t)r * K + k0 + q);
        }
        cp_commit();
    };

    issue(0, 0);

    for (int c = 0; c < nch; c++) {
        const int cur = c & 1;
        if (c + 1 < nch) { issue(c + 1, cur ^ 1); cp_wait<1>(); }
        else cp_wait<0>();
        __syncthreads();

        const uint32_t aBase = smemU + cur * (LN_STAGE_HALFS * 2) + aOff;
        const uint32_t bBase = smemU + cur * (LN_STAGE_HALFS * 2) + LN_A_HALFS * 2 + bOff;
#pragma unroll
        for (int kk = 0; kk < 4; kk++) {
            uint32_t af[4][4], bf[4][2];
#pragma unroll
            for (int mt = 0; mt < 4; mt++)
                ldsm4(af[mt][0], af[mt][1], af[mt][2], af[mt][3],
                      aBase + mt * (16 * HS * 2) + kk * 32);
#pragma unroll
            for (int ntp = 0; ntp < 2; ntp++)
                ldsm4(bf[2 * ntp][0], bf[2 * ntp][1], bf[2 * ntp + 1][0], bf[2 * ntp + 1][1],
                      bBase + ntp * (16 * HS * 2) + kk * 32);
#pragma unroll
            for (int mt = 0; mt < 4; mt++)
#pragma unroll
                for (int nt = 0; nt < 4; nt++)
                    mma_fp16(acc[mt][nt], af[mt], bf[nt]);
        }
        __syncthreads();
    }

#pragma unroll
    for (int mt = 0; mt < 4; mt++) {
        int r0 = mt * 16 + gr, r1 = r0 + 8;
        float s0 = 0.f, q0 = 0.f, s1 = 0.f, q1 = 0.f;
#pragma unroll
        for (int nt = 0; nt < 4; nt++) {
            int col = wn + nt * 8 + gc * 2;
            float2 bi = *reinterpret_cast<const float2*>(&bias[col]);
            float2 e0 = *reinterpret_cast<const float2*>(&Res[(size_t)(brow + r0) * 256 + col]);
            float2 e1 = *reinterpret_cast<const float2*>(&Res[(size_t)(brow + r1) * 256 + col]);
            float v0 = acc[mt][nt][0] + bi.x + e0.x;
            float v1 = acc[mt][nt][1] + bi.y + e0.y;
            float v2 = acc[mt][nt][2] + bi.x + e1.x;
            float v3 = acc[mt][nt][3] + bi.y + e1.y;
            acc[mt][nt][0] = v0; acc[mt][nt][1] = v1;
            acc[mt][nt][2] = v2; acc[mt][nt][3] = v3;
            s0 += v0 + v1; q0 += v0 * v0 + v1 * v1;
            s1 += v2 + v3; q1 += v2 * v2 + v3 * v3;
        }
#pragma unroll
        for (int o = 1; o <= 2; o <<= 1) {
            s0 += __shfl_xor_sync(0xffffffffu, s0, o);
            q0 += __shfl_xor_sync(0xffffffffu, q0, o);
            s1 += __shfl_xor_sync(0xffffffffu, s1, o);
            q1 += __shfl_xor_sync(0xffffffffu, q1, o);
        }
        if (gc == 0) {
            red[r0 * 8 + wid] = s0;  red[512 + r0 * 8 + wid] = q0;
            red[r1 * 8 + wid] = s1;  red[512 + r1 * 8 + wid] = q1;
        }
    }
    __syncthreads();
    if (tid < 64) {
        float s = 0.f, q = 0.f;
#pragma unroll
        for (int w = 0; w < 8; w++) { s += red[tid * 8 + w]; q += red[512 + tid * 8 + w]; }
        float m = s * (1.f / 256.f);
        float var = q * (1.f / 256.f) - m * m;
        stat[tid * 2 + 0] = m;
        stat[tid * 2 + 1] = rsqrtf(var + 1e-5f);
    }
    __syncthreads();

#pragma unroll
    for (int mt = 0; mt < 4; mt++) {
        int r0 = mt * 16 + gr, r1 = r0 + 8;
        float m0 = stat[r0 * 2], iv0 = stat[r0 * 2 + 1];
        float m1 = stat[r1 * 2], iv1 = stat[r1 * 2 + 1];
#pragma unroll
        for (int nt = 0; nt < 4; nt++) {
            int col = wn + nt * 8 + gc * 2;
            float2 gm = *reinterpret_cast<const float2*>(&gam[col]);
            float2 bt = *reinterpret_cast<const float2*>(&bet[col]);
            float o0 = (acc[mt][nt][0] - m0) * iv0 * gm.x + bt.x;
            float o1 = (acc[mt][nt][1] - m0) * iv0 * gm.y + bt.y;
            float o2 = (acc[mt][nt][2] - m1) * iv1 * gm.x + bt.x;
            float o3 = (acc[mt][nt][3] - m1) * iv1 * gm.y + bt.y;
            *reinterpret_cast<float2*>(&Of[(size_t)(brow + r0) * 256 + col]) = make_float2(o0, o1);
            *reinterpret_cast<float2*>(&Of[(size_t)(brow + r1) * 256 + col]) = make_float2(o2, o3);
            if (WRITE_H) {
                *reinterpret_cast<__half2*>(&Oh[(size_t)(brow + r0) * 256 + col]) = __floats2half2_rn(o0, o1);
                *reinterpret_cast<__half2*>(&Oh[(size_t)(brow + r1) * 256 + col]) = __floats2half2_rn(o2, o3);
            }
        }
    }
}

// ---------------- merged prep: all weight transposes + bias concat ----------------
__global__ void prep_k(const float* __restrict__ w_val, const float* __restrict__ w_off,
                       const float* __restrict__ w_attn, const float* __restrict__ w_out,
                       const float* __restrict__ w_ff1, const float* __restrict__ w_ff2,
                       const float* __restrict__ b_off, const float* __restrict__ b_attn,
                       half_t* __restrict__ WvT, half_t* __restrict__ WqaT,
                       half_t* __restrict__ WuT, half_t* __restrict__ W1T,
                       half_t* __restrict__ W2T, float* __restrict__ bqa)
{
    int idx = blockIdx.x * blockDim.x + threadIdx.x;
    auto tr = [](const float* w, half_t* o, int i, int K, int N) {
        int n = i / K, k = i % K;
        o[i] = __float2half_rn(w[(size_t)k * N + n]);
    };
    if (idx < 65536)                { tr(w_val,  WvT,              idx, 256,  256);  return; }
    if ((idx -= 65536) < 65536)     { tr(w_off,  WqaT,             idx, 256,  256);  return; }
    if ((idx -= 65536) < 32768)     { tr(w_attn, WqaT + 256 * CD,  idx, 256,  128);  return; }
    if ((idx -= 32768) < 65536)     { tr(w_out,  WuT,              idx, 256,  256);  return; }
    if ((idx -= 65536) < 262144)    { tr(w_ff1,  W1T,              idx, 256,  1024); return; }
    if ((idx -= 262144) < 262144)   { tr(w_ff2,  W2T,              idx, 1024, 256);  return; }
    idx -= 262144;
    if (idx < 256)      bqa[idx] = b_off[idx];
    else if (idx < 384) bqa[idx] = b_attn[idx - 256];
}

// ---------------- addvec: srcH = h(src); QH = h(src+pos) ----------------
__global__ void addvec_k(const float* __restrict__ a, const float* __restrict__ b,
                         half_t* __restrict__ sh, half_t* __restrict__ qh)
{
    int i = blockIdx.x * blockDim.x + threadIdx.x;
    float4 x = reinterpret_cast<const float4*>(a)[i];
    float4 y = reinterpret_cast<const float4*>(b)[i];
    __half2 s0 = __floats2half2_rn(x.x, x.y);
    __half2 s1 = __floats2half2_rn(x.z, x.w);
    __half2 q0 = __floats2half2_rn(x.x + y.x, x.y + y.y);
    __half2 q1 = __floats2half2_rn(x.z + y.z, x.w + y.w);
    reinterpret_cast<__half2*>(sh)[i * 2 + 0] = s0;
    reinterpret_cast<__half2*>(sh)[i * 2 + 1] = s1;
    reinterpret_cast<__half2*>(qh)[i * 2 + 0] = q0;
    reinterpret_cast<__half2*>(qh)[i * 2 + 1] = q1;
}

// ---------------- deformable sampling: 2 heads/warp, half2 channels ----------------
// block = 256 threads = 2 rows (4 warps per row, 2 heads per warp).
// lanes 0-15: head 2*(w&3); lanes 16-31: head 2*(w&3)+1; lane&15 = channel pair.
__global__ void deform_k(const half_t* __restrict__ V, const float* __restrict__ OA,
                         const float* __restrict__ REF, half_t* __restrict__ OUT)
{
    const int tid  = threadIdx.x;
    const int w    = tid >> 5;
    const int lane = tid & 31;
    const int row  = blockIdx.x * 2 + (w >> 2);
    const int h    = ((w & 3) << 1) + (lane >> 4);
    const int cp   = lane & 15;                 // channel-pair index
    const int n    = row / LQN;

    // softmax over this head's 16 logits (lane cp owns logit cp of head h)
    float lg = OA[(size_t)row * 384 + 256 + h * 16 + cp];
    float mx = lg;
#pragma unroll
    for (int o = 8; o; o >>= 1) mx = fmaxf(mx, __shfl_xor_sync(0xffffffffu, mx, o));
    float ev = expf(lg - mx);
    float sum = ev;
#pragma unroll
    for (int o = 8; o; o >>= 1) sum += __shfl_xor_sync(0xffffffffu, sum, o);
    float prob = ev / sum;

    const float*  off = OA + (size_t)row * 384 + h * 32;
    const float*  ref = REF + (size_t)row * 8;
    const half_t* Vb  = V + (size_t)n * LQN * 256 + h * 32 + 2 * cp;

    const int   Wt[4]   = {64, 32, 16, 8};
    const int   St[4]   = {0, 4096, 5120, 5376};
    const float invW[4] = {1.f/64.f, 1.f/32.f, 1.f/16.f, 1.f/8.f};

    float ax = 0.f, ay = 0.f;
#pragma unroll
    for (int l = 0; l < 4; l++) {
        const int W = Wt[l], H = Wt[l];
        const half_t* Vl = Vb + (size_t)St[l] * 256;
        const float rx = ref[l * 2 + 0], ry = ref[l * 2 + 1];
#pragma unroll
        for (int p = 0; p < 4; p++) {
            float ox = off[l * 8 + p * 2 + 0];
            float oy = off[l * 8 + p * 2 + 1];
            float lx = rx + ox * invW[l];
            float ly = ry + oy * invW[l];
            float gx = 2.f * lx - 1.f, gy = 2.f * ly - 1.f;
            float x = (gx + 1.f) * (W * 0.5f) - 0.5f;
            float y = (gy + 1.f) * (H * 0.5f) - 0.5f;
            float x0f = floorf(x), y0f = floorf(y);
            float wx = x - x0f, wy = y - y0f;
            int x0 = (int)x0f, y0 = (int)y0f;
            float a = __shfl_sync(0xffffffffu, prob, (lane & 16) | (l * 4 + p));
            bool xv0 = (x0 >= 0)  && (x0 < W);
            bool xv1 = (x0 >= -1) && (x0 < W - 1);
            bool yv0 = (y0 >= 0)  && (y0 < H);
            bool yv1 = (y0 >= -1) && (y0 < H - 1);
            float w00 = (1.f - wx) * (1.f - wy) * a;
            float w10 = wx * (1.f - wy) * a;
            float w01 = (1.f - wx) * wy * a;
            float w11 = wx * wy * a;
            if (xv0 && yv0) {
                float2 v = __half22float2(*reinterpret_cast<const __half2*>(Vl + (y0 * W + x0) * 256));
                ax += w00 * v.x; ay += w00 * v.y;
            }
            if (xv1 && yv0) {
                float2 v = __half22float2(*reinterpret_cast<const __half2*>(Vl + (y0 * W + x0 + 1) * 256));
                ax += w10 * v.x; ay += w10 * v.y;
            }
            if (xv0 && yv1) {
                float2 v = __half22float2(*reinterpret_cast<const __half2*>(Vl + ((y0 + 1) * W + x0) * 256));
                ax += w01 * v.x; ay += w01 * v.y;
            }
            if (xv1 && yv1) {
                float2 v = __half22float2(*reinterpret_cast<const __half2*>(Vl + ((y0 + 1) * W + x0 + 1) * 256));
                ax += w11 * v.x; ay += w11 * v.y;
            }
        }
    }
    *reinterpret_cast<__half2*>(&OUT[(size_t)row * 256 + h * 32 + 2 * cp]) =
        __floats2half2_rn(ax, ay);
}

// ---------------- launch ----------------
extern "C" void kernel_launch(void* const* d_in, const int* in_sizes, int n_in,
                              void* d_out, int out_size)
{
    const float* src    = (const float*)d_in[0];
    const float* pos    = (const float*)d_in[1];
    const float* ref    = (const float*)d_in[2];
    const float* w_off  = (const float*)d_in[3];
    const float* b_off  = (const float*)d_in[4];
    const float* w_attn = (const float*)d_in[5];
    const float* b_attn = (const float*)d_in[6];
    const float* w_val  = (const float*)d_in[7];
    const float* b_val  = (const float*)d_in[8];
    const float* w_out  = (const float*)d_in[9];
    const float* b_out  = (const float*)d_in[10];
    const float* g1     = (const float*)d_in[11];
    const float* be1    = (const float*)d_in[12];
    const float* w_ff1  = (const float*)d_in[13];
    const float* b_ff1  = (const float*)d_in[14];
    const float* w_ff2  = (const float*)d_in[15];
    const float* b_ff2  = (const float*)d_in[16];
    const float* g2     = (const float*)d_in[17];
    const float* be2    = (const float*)d_in[18];
    const unsigned char* mask = (const unsigned char*)d_in[19];

    half_t *srcH, *QH, *VH, *ATTH, *XH, *HH, *WvT, *WqaT, *WuT, *W1T, *W2T;
    float *pOA, *pX, *pbqa;
    cudaGetSymbolAddress((void**)&srcH, g_srcH);
    cudaGetSymbolAddress((void**)&QH,   g_QH);
    cudaGetSymbolAddress((void**)&VH,   g_VH);
    cudaGetSymbolAddress((void**)&ATTH, g_ATTH);
    cudaGetSymbolAddress((void**)&XH,   g_XH);
    cudaGetSymbolAddress((void**)&HH,   g_HH);
    cudaGetSymbolAddress((void**)&WvT,  g_WvT);
    cudaGetSymbolAddress((void**)&WqaT, g_WqaT);
    cudaGetSymbolAddress((void**)&WuT,  g_WuT);
    cudaGetSymbolAddress((void**)&W1T,  g_W1T);
    cudaGetSymbolAddress((void**)&W2T,  g_W2T);
    cudaGetSymbolAddress((void**)&pOA,  g_OA);
    cudaGetSymbolAddress((void**)&pX,   g_X);
    cudaGetSymbolAddress((void**)&pbqa, g_bqa);

    cudaFuncSetAttribute(hgemm_k<false, true,  true >, cudaFuncAttributeMaxDynamicSharedMemorySize, SMEM_BYTES);
    cudaFuncSetAttribute(hgemm_k<false, false, false>, cudaFuncAttributeMaxDynamicSharedMemorySize, SMEM_BYTES);
    cudaFuncSetAttribute(hgemm_k<true,  false, true >, cudaFuncAttributeMaxDynamicSharedMemorySize, SMEM_BYTES);
    cudaFuncSetAttribute(hgemm_ln_k<true >, cudaFuncAttributeMaxDynamicSharedMemorySize, LN_SMEM_BYTES);
    cudaFuncSetAttribute(hgemm_ln_k<false>, cudaFuncAttributeMaxDynamicSharedMemorySize, LN_SMEM_BYTES);

    addvec_k<<<RR * CD / 4 / 256, 256>>>(src, pos, srcH, QH);
    prep_k<<<(754048 + 255) / 256, 256>>>(w_val, w_off, w_attn, w_out, w_ff1, w_ff2,
                                          b_off, b_attn, WvT, WqaT, WuT, W1T, W2T, pbqa);

    // value = mask0(src @ w_val + b_val) -> fp16
    hgemm_k<false, true,  true ><<<dim3(340, 2), 256, SMEM_BYTES>>>(
        srcH, WvT, b_val, mask, nullptr, VH, 256, 256);
    // [off | attn logits] = Q @ [w_off | w_attn] + bqa
    hgemm_k<false, false, false><<<dim3(340, 3), 256, SMEM_BYTES>>>(
        QH, WqaT, pbqa, nullptr, pOA, nullptr, 256, 384);
    deform_k<<<RR / 2, 256>>>(VH, pOA, ref, ATTH);
    // X = LN1(src + ATT @ w_out + b_out)  -> pX fp32 + XH fp16
    hgemm_ln_k<true ><<<680, 256, LN_SMEM_BYTES>>>(
        ATTH, WuT, b_out, src, g1, be1, pX, XH, 256);
    // H = relu(X @ w_ff1 + b_ff1) -> fp16
    hgemm_k<true,  false, true ><<<dim3(340, 8), 256, SMEM_BYTES>>>(
        XH, W1T, b_ff1, nullptr, nullptr, HH, 256, 1024);
    // out = LN2(X + H @ w_ff2 + b_ff2)
    hgemm_ln_k<false><<<680, 256, LN_SMEM_BYTES>>>(
        HH, W2T, b_ff2, pX, g2, be2, (float*)d_out, nullptr, 1024);
}

// round 11
// speedup vs baseline: 5.4603x; 1.1878x over previous
#include <cuda_runtime.h>
#include <cuda_fp16.h>
#include <cstdint>

#define NB 8
#define LQN 5440
#define CD 256
#define RR 43520          // NB*LQN
#define DFFN 1024

typedef __half half_t;

// ---------------- scratch (static device arrays; no allocation) ----------------
__device__ half_t g_srcH[RR * CD];
__device__ half_t g_QH  [RR * CD];
__device__ half_t g_VH  [RR * CD];
__device__ half_t g_ATTH[RR * CD];
__device__ half_t g_XH  [RR * CD];
__device__ half_t g_HH  [RR * DFFN];
// transposed fp16 weights [N][K]
__device__ half_t g_WvT [CD * CD];
__device__ half_t g_WqaT[384 * CD];
__device__ half_t g_WuT [CD * CD];
__device__ half_t g_W1T [DFFN * CD];
__device__ half_t g_W2T [CD * DFFN];
__device__ float  g_bqa [384];
// fp32 intermediates
__device__ float g_OA [RR * 384];            // off (256) ++ logits (128)
__device__ float g_X  [RR * CD];             // LN1 output fp32 (residual for LN2)

// ---------------- PTX helpers ----------------
__device__ __forceinline__ void mma_fp16(float d[4], const uint32_t a[4],
                                         const uint32_t b[2]) {
    asm volatile(
        "mma.sync.aligned.m16n8k16.row.col.f32.f16.f16.f32 "
        "{%0,%1,%2,%3}, {%4,%5,%6,%7}, {%8,%9}, {%0,%1,%2,%3};\n"
        : "+f"(d[0]), "+f"(d[1]), "+f"(d[2]), "+f"(d[3])
        : "r"(a[0]), "r"(a[1]), "r"(a[2]), "r"(a[3]),
          "r"(b[0]), "r"(b[1]));
}
__device__ __forceinline__ void ldsm4(uint32_t& r0, uint32_t& r1, uint32_t& r2,
                                      uint32_t& r3, uint32_t addr) {
    asm volatile("ldmatrix.sync.aligned.m8n8.x4.shared.b16 {%0,%1,%2,%3}, [%4];"
                 : "=r"(r0), "=r"(r1), "=r"(r2), "=r"(r3) : "r"(addr));
}
__device__ __forceinline__ void cp_async16(void* s, const void* g) {
    uint32_t sa = (uint32_t)__cvta_generic_to_shared(s);
    asm volatile("cp.async.cg.shared.global [%0], [%1], 16;\n" :: "r"(sa), "l"(g));
}
__device__ __forceinline__ void cp_commit() { asm volatile("cp.async.commit_group;\n"); }
template<int N> __device__ __forceinline__ void cp_wait() {
    asm volatile("cp.async.wait_group %0;\n" :: "n"(N));
}

#define HS 72                           // half stride (64 + 8 pad)

// ================= generic FP16 GEMM (BM=BN=128, 3-stage) =================
#define TILE_HALFS (128 * HS)
#define STAGE_HALFS (2 * TILE_HALFS)
#define TILE_BYTES (TILE_HALFS * 2)
#define STAGE_BYTES (STAGE_HALFS * 2)
#define SMEM_BYTES (3 * STAGE_BYTES)    // 110,592 B

template<bool RELU, bool MASK, bool HALF_OUT>
__global__ __launch_bounds__(256, 2)
void hgemm_k(const half_t* __restrict__ A, const half_t* __restrict__ B,
             const float* __restrict__ bias, const unsigned char* __restrict__ mask,
             float* __restrict__ Cf, half_t* __restrict__ Ch, int K, int Nout)
{
    extern __shared__ half_t sm[];

    const int tid  = threadIdx.x;
    const int brow = blockIdx.x * 128;
    const int bcol = blockIdx.y * 128;

    const int lane = tid & 31;
    const int wid  = tid >> 5;
    const int wm   = (wid >> 2) * 64;
    const int wn   = (wid & 3) * 32;
    const int gr   = lane >> 2;
    const int gc   = lane & 3;

    const uint32_t smemU = (uint32_t)__cvta_generic_to_shared(sm);
    const uint32_t aOff = ((wm + (lane & 7) + ((lane >> 3) & 1) * 8) * HS
                           + ((lane >> 4) & 1) * 8) * 2;
    const uint32_t bOff = ((wn + (lane & 7) + ((lane >> 4) & 1) * 8) * HS
                           + ((lane >> 3) & 1) * 8) * 2;

    float acc[4][4][4];
#pragma unroll
    for (int i = 0; i < 4; i++)
#pragma unroll
        for (int j = 0; j < 4; j++)
#pragma unroll
            for (int t = 0; t < 4; t++) acc[i][j][t] = 0.f;

    const int nch = K >> 6;

    auto issue = [&](int chunk, int stg) {
        const int k0 = chunk << 6;
        half_t* As = sm + stg * STAGE_HALFS;
        half_t* Bs = As + TILE_HALFS;
#pragma unroll
        for (int i = 0; i < 4; i++) {
            int t = tid + i * 256;
            int r = t >> 3, q = (t & 7) << 3;
            cp_async16(As + r * HS + q, A + (size_t)(brow + r) * K + k0 + q);
        }
#pragma unroll
        for (int i = 0; i < 4; i++) {
            int t = tid + i * 256;
            int r = t >> 3, q = (t & 7) << 3;
            cp_async16(Bs + r * HS + q, B + (size_t)(bcol + r) * K + k0 + q);
        }
        cp_commit();
    };

    issue(0, 0);
    if (nch > 1) issue(1, 1);
    else cp_commit();

    for (int c = 0; c < nch; c++) {
        const int cur = c % 3;
        if (c + 2 < nch) issue(c + 2, (c + 2) % 3);
        else cp_commit();
        cp_wait<2>();
        __syncthreads();

        const uint32_t aBase = smemU + cur * STAGE_BYTES + aOff;
        const uint32_t bBase = smemU + cur * STAGE_BYTES + TILE_BYTES + bOff;
#pragma unroll
        for (int kk = 0; kk < 4; kk++) {
            uint32_t af[4][4], bf[4][2];
#pragma unroll
            for (int mt = 0; mt < 4; mt++)
                ldsm4(af[mt][0], af[mt][1], af[mt][2], af[mt][3],
                      aBase + mt * (16 * HS * 2) + kk * 32);
#pragma unroll
            for (int ntp = 0; ntp < 2; ntp++)
                ldsm4(bf[2 * ntp][0], bf[2 * ntp][1], bf[2 * ntp + 1][0], bf[2 * ntp + 1][1],
                      bBase + ntp * (16 * HS * 2) + kk * 32);
#pragma unroll
            for (int mt = 0; mt < 4; mt++)
#pragma unroll
                for (int nt = 0; nt < 4; nt++)
                    mma_fp16(acc[mt][nt], af[mt], bf[nt]);
        }
        __syncthreads();
    }

#pragma unroll
    for (int mt = 0; mt < 4; mt++) {
        int r0 = brow + wm + mt * 16 + gr;
        int r1 = r0 + 8;
        float ms0 = 1.f, ms1 = 1.f;
        if (MASK) { ms0 = mask[r0] ? 0.f : 1.f; ms1 = mask[r1] ? 0.f : 1.f; }
#pragma unroll
        for (int nt = 0; nt < 4; nt++) {
            int col = bcol + wn + nt * 8 + gc * 2;
            float2 bi = *reinterpret_cast<const float2*>(&bias[col]);
            float v0 = acc[mt][nt][0] + bi.x;
            float v1 = acc[mt][nt][1] + bi.y;
            float v2 = acc[mt][nt][2] + bi.x;
            float v3 = acc[mt][nt][3] + bi.y;
            if (MASK) { v0 *= ms0; v1 *= ms0; v2 *= ms1; v3 *= ms1; }
            if (RELU) {
                v0 = fmaxf(v0, 0.f); v1 = fmaxf(v1, 0.f);
                v2 = fmaxf(v2, 0.f); v3 = fmaxf(v3, 0.f);
            }
            if (HALF_OUT) {
                *reinterpret_cast<__half2*>(&Ch[(size_t)r0 * Nout + col]) = __floats2half2_rn(v0, v1);
                *reinterpret_cast<__half2*>(&Ch[(size_t)r1 * Nout + col]) = __floats2half2_rn(v2, v3);
            } else {
                *reinterpret_cast<float2*>(&Cf[(size_t)r0 * Nout + col]) = make_float2(v0, v1);
                *reinterpret_cast<float2*>(&Cf[(size_t)r1 * Nout + col]) = make_float2(v2, v3);
            }
        }
    }
}

// ============ fused GEMM + residual + LayerNorm (BM=64, BN=256, 2-stage) ============
#define LN_A_HALFS (64 * HS)
#define LN_B_HALFS (256 * HS)
#define LN_STAGE_HALFS (LN_A_HALFS + LN_B_HALFS)
#define LN_RED_FLOATS (2 * 64 * 8 + 64 * 2)
#define LN_SMEM_BYTES (2 * LN_STAGE_HALFS * 2 + LN_RED_FLOATS * 4)

template<bool WRITE_H>
__global__ __launch_bounds__(256, 2)
void hgemm_ln_k(const half_t* __restrict__ A, const half_t* __restrict__ B,
                const float* __restrict__ bias, const float* __restrict__ Res,
                const float* __restrict__ gam, const float* __restrict__ bet,
                float* __restrict__ Of, half_t* __restrict__ Oh, int K)
{
    extern __shared__ half_t sm[];
    float* red  = reinterpret_cast<float*>(sm + 2 * LN_STAGE_HALFS);
    float* stat = red + 2 * 64 * 8;

    const int tid  = threadIdx.x;
    const int brow = blockIdx.x * 64;

    const int lane = tid & 31;
    const int wid  = tid >> 5;
    const int wn   = wid * 32;
    const int gr   = lane >> 2;
    const int gc   = lane & 3;

    const uint32_t smemU = (uint32_t)__cvta_generic_to_shared(sm);
    const uint32_t aOff = (((lane & 7) + ((lane >> 3) & 1) * 8) * HS
                           + ((lane >> 4) & 1) * 8) * 2;
    const uint32_t bOff = ((wn + (lane & 7) + ((lane >> 4) & 1) * 8) * HS
                           + ((lane >> 3) & 1) * 8) * 2;

    float acc[4][4][4];
#pragma unroll
    for (int i = 0; i < 4; i++)
#pragma unroll
        for (int j = 0; j < 4; j++)
#pragma unroll
            for (int t = 0; t < 4; t++) acc[i][j][t] = 0.f;

    const int nch = K >> 6;

    auto issue = [&](int chunk, int stg) {
        const int k0 = chunk << 6;
        half_t* As = sm + stg * LN_STAGE_HALFS;
        half_t* Bs = As + LN_A_HALFS;
#pragma unroll
        for (int i = 0; i < 2; i++) {
            int t = tid + i * 256;
            int r = t >> 3, q = (t & 7) << 3;
            cp_async16(As + r * HS + q, A + (size_t)(brow + r) * K + k0 + q);
        }
#pragma unroll
        for (int i = 0; i < 8; i++) {
            int t = tid + i * 256;
            int r = t >> 3, q = (t & 7) << 3;
            cp_async16(Bs + r * HS + q, B + (size_t)r * K + k0 + q);
        }
        cp_commit();
    };

    issue(0, 0);

    for (int c = 0; c < nch; c++) {
        const int cur = c & 1;
        if (c + 1 < nch) { issue(c + 1, cur ^ 1); cp_wait<1>(); }
        else cp_wait<0>();
        __syncthreads();

        const uint32_t aBase = smemU + cur * (LN_STAGE_HALFS * 2) + aOff;
        const uint32_t bBase = smemU + cur * (LN_STAGE_HALFS * 2) + LN_A_HALFS * 2 + bOff;
#pragma unroll
        for (int kk = 0; kk < 4; kk++) {
            uint32_t af[4][4], bf[4][2];
#pragma unroll
            for (int mt = 0; mt < 4; mt++)
                ldsm4(af[mt][0], af[mt][1], af[mt][2], af[mt][3],
                      aBase + mt * (16 * HS * 2) + kk * 32);
#pragma unroll
            for (int ntp = 0; ntp < 2; ntp++)
                ldsm4(bf[2 * ntp][0], bf[2 * ntp][1], bf[2 * ntp + 1][0], bf[2 * ntp + 1][1],
                      bBase + ntp * (16 * HS * 2) + kk * 32);
#pragma unroll
            for (int mt = 0; mt < 4; mt++)
#pragma unroll
                for (int nt = 0; nt < 4; nt++)
                    mma_fp16(acc[mt][nt], af[mt], bf[nt]);
        }
        __syncthreads();
    }

#pragma unroll
    for (int mt = 0; mt < 4; mt++) {
        int r0 = mt * 16 + gr, r1 = r0 + 8;
        float s0 = 0.f, q0 = 0.f, s1 = 0.f, q1 = 0.f;
#pragma unroll
        for (int nt = 0; nt < 4; nt++) {
            int col = wn + nt * 8 + gc * 2;
            float2 bi = *reinterpret_cast<const float2*>(&bias[col]);
            float2 e0 = *reinterpret_cast<const float2*>(&Res[(size_t)(brow + r0) * 256 + col]);
            float2 e1 = *reinterpret_cast<const float2*>(&Res[(size_t)(brow + r1) * 256 + col]);
            float v0 = acc[mt][nt][0] + bi.x + e0.x;
            float v1 = acc[mt][nt][1] + bi.y + e0.y;
            float v2 = acc[mt][nt][2] + bi.x + e1.x;
            float v3 = acc[mt][nt][3] + bi.y + e1.y;
            acc[mt][nt][0] = v0; acc[mt][nt][1] = v1;
            acc[mt][nt][2] = v2; acc[mt][nt][3] = v3;
            s0 += v0 + v1; q0 += v0 * v0 + v1 * v1;
            s1 += v2 + v3; q1 += v2 * v2 + v3 * v3;
        }
#pragma unroll
        for (int o = 1; o <= 2; o <<= 1) {
            s0 += __shfl_xor_sync(0xffffffffu, s0, o);
            q0 += __shfl_xor_sync(0xffffffffu, q0, o);
            s1 += __shfl_xor_sync(0xffffffffu, s1, o);
            q1 += __shfl_xor_sync(0xffffffffu, q1, o);
        }
        if (gc == 0) {
            red[r0 * 8 + wid] = s0;  red[512 + r0 * 8 + wid] = q0;
            red[r1 * 8 + wid] = s1;  red[512 + r1 * 8 + wid] = q1;
        }
    }
    __syncthreads();
    if (tid < 64) {
        float s = 0.f, q = 0.f;
#pragma unroll
        for (int w = 0; w < 8; w++) { s += red[tid * 8 + w]; q += red[512 + tid * 8 + w]; }
        float m = s * (1.f / 256.f);
        float var = q * (1.f / 256.f) - m * m;
        stat[tid * 2 + 0] = m;
        stat[tid * 2 + 1] = rsqrtf(var + 1e-5f);
    }
    __syncthreads();

#pragma unroll
    for (int mt = 0; mt < 4; mt++) {
        int r0 = mt * 16 + gr, r1 = r0 + 8;
        float m0 = stat[r0 * 2], iv0 = stat[r0 * 2 + 1];
        float m1 = stat[r1 * 2], iv1 = stat[r1 * 2 + 1];
#pragma unroll
        for (int nt = 0; nt < 4; nt++) {
            int col = wn + nt * 8 + gc * 2;
            float2 gm = *reinterpret_cast<const float2*>(&gam[col]);
            float2 bt = *reinterpret_cast<const float2*>(&bet[col]);
            float o0 = (acc[mt][nt][0] - m0) * iv0 * gm.x + bt.x;
            float o1 = (acc[mt][nt][1] - m0) * iv0 * gm.y + bt.y;
            float o2 = (acc[mt][nt][2] - m1) * iv1 * gm.x + bt.x;
            float o3 = (acc[mt][nt][3] - m1) * iv1 * gm.y + bt.y;
            *reinterpret_cast<float2*>(&Of[(size_t)(brow + r0) * 256 + col]) = make_float2(o0, o1);
            *reinterpret_cast<float2*>(&Of[(size_t)(brow + r1) * 256 + col]) = make_float2(o2, o3);
            if (WRITE_H) {
                *reinterpret_cast<__half2*>(&Oh[(size_t)(brow + r0) * 256 + col]) = __floats2half2_rn(o0, o1);
                *reinterpret_cast<__half2*>(&Oh[(size_t)(brow + r1) * 256 + col]) = __floats2half2_rn(o2, o3);
            }
        }
    }
}

// ---------------- merged prep: all weight transposes + bias concat ----------------
__global__ void prep_k(const float* __restrict__ w_val, const float* __restrict__ w_off,
                       const float* __restrict__ w_attn, const float* __restrict__ w_out,
                       const float* __restrict__ w_ff1, const float* __restrict__ w_ff2,
                       const float* __restrict__ b_off, const float* __restrict__ b_attn,
                       half_t* __restrict__ WvT, half_t* __restrict__ WqaT,
                       half_t* __restrict__ WuT, half_t* __restrict__ W1T,
                       half_t* __restrict__ W2T, float* __restrict__ bqa)
{
    int idx = blockIdx.x * blockDim.x + threadIdx.x;
    auto tr = [](const float* w, half_t* o, int i, int K, int N) {
        int n = i / K, k = i % K;
        o[i] = __float2half_rn(w[(size_t)k * N + n]);
    };
    if (idx < 65536)                { tr(w_val,  WvT,              idx, 256,  256);  return; }
    if ((idx -= 65536) < 65536)     { tr(w_off,  WqaT,             idx, 256,  256);  return; }
    if ((idx -= 65536) < 32768)     { tr(w_attn, WqaT + 256 * CD,  idx, 256,  128);  return; }
    if ((idx -= 32768) < 65536)     { tr(w_out,  WuT,              idx, 256,  256);  return; }
    if ((idx -= 65536) < 262144)    { tr(w_ff1,  W1T,              idx, 256,  1024); return; }
    if ((idx -= 262144) < 262144)   { tr(w_ff2,  W2T,              idx, 1024, 256);  return; }
    idx -= 262144;
    if (idx < 256)      bqa[idx] = b_off[idx];
    else if (idx < 384) bqa[idx] = b_attn[idx - 256];
}

// ---------------- addvec: srcH = h(src); QH = h(src+pos) ----------------
__global__ void addvec_k(const float* __restrict__ a, const float* __restrict__ b,
                         half_t* __restrict__ sh, half_t* __restrict__ qh)
{
    int i = blockIdx.x * blockDim.x + threadIdx.x;
    float4 x = reinterpret_cast<const float4*>(a)[i];
    float4 y = reinterpret_cast<const float4*>(b)[i];
    __half2 s0 = __floats2half2_rn(x.x, x.y);
    __half2 s1 = __floats2half2_rn(x.z, x.w);
    __half2 q0 = __floats2half2_rn(x.x + y.x, x.y + y.y);
    __half2 q1 = __floats2half2_rn(x.z + y.z, x.w + y.w);
    reinterpret_cast<__half2*>(sh)[i * 2 + 0] = s0;
    reinterpret_cast<__half2*>(sh)[i * 2 + 1] = s1;
    reinterpret_cast<__half2*>(qh)[i * 2 + 0] = q0;
    reinterpret_cast<__half2*>(qh)[i * 2 + 1] = q1;
}

// ---------------- deformable sampling: 4 heads/warp, half4 channels ----------------
// block = 256 threads = 8 warps = 4 rows (2 warps per row, 4 heads per warp).
// lane>>3 = head-in-warp (0..3), lane&7 = channel-quad (4 halves = 8B per lane).
__global__ void deform_k(const half_t* __restrict__ V, const float* __restrict__ OA,
                         const float* __restrict__ REF, half_t* __restrict__ OUT)
{
    const int tid  = threadIdx.x;
    const int w    = tid >> 5;
    const int lane = tid & 31;
    const int row  = blockIdx.x * 4 + (w >> 1);
    const int h    = ((w & 1) << 2) + (lane >> 3);
    const int cq   = lane & 7;                  // channel-quad index
    const int n    = row / LQN;

    // softmax over this head's 16 logits; each lane owns logits cq and cq+8
    const float* lgp = OA + (size_t)row * 384 + 256 + h * 16;
    float lg0 = lgp[cq], lg1 = lgp[cq + 8];
    float mx = fmaxf(lg0, lg1);
#pragma unroll
    for (int o = 4; o; o >>= 1) mx = fmaxf(mx, __shfl_xor_sync(0xffffffffu, mx, o));
    float e0 = expf(lg0 - mx), e1 = expf(lg1 - mx);
    float sum = e0 + e1;
#pragma unroll
    for (int o = 4; o; o >>= 1) sum += __shfl_xor_sync(0xffffffffu, sum, o);
    float inv = 1.f / sum;
    float p0 = e0 * inv, p1 = e1 * inv;        // probs for samples cq and cq+8

    const float*  off = OA + (size_t)row * 384 + h * 32;
    const float*  ref = REF + (size_t)row * 8;
    const half_t* Vb  = V + (size_t)n * LQN * 256 + h * 32 + 4 * cq;
    const int     gbase = lane & 24;           // head-group lane base

    const int   Wt[4]   = {64, 32, 16, 8};
    const int   St[4]   = {0, 4096, 5120, 5376};
    const float invW[4] = {1.f/64.f, 1.f/32.f, 1.f/16.f, 1.f/8.f};

    float a0 = 0.f, a1 = 0.f, a2 = 0.f, a3 = 0.f;
#pragma unroll
    for (int l = 0; l < 4; l++) {
        const int W = Wt[l], H = Wt[l];
        const half_t* Vl = Vb + (size_t)St[l] * 256;
        const float rx = ref[l * 2 + 0], ry = ref[l * 2 + 1];
#pragma unroll
        for (int p = 0; p < 4; p++) {
            const int s = l * 4 + p;
            float ox = off[s * 2 + 0];
            float oy = off[s * 2 + 1];
            float lx = rx + ox * invW[l];
            float ly = ry + oy * invW[l];
            float gx = 2.f * lx - 1.f, gy = 2.f * ly - 1.f;
            float x = (gx + 1.f) * (W * 0.5f) - 0.5f;
            float y = (gy + 1.f) * (H * 0.5f) - 0.5f;
            float x0f = floorf(x), y0f = floorf(y);
            float wx = x - x0f, wy = y - y0f;
            int x0 = (int)x0f, y0 = (int)y0f;
            // per-sample softmax weight: owner lane gbase|(s&7), field p0 (s<8) or p1
            int src = gbase | (s & 7);
            float aw0 = __shfl_sync(0xffffffffu, p0, src);
            float aw1 = __shfl_sync(0xffffffffu, p1, src);
            float a = (s < 8) ? aw0 : aw1;
            bool xv0 = (x0 >= 0)  && (x0 < W);
            bool xv1 = (x0 >= -1) && (x0 < W - 1);
            bool yv0 = (y0 >= 0)  && (y0 < H);
            bool yv1 = (y0 >= -1) && (y0 < H - 1);
            float w00 = (1.f - wx) * (1.f - wy) * a;
            float w10 = wx * (1.f - wy) * a;
            float w01 = (1.f - wx) * wy * a;
            float w11 = wx * wy * a;
            if (xv0 && yv0) {
                uint2 u = *reinterpret_cast<const uint2*>(Vl + (y0 * W + x0) * 256);
                float2 vA = __half22float2(*reinterpret_cast<__half2*>(&u.x));
                float2 vB = __half22float2(*reinterpret_cast<__half2*>(&u.y));
                a0 += w00 * vA.x; a1 += w00 * vA.y; a2 += w00 * vB.x; a3 += w00 * vB.y;
            }
            if (xv1 && yv0) {
                uint2 u = *reinterpret_cast<const uint2*>(Vl + (y0 * W + x0 + 1) * 256);
                float2 vA = __half22float2(*reinterpret_cast<__half2*>(&u.x));
                float2 vB = __half22float2(*reinterpret_cast<__half2*>(&u.y));
                a0 += w10 * vA.x; a1 += w10 * vA.y; a2 += w10 * vB.x; a3 += w10 * vB.y;
            }
            if (xv0 && yv1) {
                uint2 u = *reinterpret_cast<const uint2*>(Vl + ((y0 + 1) * W + x0) * 256);
                float2 vA = __half22float2(*reinterpret_cast<__half2*>(&u.x));
                float2 vB = __half22float2(*reinterpret_cast<__half2*>(&u.y));
                a0 += w01 * vA.x; a1 += w01 * vA.y; a2 += w01 * vB.x; a3 += w01 * vB.y;
            }
            if (xv1 && yv1) {
                uint2 u = *reinterpret_cast<const uint2*>(Vl + ((y0 + 1) * W + x0 + 1) * 256);
                float2 vA = __half22float2(*reinterpret_cast<__half2*>(&u.x));
                float2 vB = __half22float2(*reinterpret_cast<__half2*>(&u.y));
                a0 += w11 * vA.x; a1 += w11 * vA.y; a2 += w11 * vB.x; a3 += w11 * vB.y;
            }
        }
    }
    half_t* dst = &OUT[(size_t)row * 256 + h * 32 + 4 * cq];
    *reinterpret_cast<__half2*>(dst)     = __floats2half2_rn(a0, a1);
    *reinterpret_cast<__half2*>(dst + 2) = __floats2half2_rn(a2, a3);
}

// ---------------- launch ----------------
extern "C" void kernel_launch(void* const* d_in, const int* in_sizes, int n_in,
                              void* d_out, int out_size)
{
    const float* src    = (const float*)d_in[0];
    const float* pos    = (const float*)d_in[1];
    const float* ref    = (const float*)d_in[2];
    const float* w_off  = (const float*)d_in[3];
    const float* b_off  = (const float*)d_in[4];
    const float* w_attn = (const float*)d_in[5];
    const float* b_attn = (const float*)d_in[6];
    const float* w_val  = (const float*)d_in[7];
    const float* b_val  = (const float*)d_in[8];
    const float* w_out  = (const float*)d_in[9];
    const float* b_out  = (const float*)d_in[10];
    const float* g1     = (const float*)d_in[11];
    const float* be1    = (const float*)d_in[12];
    const float* w_ff1  = (const float*)d_in[13];
    const float* b_ff1  = (const float*)d_in[14];
    const float* w_ff2  = (const float*)d_in[15];
    const float* b_ff2  = (const float*)d_in[16];
    const float* g2     = (const float*)d_in[17];
    const float* be2    = (const float*)d_in[18];
    const unsigned char* mask = (const unsigned char*)d_in[19];

    half_t *srcH, *QH, *VH, *ATTH, *XH, *HH, *WvT, *WqaT, *WuT, *W1T, *W2T;
    float *pOA, *pX, *pbqa;
    cudaGetSymbolAddress((void**)&srcH, g_srcH);
    cudaGetSymbolAddress((void**)&QH,   g_QH);
    cudaGetSymbolAddress((void**)&VH,   g_VH);
    cudaGetSymbolAddress((void**)&ATTH, g_ATTH);
    cudaGetSymbolAddress((void**)&XH,   g_XH);
    cudaGetSymbolAddress((void**)&HH,   g_HH);
    cudaGetSymbolAddress((void**)&WvT,  g_WvT);
    cudaGetSymbolAddress((void**)&WqaT, g_WqaT);
    cudaGetSymbolAddress((void**)&WuT,  g_WuT);
    cudaGetSymbolAddress((void**)&W1T,  g_W1T);
    cudaGetSymbolAddress((void**)&W2T,  g_W2T);
    cudaGetSymbolAddress((void**)&pOA,  g_OA);
    cudaGetSymbolAddress((void**)&pX,   g_X);
    cudaGetSymbolAddress((void**)&pbqa, g_bqa);

    cudaFuncSetAttribute(hgemm_k<false, true,  true >, cudaFuncAttributeMaxDynamicSharedMemorySize, SMEM_BYTES);
    cudaFuncSetAttribute(hgemm_k<false, false, false>, cudaFuncAttributeMaxDynamicSharedMemorySize, SMEM_BYTES);
    cudaFuncSetAttribute(hgemm_k<true,  false, true >, cudaFuncAttributeMaxDynamicSharedMemorySize, SMEM_BYTES);
    cudaFuncSetAttribute(hgemm_ln_k<true >, cudaFuncAttributeMaxDynamicSharedMemorySize, LN_SMEM_BYTES);
    cudaFuncSetAttribute(hgemm_ln_k<false>, cudaFuncAttributeMaxDynamicSharedMemorySize, LN_SMEM_BYTES);

    addvec_k<<<RR * CD / 4 / 256, 256>>>(src, pos, srcH, QH);
    prep_k<<<(754048 + 255) / 256, 256>>>(w_val, w_off, w_attn, w_out, w_ff1, w_ff2,
                                          b_off, b_attn, WvT, WqaT, WuT, W1T, W2T, pbqa);

    // value = mask0(src @ w_val + b_val) -> fp16
    hgemm_k<false, true,  true ><<<dim3(340, 2), 256, SMEM_BYTES>>>(
        srcH, WvT, b_val, mask, nullptr, VH, 256, 256);
    // [off | attn logits] = Q @ [w_off | w_attn] + bqa
    hgemm_k<false, false, false><<<dim3(340, 3), 256, SMEM_BYTES>>>(
        QH, WqaT, pbqa, nullptr, pOA, nullptr, 256, 384);
    deform_k<<<RR / 4, 256>>>(VH, pOA, ref, ATTH);
    // X = LN1(src + ATT @ w_out + b_out)  -> pX fp32 + XH fp16
    hgemm_ln_k<true ><<<680, 256, LN_SMEM_BYTES>>>(
        ATTH, WuT, b_out, src, g1, be1, pX, XH, 256);
    // H = relu(X @ w_ff1 + b_ff1) -> fp16
    hgemm_k<true,  false, true ><<<dim3(340, 8), 256, SMEM_BYTES>>>(
        XH, W1T, b_ff1, nullptr, nullptr, HH, 256, 1024);
    // out = LN2(X + H @ w_ff2 + b_ff2)
    hgemm_ln_k<false><<<680, 256, LN_SMEM_BYTES>>>(
        HH, W2T, b_ff2, pX, g2, be2, (float*)d_out, nullptr, 1024);
}

// round 14
// speedup vs baseline: 5.8825x; 1.0773x over previous
#include <cuda_runtime.h>
#include <cuda_fp16.h>
#include <cstdint>

#define NB 8
#define LQN 5440
#define CD 256
#define RR 43520          // NB*LQN
#define DFFN 1024

typedef __half half_t;

// ---------------- scratch (static device arrays; no allocation) ----------------
__device__ half_t g_srcH[RR * CD];
__device__ half_t g_QH  [RR * CD];
__device__ half_t g_VH  [RR * CD];
__device__ half_t g_ATTH[RR * CD];
__device__ half_t g_XH  [RR * CD];
__device__ half_t g_HH  [RR * DFFN];
// transposed fp16 weights [N][K]
__device__ half_t g_WvT [CD * CD];
__device__ half_t g_WqaT[384 * CD];
__device__ half_t g_WuT [CD * CD];
__device__ half_t g_W1T [DFFN * CD];
__device__ half_t g_W2T [CD * DFFN];
__device__ float  g_bqa [384];
// fp32 intermediates
__device__ float g_OA [RR * 384];            // off (256) ++ logits (128)
__device__ float g_X  [RR * CD];             // LN1 output fp32 (residual for LN2)

// ---------------- PTX helpers ----------------
__device__ __forceinline__ void mma_fp16(float d[4], const uint32_t a[4],
                                         const uint32_t b[2]) {
    asm volatile(
        "mma.sync.aligned.m16n8k16.row.col.f32.f16.f16.f32 "
        "{%0,%1,%2,%3}, {%4,%5,%6,%7}, {%8,%9}, {%0,%1,%2,%3};\n"
        : "+f"(d[0]), "+f"(d[1]), "+f"(d[2]), "+f"(d[3])
        : "r"(a[0]), "r"(a[1]), "r"(a[2]), "r"(a[3]),
          "r"(b[0]), "r"(b[1]));
}
__device__ __forceinline__ void ldsm4(uint32_t& r0, uint32_t& r1, uint32_t& r2,
                                      uint32_t& r3, uint32_t addr) {
    asm volatile("ldmatrix.sync.aligned.m8n8.x4.shared.b16 {%0,%1,%2,%3}, [%4];"
                 : "=r"(r0), "=r"(r1), "=r"(r2), "=r"(r3) : "r"(addr));
}
__device__ __forceinline__ void cp_async16(void* s, const void* g) {
    uint32_t sa = (uint32_t)__cvta_generic_to_shared(s);
    asm volatile("cp.async.cg.shared.global [%0], [%1], 16;\n" :: "r"(sa), "l"(g));
}
__device__ __forceinline__ void cp_commit() { asm volatile("cp.async.commit_group;\n"); }
template<int N> __device__ __forceinline__ void cp_wait() {
    asm volatile("cp.async.wait_group %0;\n" :: "n"(N));
}

#define HS 72                           // half stride (64 + 8 pad)

// ================= generic FP16 GEMM (BM=BN=128, 3-stage) =================
#define TILE_HALFS (128 * HS)
#define STAGE_HALFS (2 * TILE_HALFS)
#define TILE_BYTES (TILE_HALFS * 2)
#define STAGE_BYTES (STAGE_HALFS * 2)
#define SMEM_BYTES (3 * STAGE_BYTES)    // 110,592 B

template<bool RELU, bool MASK, bool HALF_OUT>
__global__ __launch_bounds__(256, 2)
void hgemm_k(const half_t* __restrict__ A, const half_t* __restrict__ B,
             const float* __restrict__ bias, const unsigned char* __restrict__ mask,
             float* __restrict__ Cf, half_t* __restrict__ Ch, int K, int Nout)
{
    extern __shared__ half_t sm[];

    const int tid  = threadIdx.x;
    const int brow = blockIdx.x * 128;
    const int bcol = blockIdx.y * 128;

    const int lane = tid & 31;
    const int wid  = tid >> 5;
    const int wm   = (wid >> 2) * 64;
    const int wn   = (wid & 3) * 32;
    const int gr   = lane >> 2;
    const int gc   = lane & 3;

    const uint32_t smemU = (uint32_t)__cvta_generic_to_shared(sm);
    const uint32_t aOff = ((wm + (lane & 7) + ((lane >> 3) & 1) * 8) * HS
                           + ((lane >> 4) & 1) * 8) * 2;
    const uint32_t bOff = ((wn + (lane & 7) + ((lane >> 4) & 1) * 8) * HS
                           + ((lane >> 3) & 1) * 8) * 2;

    float acc[4][4][4];
#pragma unroll
    for (int i = 0; i < 4; i++)
#pragma unroll
        for (int j = 0; j < 4; j++)
#pragma unroll
            for (int t = 0; t < 4; t++) acc[i][j][t] = 0.f;

    const int nch = K >> 6;

    auto issue = [&](int chunk, int stg) {
        const int k0 = chunk << 6;
        half_t* As = sm + stg * STAGE_HALFS;
        half_t* Bs = As + TILE_HALFS;
#pragma unroll
        for (int i = 0; i < 4; i++) {
            int t = tid + i * 256;
            int r = t >> 3, q = (t & 7) << 3;
            cp_async16(As + r * HS + q, A + (size_t)(brow + r) * K + k0 + q);
        }
#pragma unroll
        for (int i = 0; i < 4; i++) {
            int t = tid + i * 256;
            int r = t >> 3, q = (t & 7) << 3;
            cp_async16(Bs + r * HS + q, B + (size_t)(bcol + r) * K + k0 + q);
        }
        cp_commit();
    };

    issue(0, 0);
    if (nch > 1) issue(1, 1);
    else cp_commit();

    for (int c = 0; c < nch; c++) {
        const int cur = c % 3;
        if (c + 2 < nch) issue(c + 2, (c + 2) % 3);
        else cp_commit();
        cp_wait<2>();
        __syncthreads();

        const uint32_t aBase = smemU + cur * STAGE_BYTES + aOff;
        const uint32_t bBase = smemU + cur * STAGE_BYTES + TILE_BYTES + bOff;
#pragma unroll
        for (int kk = 0; kk < 4; kk++) {
            uint32_t af[4][4], bf[4][2];
#pragma unroll
            for (int mt = 0; mt < 4; mt++)
                ldsm4(af[mt][0], af[mt][1], af[mt][2], af[mt][3],
                      aBase + mt * (16 * HS * 2) + kk * 32);
#pragma unroll
            for (int ntp = 0; ntp < 2; ntp++)
                ldsm4(bf[2 * ntp][0], bf[2 * ntp][1], bf[2 * ntp + 1][0], bf[2 * ntp + 1][1],
                      bBase + ntp * (16 * HS * 2) + kk * 32);
#pragma unroll
            for (int mt = 0; mt < 4; mt++)
#pragma unroll
                for (int nt = 0; nt < 4; nt++)
                    mma_fp16(acc[mt][nt], af[mt], bf[nt]);
        }
        __syncthreads();
    }

#pragma unroll
    for (int mt = 0; mt < 4; mt++) {
        int r0 = brow + wm + mt * 16 + gr;
        int r1 = r0 + 8;
        float ms0 = 1.f, ms1 = 1.f;
        if (MASK) { ms0 = mask[r0] ? 0.f : 1.f; ms1 = mask[r1] ? 0.f : 1.f; }
#pragma unroll
        for (int nt = 0; nt < 4; nt++) {
            int col = bcol + wn + nt * 8 + gc * 2;
            float2 bi = *reinterpret_cast<const float2*>(&bias[col]);
            float v0 = acc[mt][nt][0] + bi.x;
            float v1 = acc[mt][nt][1] + bi.y;
            float v2 = acc[mt][nt][2] + bi.x;
            float v3 = acc[mt][nt][3] + bi.y;
            if (MASK) { v0 *= ms0; v1 *= ms0; v2 *= ms1; v3 *= ms1; }
            if (RELU) {
                v0 = fmaxf(v0, 0.f); v1 = fmaxf(v1, 0.f);
                v2 = fmaxf(v2, 0.f); v3 = fmaxf(v3, 0.f);
            }
            if (HALF_OUT) {
                *reinterpret_cast<__half2*>(&Ch[(size_t)r0 * Nout + col]) = __floats2half2_rn(v0, v1);
                *reinterpret_cast<__half2*>(&Ch[(size_t)r1 * Nout + col]) = __floats2half2_rn(v2, v3);
            } else {
                *reinterpret_cast<float2*>(&Cf[(size_t)r0 * Nout + col]) = make_float2(v0, v1);
                *reinterpret_cast<float2*>(&Cf[(size_t)r1 * Nout + col]) = make_float2(v2, v3);
            }
        }
    }
}

// ============ fused GEMM + residual + LayerNorm (BM=64, BN=256, 2-stage) ============
#define LN_A_HALFS (64 * HS)
#define LN_B_HALFS (256 * HS)
#define LN_STAGE_HALFS (LN_A_HALFS + LN_B_HALFS)
#define LN_RED_FLOATS (2 * 64 * 8 + 64 * 2)
#define LN_SMEM_BYTES (2 * LN_STAGE_HALFS * 2 + LN_RED_FLOATS * 4)

template<bool WRITE_H>
__global__ __launch_bounds__(256, 2)
void hgemm_ln_k(const half_t* __restrict__ A, const half_t* __restrict__ B,
                const float* __restrict__ bias, const float* __restrict__ Res,
                const float* __restrict__ gam, const float* __restrict__ bet,
                float* __restrict__ Of, half_t* __restrict__ Oh, int K)
{
    extern __shared__ half_t sm[];
    float* red  = reinterpret_cast<float*>(sm + 2 * LN_STAGE_HALFS);
    float* stat = red + 2 * 64 * 8;

    const int tid  = threadIdx.x;
    const int brow = blockIdx.x * 64;

    const int lane = tid & 31;
    const int wid  = tid >> 5;
    const int wn   = wid * 32;
    const int gr   = lane >> 2;
    const int gc   = lane & 3;

    const uint32_t smemU = (uint32_t)__cvta_generic_to_shared(sm);
    const uint32_t aOff = (((lane & 7) + ((lane >> 3) & 1) * 8) * HS
                           + ((lane >> 4) & 1) * 8) * 2;
    const uint32_t bOff = ((wn + (lane & 7) + ((lane >> 4) & 1) * 8) * HS
                           + ((lane >> 3) & 1) * 8) * 2;

    float acc[4][4][4];
#pragma unroll
    for (int i = 0; i < 4; i++)
#pragma unroll
        for (int j = 0; j < 4; j++)
#pragma unroll
            for (int t = 0; t < 4; t++) acc[i][j][t] = 0.f;

    const int nch = K >> 6;

    auto issue = [&](int chunk, int stg) {
        const int k0 = chunk << 6;
        half_t* As = sm + stg * LN_STAGE_HALFS;
        half_t* Bs = As + LN_A_HALFS;
#pragma unroll
        for (int i = 0; i < 2; i++) {
            int t = tid + i * 256;
            int r = t >> 3, q = (t & 7) << 3;
            cp_async16(As + r * HS + q, A + (size_t)(brow + r) * K + k0 + q);
        }
#pragma unroll
        for (int i = 0; i < 8; i++) {
            int t = tid + i * 256;
            int r = t >> 3, q = (t & 7) << 3;
            cp_async16(Bs + r * HS + q, B + (size_t)r * K + k0 + q);
        }
        cp_commit();
    };

    issue(0, 0);

    for (int c = 0; c < nch; c++) {
        const int cur = c & 1;
        if (c + 1 < nch) { issue(c + 1, cur ^ 1); cp_wait<1>(); }
        else cp_wait<0>();
        __syncthreads();

        const uint32_t aBase = smemU + cur * (LN_STAGE_HALFS * 2) + aOff;
        const uint32_t bBase = smemU + cur * (LN_STAGE_HALFS * 2) + LN_A_HALFS * 2 + bOff;
#pragma unroll
        for (int kk = 0; kk < 4; kk++) {
            uint32_t af[4][4], bf[4][2];
#pragma unroll
            for (int mt = 0; mt < 4; mt++)
                ldsm4(af[mt][0], af[mt][1], af[mt][2], af[mt][3],
                      aBase + mt * (16 * HS * 2) + kk * 32);
#pragma unroll
            for (int ntp = 0; ntp < 2; ntp++)
                ldsm4(bf[2 * ntp][0], bf[2 * ntp][1], bf[2 * ntp + 1][0], bf[2 * ntp + 1][1],
                      bBase + ntp * (16 * HS * 2) + kk * 32);
#pragma unroll
            for (int mt = 0; mt < 4; mt++)
#pragma unroll
                for (int nt = 0; nt < 4; nt++)
                    mma_fp16(acc[mt][nt], af[mt], bf[nt]);
        }
        __syncthreads();
    }

#pragma unroll
    for (int mt = 0; mt < 4; mt++) {
        int r0 = mt * 16 + gr, r1 = r0 + 8;
        float s0 = 0.f, q0 = 0.f, s1 = 0.f, q1 = 0.f;
#pragma unroll
        for (int nt = 0; nt < 4; nt++) {
            int col = wn + nt * 8 + gc * 2;
            float2 bi = *reinterpret_cast<const float2*>(&bias[col]);
            float2 e0 = *reinterpret_cast<const float2*>(&Res[(size_t)(brow + r0) * 256 + col]);
            float2 e1 = *reinterpret_cast<const float2*>(&Res[(size_t)(brow + r1) * 256 + col]);
            float v0 = acc[mt][nt][0] + bi.x + e0.x;
            float v1 = acc[mt][nt][1] + bi.y + e0.y;
            float v2 = acc[mt][nt][2] + bi.x + e1.x;
            float v3 = acc[mt][nt][3] + bi.y + e1.y;
            acc[mt][nt][0] = v0; acc[mt][nt][1] = v1;
            acc[mt][nt][2] = v2; acc[mt][nt][3] = v3;
            s0 += v0 + v1; q0 += v0 * v0 + v1 * v1;
            s1 += v2 + v3; q1 += v2 * v2 + v3 * v3;
        }
#pragma unroll
        for (int o = 1; o <= 2; o <<= 1) {
            s0 += __shfl_xor_sync(0xffffffffu, s0, o);
            q0 += __shfl_xor_sync(0xffffffffu, q0, o);
            s1 += __shfl_xor_sync(0xffffffffu, s1, o);
            q1 += __shfl_xor_sync(0xffffffffu, q1, o);
        }
        if (gc == 0) {
            red[r0 * 8 + wid] = s0;  red[512 + r0 * 8 + wid] = q0;
            red[r1 * 8 + wid] = s1;  red[512 + r1 * 8 + wid] = q1;
        }
    }
    __syncthreads();
    if (tid < 64) {
        float s = 0.f, q = 0.f;
#pragma unroll
        for (int w = 0; w < 8; w++) { s += red[tid * 8 + w]; q += red[512 + tid * 8 + w]; }
        float m = s * (1.f / 256.f);
        float var = q * (1.f / 256.f) - m * m;
        stat[tid * 2 + 0] = m;
        stat[tid * 2 + 1] = rsqrtf(var + 1e-5f);
    }
    __syncthreads();

#pragma unroll
    for (int mt = 0; mt < 4; mt++) {
        int r0 = mt * 16 + gr, r1 = r0 + 8;
        float m0 = stat[r0 * 2], iv0 = stat[r0 * 2 + 1];
        float m1 = stat[r1 * 2], iv1 = stat[r1 * 2 + 1];
#pragma unroll
        for (int nt = 0; nt < 4; nt++) {
            int col = wn + nt * 8 + gc * 2;
            float2 gm = *reinterpret_cast<const float2*>(&gam[col]);
            float2 bt = *reinterpret_cast<const float2*>(&bet[col]);
            float o0 = (acc[mt][nt][0] - m0) * iv0 * gm.x + bt.x;
            float o1 = (acc[mt][nt][1] - m0) * iv0 * gm.y + bt.y;
            float o2 = (acc[mt][nt][2] - m1) * iv1 * gm.x + bt.x;
            float o3 = (acc[mt][nt][3] - m1) * iv1 * gm.y + bt.y;
            *reinterpret_cast<float2*>(&Of[(size_t)(brow + r0) * 256 + col]) = make_float2(o0, o1);
            *reinterpret_cast<float2*>(&Of[(size_t)(brow + r1) * 256 + col]) = make_float2(o2, o3);
            if (WRITE_H) {
                *reinterpret_cast<__half2*>(&Oh[(size_t)(brow + r0) * 256 + col]) = __floats2half2_rn(o0, o1);
                *reinterpret_cast<__half2*>(&Oh[(size_t)(brow + r1) * 256 + col]) = __floats2half2_rn(o2, o3);
            }
        }
    }
}

// ---------------- merged prep: all weight transposes + bias concat ----------------
__global__ void prep_k(const float* __restrict__ w_val, const float* __restrict__ w_off,
                       const float* __restrict__ w_attn, const float* __restrict__ w_out,
                       const float* __restrict__ w_ff1, const float* __restrict__ w_ff2,
                       const float* __restrict__ b_off, const float* __restrict__ b_attn,
                       half_t* __restrict__ WvT, half_t* __restrict__ WqaT,
                       half_t* __restrict__ WuT, half_t* __restrict__ W1T,
                       half_t* __restrict__ W2T, float* __restrict__ bqa)
{
    int idx = blockIdx.x * blockDim.x + threadIdx.x;
    auto tr = [](const float* w, half_t* o, int i, int K, int N) {
        int n = i / K, k = i % K;
        o[i] = __float2half_rn(w[(size_t)k * N + n]);
    };
    if (idx < 65536)                { tr(w_val,  WvT,              idx, 256,  256);  return; }
    if ((idx -= 65536) < 65536)     { tr(w_off,  WqaT,             idx, 256,  256);  return; }
    if ((idx -= 65536) < 32768)     { tr(w_attn, WqaT + 256 * CD,  idx, 256,  128);  return; }
    if ((idx -= 32768) < 65536)     { tr(w_out,  WuT,              idx, 256,  256);  return; }
    if ((idx -= 65536) < 262144)    { tr(w_ff1,  W1T,              idx, 256,  1024); return; }
    if ((idx -= 262144) < 262144)   { tr(w_ff2,  W2T,              idx, 1024, 256);  return; }
    idx -= 262144;
    if (idx < 256)      bqa[idx] = b_off[idx];
    else if (idx < 384) bqa[idx] = b_attn[idx - 256];
}

// ---------------- addvec: srcH = h(src); QH = h(src+pos) ----------------
__global__ void addvec_k(const float* __restrict__ a, const float* __restrict__ b,
                         half_t* __restrict__ sh, half_t* __restrict__ qh)
{
    int i = blockIdx.x * blockDim.x + threadIdx.x;
    float4 x = reinterpret_cast<const float4*>(a)[i];
    float4 y = reinterpret_cast<const float4*>(b)[i];
    __half2 s0 = __floats2half2_rn(x.x, x.y);
    __half2 s1 = __floats2half2_rn(x.z, x.w);
    __half2 q0 = __floats2half2_rn(x.x + y.x, x.y + y.y);
    __half2 q1 = __floats2half2_rn(x.z + y.z, x.w + y.w);
    reinterpret_cast<__half2*>(sh)[i * 2 + 0] = s0;
    reinterpret_cast<__half2*>(sh)[i * 2 + 1] = s1;
    reinterpret_cast<__half2*>(qh)[i * 2 + 0] = q0;
    reinterpret_cast<__half2*>(qh)[i * 2 + 1] = q1;
}

// ---------------- deformable sampling: 8 heads/warp, 16B gathers ----------------
// block = 256 threads = 8 warps = 8 rows (1 warp per row).
// lane>>2 = head (0..7), lane&3 = channel-octet (8 halves = 16B per lane).
__global__ void deform_k(const half_t* __restrict__ V, const float* __restrict__ OA,
                         const float* __restrict__ REF, half_t* __restrict__ OUT)
{
    const int tid  = threadIdx.x;
    const int w    = tid >> 5;
    const int lane = tid & 31;
    const int row  = blockIdx.x * 8 + w;
    const int h    = lane >> 2;
    const int co   = lane & 3;                  // channel-octet index
    const int n    = row / LQN;

    // softmax over this head's 16 logits; lane owns logits co, co+4, co+8, co+12
    const float* lgp = OA + (size_t)row * 384 + 256 + h * 16;
    float l0 = lgp[co], l1 = lgp[co + 4], l2 = lgp[co + 8], l3 = lgp[co + 12];
    float mx = fmaxf(fmaxf(l0, l1), fmaxf(l2, l3));
#pragma unroll
    for (int o = 2; o; o >>= 1) mx = fmaxf(mx, __shfl_xor_sync(0xffffffffu, mx, o));
    float e0 = expf(l0 - mx), e1 = expf(l1 - mx), e2 = expf(l2 - mx), e3 = expf(l3 - mx);
    float sum = e0 + e1 + e2 + e3;
#pragma unroll
    for (int o = 2; o; o >>= 1) sum += __shfl_xor_sync(0xffffffffu, sum, o);
    float inv = 1.f / sum;
    float p0 = e0 * inv, p1 = e1 * inv, p2 = e2 * inv, p3 = e3 * inv;

    // gather all 16 probs into registers (owner lane (lane&28)|(s&3), field s>>2)
    float pr[16];
    const int gb = lane & 28;
#pragma unroll
    for (int s = 0; s < 16; s++) {
        float v = (s >> 2) == 0 ? p0 : (s >> 2) == 1 ? p1 : (s >> 2) == 2 ? p2 : p3;
        pr[s] = __shfl_sync(0xffffffffu, v, gb | (s & 3));
    }

    const float*  off = OA + (size_t)row * 384 + h * 32;
    const float*  ref = REF + (size_t)row * 8;
    const half_t* Vb  = V + (size_t)n * LQN * 256 + h * 32 + 8 * co;

    const int   Wt[4]   = {64, 32, 16, 8};
    const int   St[4]   = {0, 4096, 5120, 5376};
    const float invW[4] = {1.f/64.f, 1.f/32.f, 1.f/16.f, 1.f/8.f};

    float a0 = 0.f, a1 = 0.f, a2 = 0.f, a3 = 0.f;
    float a4 = 0.f, a5 = 0.f, a6 = 0.f, a7 = 0.f;
#pragma unroll
    for (int l = 0; l < 4; l++) {
        const int W = Wt[l], H = Wt[l];
        const half_t* Vl = Vb + (size_t)St[l] * 256;
        const float rx = ref[l * 2 + 0], ry = ref[l * 2 + 1];
#pragma unroll
        for (int p = 0; p < 4; p++) {
            const int s = l * 4 + p;
            float ox = off[s * 2 + 0];
            float oy = off[s * 2 + 1];
            float lx = rx + ox * invW[l];
            float ly = ry + oy * invW[l];
            float gx = 2.f * lx - 1.f, gy = 2.f * ly - 1.f;
            float x = (gx + 1.f) * (W * 0.5f) - 0.5f;
            float y = (gy + 1.f) * (H * 0.5f) - 0.5f;
            float x0f = floorf(x), y0f = floorf(y);
            float wx = x - x0f, wy = y - y0f;
            int x0 = (int)x0f, y0 = (int)y0f;
            float a = pr[s];
            bool xv0 = (x0 >= 0)  && (x0 < W);
            bool xv1 = (x0 >= -1) && (x0 < W - 1);
            bool yv0 = (y0 >= 0)  && (y0 < H);
            bool yv1 = (y0 >= -1) && (y0 < H - 1);
            float w00 = (1.f - wx) * (1.f - wy) * a;
            float w10 = wx * (1.f - wy) * a;
            float w01 = (1.f - wx) * wy * a;
            float w11 = wx * wy * a;
            if (xv0 && yv0) {
                uint4 u = *reinterpret_cast<const uint4*>(Vl + (y0 * W + x0) * 256);
                float2 vA = __half22float2(*reinterpret_cast<__half2*>(&u.x));
                float2 vB = __half22float2(*reinterpret_cast<__half2*>(&u.y));
                float2 vC = __half22float2(*reinterpret_cast<__half2*>(&u.z));
                float2 vD = __half22float2(*reinterpret_cast<__half2*>(&u.w));
                a0 += w00 * vA.x; a1 += w00 * vA.y; a2 += w00 * vB.x; a3 += w00 * vB.y;
                a4 += w00 * vC.x; a5 += w00 * vC.y; a6 += w00 * vD.x; a7 += w00 * vD.y;
            }
            if (xv1 && yv0) {
                uint4 u = *reinterpret_cast<const uint4*>(Vl + (y0 * W + x0 + 1) * 256);
                float2 vA = __half22float2(*reinterpret_cast<__half2*>(&u.x));
                float2 vB = __half22float2(*reinterpret_cast<__half2*>(&u.y));
                float2 vC = __half22float2(*reinterpret_cast<__half2*>(&u.z));
                float2 vD = __half22float2(*reinterpret_cast<__half2*>(&u.w));
                a0 += w10 * vA.x; a1 += w10 * vA.y; a2 += w10 * vB.x; a3 += w10 * vB.y;
                a4 += w10 * vC.x; a5 += w10 * vC.y; a6 += w10 * vD.x; a7 += w10 * vD.y;
            }
            if (xv0 && yv1) {
                uint4 u = *reinterpret_cast<const uint4*>(Vl + ((y0 + 1) * W + x0) * 256);
                float2 vA = __half22float2(*reinterpret_cast<__half2*>(&u.x));
                float2 vB = __half22float2(*reinterpret_cast<__half2*>(&u.y));
                float2 vC = __half22float2(*reinterpret_cast<__half2*>(&u.z));
                float2 vD = __half22float2(*reinterpret_cast<__half2*>(&u.w));
                a0 += w01 * vA.x; a1 += w01 * vA.y; a2 += w01 * vB.x; a3 += w01 * vB.y;
                a4 += w01 * vC.x; a5 += w01 * vC.y; a6 += w01 * vD.x; a7 += w01 * vD.y;
            }
            if (xv1 && yv1) {
                uint4 u = *reinterpret_cast<const uint4*>(Vl + ((y0 + 1) * W + x0 + 1) * 256);
                float2 vA = __half22float2(*reinterpret_cast<__half2*>(&u.x));
                float2 vB = __half22float2(*reinterpret_cast<__half2*>(&u.y));
                float2 vC = __half22float2(*reinterpret_cast<__half2*>(&u.z));
                float2 vD = __half22float2(*reinterpret_cast<__half2*>(&u.w));
                a0 += w11 * vA.x; a1 += w11 * vA.y; a2 += w11 * vB.x; a3 += w11 * vB.y;
                a4 += w11 * vC.x; a5 += w11 * vC.y; a6 += w11 * vD.x; a7 += w11 * vD.y;
            }
        }
    }
    half_t* dst = &OUT[(size_t)row * 256 + h * 32 + 8 * co];
    __half2 o0 = __floats2half2_rn(a0, a1);
    __half2 o1 = __floats2half2_rn(a2, a3);
    __half2 o2 = __floats2half2_rn(a4, a5);
    __half2 o3 = __floats2half2_rn(a6, a7);
    uint4 out;
    out.x = *reinterpret_cast<uint32_t*>(&o0);
    out.y = *reinterpret_cast<uint32_t*>(&o1);
    out.z = *reinterpret_cast<uint32_t*>(&o2);
    out.w = *reinterpret_cast<uint32_t*>(&o3);
    *reinterpret_cast<uint4*>(dst) = out;
}

// ---------------- launch ----------------
extern "C" void kernel_launch(void* const* d_in, const int* in_sizes, int n_in,
                              void* d_out, int out_size)
{
    const float* src    = (const float*)d_in[0];
    const float* pos    = (const float*)d_in[1];
    const float* ref    = (const float*)d_in[2];
    const float* w_off  = (const float*)d_in[3];
    const float* b_off  = (const float*)d_in[4];
    const float* w_attn = (const float*)d_in[5];
    const float* b_attn = (const float*)d_in[6];
    const float* w_val  = (const float*)d_in[7];
    const float* b_val  = (const float*)d_in[8];
    const float* w_out  = (const float*)d_in[9];
    const float* b_out  = (const float*)d_in[10];
    const float* g1     = (const float*)d_in[11];
    const float* be1    = (const float*)d_in[12];
    const float* w_ff1  = (const float*)d_in[13];
    const float* b_ff1  = (const float*)d_in[14];
    const float* w_ff2  = (const float*)d_in[15];
    const float* b_ff2  = (const float*)d_in[16];
    const float* g2     = (const float*)d_in[17];
    const float* be2    = (const float*)d_in[18];
    const unsigned char* mask = (const unsigned char*)d_in[19];

    half_t *srcH, *QH, *VH, *ATTH, *XH, *HH, *WvT, *WqaT, *WuT, *W1T, *W2T;
    float *pOA, *pX, *pbqa;
    cudaGetSymbolAddress((void**)&srcH, g_srcH);
    cudaGetSymbolAddress((void**)&QH,   g_QH);
    cudaGetSymbolAddress((void**)&VH,   g_VH);
    cudaGetSymbolAddress((void**)&ATTH, g_ATTH);
    cudaGetSymbolAddress((void**)&XH,   g_XH);
    cudaGetSymbolAddress((void**)&HH,   g_HH);
    cudaGetSymbolAddress((void**)&WvT,  g_WvT);
    cudaGetSymbolAddress((void**)&WqaT, g_WqaT);
    cudaGetSymbolAddress((void**)&WuT,  g_WuT);
    cudaGetSymbolAddress((void**)&W1T,  g_W1T);
    cudaGetSymbolAddress((void**)&W2T,  g_W2T);
    cudaGetSymbolAddress((void**)&pOA,  g_OA);
    cudaGetSymbolAddress((void**)&pX,   g_X);
    cudaGetSymbolAddress((void**)&pbqa, g_bqa);

    cudaFuncSetAttribute(hgemm_k<false, true,  true >, cudaFuncAttributeMaxDynamicSharedMemorySize, SMEM_BYTES);
    cudaFuncSetAttribute(hgemm_k<false, false, false>, cudaFuncAttributeMaxDynamicSharedMemorySize, SMEM_BYTES);
    cudaFuncSetAttribute(hgemm_k<true,  false, true >, cudaFuncAttributeMaxDynamicSharedMemorySize, SMEM_BYTES);
    cudaFuncSetAttribute(hgemm_ln_k<true >, cudaFuncAttributeMaxDynamicSharedMemorySize, LN_SMEM_BYTES);
    cudaFuncSetAttribute(hgemm_ln_k<false>, cudaFuncAttributeMaxDynamicSharedMemorySize, LN_SMEM_BYTES);

    addvec_k<<<RR * CD / 4 / 256, 256>>>(src, pos, srcH, QH);
    prep_k<<<(754048 + 255) / 256, 256>>>(w_val, w_off, w_attn, w_out, w_ff1, w_ff2,
                                          b_off, b_attn, WvT, WqaT, WuT, W1T, W2T, pbqa);

    // value = mask0(src @ w_val + b_val) -> fp16
    hgemm_k<false, true,  true ><<<dim3(340, 2), 256, SMEM_BYTES>>>(
        srcH, WvT, b_val, mask, nullptr, VH, 256, 256);
    // [off | attn logits] = Q @ [w_off | w_attn] + bqa
    hgemm_k<false, false, false><<<dim3(340, 3), 256, SMEM_BYTES>>>(
        QH, WqaT, pbqa, nullptr, pOA, nullptr, 256, 384);
    deform_k<<<RR / 8, 256>>>(VH, pOA, ref, ATTH);
    // X = LN1(src + ATT @ w_out + b_out)  -> pX fp32 + XH fp16
    hgemm_ln_k<true ><<<680, 256, LN_SMEM_BYTES>>>(
        ATTH, WuT, b_out, src, g1, be1, pX, XH, 256);
    // H = relu(X @ w_ff1 + b_ff1) -> fp16
    hgemm_k<true,  false, true ><<<dim3(340, 8), 256, SMEM_BYTES>>>(
        XH, W1T, b_ff1, nullptr, nullptr, HH, 256, 1024);
    // out = LN2(X + H @ w_ff2 + b_ff2)
    hgemm_ln_k<false><<<680, 256, LN_SMEM_BYTES>>>(
        HH, W2T, b_ff2, pX, g2, be2, (float*)d_out, nullptr, 1024);
}

// round 15
// speedup vs baseline: 6.1275x; 1.0417x over previous
#include <cuda_runtime.h>
#include <cuda_fp16.h>
#include <cstdint>

#define NB 8
#define LQN 5440
#define CD 256
#define RR 43520          // NB*LQN
#define DFFN 1024

typedef __half half_t;

// ---------------- scratch (static device arrays; no allocation) ----------------
__device__ half_t g_srcH[RR * CD];
__device__ half_t g_QH  [RR * CD];
__device__ half_t g_VH  [RR * CD];
__device__ half_t g_ATTH[RR * CD];
__device__ half_t g_XH  [RR * CD];
__device__ half_t g_HH  [RR * DFFN];
__device__ half_t g_OAh [RR * 384];          // off (256) ++ logits (128), fp16
// transposed fp16 weights [N][K]
__device__ half_t g_WvT [CD * CD];
__device__ half_t g_WqaT[384 * CD];
__device__ half_t g_WuT [CD * CD];
__device__ half_t g_W1T [DFFN * CD];
__device__ half_t g_W2T [CD * DFFN];
__device__ float  g_bqa [384];
// fp32 intermediates
__device__ float g_X  [RR * CD];             // LN1 output fp32 (residual for LN2)

// ---------------- PTX helpers ----------------
__device__ __forceinline__ void mma_fp16(float d[4], const uint32_t a[4],
                                         const uint32_t b[2]) {
    asm volatile(
        "mma.sync.aligned.m16n8k16.row.col.f32.f16.f16.f32 "
        "{%0,%1,%2,%3}, {%4,%5,%6,%7}, {%8,%9}, {%0,%1,%2,%3};\n"
        : "+f"(d[0]), "+f"(d[1]), "+f"(d[2]), "+f"(d[3])
        : "r"(a[0]), "r"(a[1]), "r"(a[2]), "r"(a[3]),
          "r"(b[0]), "r"(b[1]));
}
__device__ __forceinline__ void ldsm4(uint32_t& r0, uint32_t& r1, uint32_t& r2,
                                      uint32_t& r3, uint32_t addr) {
    asm volatile("ldmatrix.sync.aligned.m8n8.x4.shared.b16 {%0,%1,%2,%3}, [%4];"
                 : "=r"(r0), "=r"(r1), "=r"(r2), "=r"(r3) : "r"(addr));
}
__device__ __forceinline__ void cp_async16(void* s, const void* g) {
    uint32_t sa = (uint32_t)__cvta_generic_to_shared(s);
    asm volatile("cp.async.cg.shared.global [%0], [%1], 16;\n" :: "r"(sa), "l"(g));
}
__device__ __forceinline__ void cp_commit() { asm volatile("cp.async.commit_group;\n"); }
template<int N> __device__ __forceinline__ void cp_wait() {
    asm volatile("cp.async.wait_group %0;\n" :: "n"(N));
}

#define HS 72                           // half stride (64 + 8 pad)

// ================= generic FP16 GEMM (BM=BN=128, 3-stage) =================
#define TILE_HALFS (128 * HS)
#define STAGE_HALFS (2 * TILE_HALFS)
#define TILE_BYTES (TILE_HALFS * 2)
#define STAGE_BYTES (STAGE_HALFS * 2)
#define SMEM_BYTES (3 * STAGE_BYTES)    // 110,592 B

// ---- fused value + QA GEMM: grid (340, 5). y<2 -> value, y>=2 -> off|attn ----
__global__ __launch_bounds__(256, 2)
void vqa_k(const half_t* __restrict__ srcA, const half_t* __restrict__ QA,
           const half_t* __restrict__ WvT, const half_t* __restrict__ WqaT,
           const float* __restrict__ b_val, const float* __restrict__ bqa,
           const unsigned char* __restrict__ mask,
           half_t* __restrict__ VH, half_t* __restrict__ OAH)
{
    extern __shared__ half_t sm[];

    const int tid  = threadIdx.x;
    const int brow = blockIdx.x * 128;
    const int y    = blockIdx.y;
    const bool isV = y < 2;
    const half_t* A   = isV ? srcA : QA;
    const half_t* B   = isV ? WvT : WqaT;
    const float* bias = isV ? b_val : bqa;
    half_t* Out       = isV ? VH : OAH;
    const int Nout    = isV ? 256 : 384;
    const int bcol    = (isV ? y : (y - 2)) * 128;

    const int lane = tid & 31;
    const int wid  = tid >> 5;
    const int wm   = (wid >> 2) * 64;
    const int wn   = (wid & 3) * 32;
    const int gr   = lane >> 2;
    const int gc   = lane & 3;

    const uint32_t smemU = (uint32_t)__cvta_generic_to_shared(sm);
    const uint32_t aOff = ((wm + (lane & 7) + ((lane >> 3) & 1) * 8) * HS
                           + ((lane >> 4) & 1) * 8) * 2;
    const uint32_t bOff = ((wn + (lane & 7) + ((lane >> 4) & 1) * 8) * HS
                           + ((lane >> 3) & 1) * 8) * 2;

    float acc[4][4][4];
#pragma unroll
    for (int i = 0; i < 4; i++)
#pragma unroll
        for (int j = 0; j < 4; j++)
#pragma unroll
            for (int t = 0; t < 4; t++) acc[i][j][t] = 0.f;

    const int K = 256, nch = 4;

    auto issue = [&](int chunk, int stg) {
        const int k0 = chunk << 6;
        half_t* As = sm + stg * STAGE_HALFS;
        half_t* Bs = As + TILE_HALFS;
#pragma unroll
        for (int i = 0; i < 4; i++) {
            int t = tid + i * 256;
            int r = t >> 3, q = (t & 7) << 3;
            cp_async16(As + r * HS + q, A + (size_t)(brow + r) * K + k0 + q);
        }
#pragma unroll
        for (int i = 0; i < 4; i++) {
            int t = tid + i * 256;
            int r = t >> 3, q = (t & 7) << 3;
            cp_async16(Bs + r * HS + q, B + (size_t)(bcol + r) * K + k0 + q);
        }
        cp_commit();
    };

    issue(0, 0);
    issue(1, 1);

    for (int c = 0; c < nch; c++) {
        const int cur = c % 3;
        if (c + 2 < nch) issue(c + 2, (c + 2) % 3);
        else cp_commit();
        cp_wait<2>();
        __syncthreads();

        const uint32_t aBase = smemU + cur * STAGE_BYTES + aOff;
        const uint32_t bBase = smemU + cur * STAGE_BYTES + TILE_BYTES + bOff;
#pragma unroll
        for (int kk = 0; kk < 4; kk++) {
            uint32_t af[4][4], bf[4][2];
#pragma unroll
            for (int mt = 0; mt < 4; mt++)
                ldsm4(af[mt][0], af[mt][1], af[mt][2], af[mt][3],
                      aBase + mt * (16 * HS * 2) + kk * 32);
#pragma unroll
            for (int ntp = 0; ntp < 2; ntp++)
                ldsm4(bf[2 * ntp][0], bf[2 * ntp][1], bf[2 * ntp + 1][0], bf[2 * ntp + 1][1],
                      bBase + ntp * (16 * HS * 2) + kk * 32);
#pragma unroll
            for (int mt = 0; mt < 4; mt++)
#pragma unroll
                for (int nt = 0; nt < 4; nt++)
                    mma_fp16(acc[mt][nt], af[mt], bf[nt]);
        }
        __syncthreads();
    }

#pragma unroll
    for (int mt = 0; mt < 4; mt++) {
        int r0 = brow + wm + mt * 16 + gr;
        int r1 = r0 + 8;
        float ms0 = (isV && mask[r0]) ? 0.f : 1.f;
        float ms1 = (isV && mask[r1]) ? 0.f : 1.f;
#pragma unroll
        for (int nt = 0; nt < 4; nt++) {
            int col = bcol + wn + nt * 8 + gc * 2;
            float2 bi = *reinterpret_cast<const float2*>(&bias[col]);
            float v0 = (acc[mt][nt][0] + bi.x) * ms0;
            float v1 = (acc[mt][nt][1] + bi.y) * ms0;
            float v2 = (acc[mt][nt][2] + bi.x) * ms1;
            float v3 = (acc[mt][nt][3] + bi.y) * ms1;
            *reinterpret_cast<__half2*>(&Out[(size_t)r0 * Nout + col]) = __floats2half2_rn(v0, v1);
            *reinterpret_cast<__half2*>(&Out[(size_t)r1 * Nout + col]) = __floats2half2_rn(v2, v3);
        }
    }
}

// ---- plain GEMM (used for ff1: RELU, half out) ----
template<bool RELU, bool MASK, bool HALF_OUT>
__global__ __launch_bounds__(256, 2)
void hgemm_k(const half_t* __restrict__ A, const half_t* __restrict__ B,
             const float* __restrict__ bias, const unsigned char* __restrict__ mask,
             float* __restrict__ Cf, half_t* __restrict__ Ch, int K, int Nout)
{
    extern __shared__ half_t sm[];

    const int tid  = threadIdx.x;
    const int brow = blockIdx.x * 128;
    const int bcol = blockIdx.y * 128;

    const int lane = tid & 31;
    const int wid  = tid >> 5;
    const int wm   = (wid >> 2) * 64;
    const int wn   = (wid & 3) * 32;
    const int gr   = lane >> 2;
    const int gc   = lane & 3;

    const uint32_t smemU = (uint32_t)__cvta_generic_to_shared(sm);
    const uint32_t aOff = ((wm + (lane & 7) + ((lane >> 3) & 1) * 8) * HS
                           + ((lane >> 4) & 1) * 8) * 2;
    const uint32_t bOff = ((wn + (lane & 7) + ((lane >> 4) & 1) * 8) * HS
                           + ((lane >> 3) & 1) * 8) * 2;

    float acc[4][4][4];
#pragma unroll
    for (int i = 0; i < 4; i++)
#pragma unroll
        for (int j = 0; j < 4; j++)
#pragma unroll
            for (int t = 0; t < 4; t++) acc[i][j][t] = 0.f;

    const int nch = K >> 6;

    auto issue = [&](int chunk, int stg) {
        const int k0 = chunk << 6;
        half_t* As = sm + stg * STAGE_HALFS;
        half_t* Bs = As + TILE_HALFS;
#pragma unroll
        for (int i = 0; i < 4; i++) {
            int t = tid + i * 256;
            int r = t >> 3, q = (t & 7) << 3;
            cp_async16(As + r * HS + q, A + (size_t)(brow + r) * K + k0 + q);
        }
#pragma unroll
        for (int i = 0; i < 4; i++) {
            int t = tid + i * 256;
            int r = t >> 3, q = (t & 7) << 3;
            cp_async16(Bs + r * HS + q, B + (size_t)(bcol + r) * K + k0 + q);
        }
        cp_commit();
    };

    issue(0, 0);
    if (nch > 1) issue(1, 1);
    else cp_commit();

    for (int c = 0; c < nch; c++) {
        const int cur = c % 3;
        if (c + 2 < nch) issue(c + 2, (c + 2) % 3);
        else cp_commit();
        cp_wait<2>();
        __syncthreads();

        const uint32_t aBase = smemU + cur * STAGE_BYTES + aOff;
        const uint32_t bBase = smemU + cur * STAGE_BYTES + TILE_BYTES + bOff;
#pragma unroll
        for (int kk = 0; kk < 4; kk++) {
            uint32_t af[4][4], bf[4][2];
#pragma unroll
            for (int mt = 0; mt < 4; mt++)
                ldsm4(af[mt][0], af[mt][1], af[mt][2], af[mt][3],
                      aBase + mt * (16 * HS * 2) + kk * 32);
#pragma unroll
            for (int ntp = 0; ntp < 2; ntp++)
                ldsm4(bf[2 * ntp][0], bf[2 * ntp][1], bf[2 * ntp + 1][0], bf[2 * ntp + 1][1],
                      bBase + ntp * (16 * HS * 2) + kk * 32);
#pragma unroll
            for (int mt = 0; mt < 4; mt++)
#pragma unroll
                for (int nt = 0; nt < 4; nt++)
                    mma_fp16(acc[mt][nt], af[mt], bf[nt]);
        }
        __syncthreads();
    }

#pragma unroll
    for (int mt = 0; mt < 4; mt++) {
        int r0 = brow + wm + mt * 16 + gr;
        int r1 = r0 + 8;
        float ms0 = 1.f, ms1 = 1.f;
        if (MASK) { ms0 = mask[r0] ? 0.f : 1.f; ms1 = mask[r1] ? 0.f : 1.f; }
#pragma unroll
        for (int nt = 0; nt < 4; nt++) {
            int col = bcol + wn + nt * 8 + gc * 2;
            float2 bi = *reinterpret_cast<const float2*>(&bias[col]);
            float v0 = acc[mt][nt][0] + bi.x;
            float v1 = acc[mt][nt][1] + bi.y;
            float v2 = acc[mt][nt][2] + bi.x;
            float v3 = acc[mt][nt][3] + bi.y;
            if (MASK) { v0 *= ms0; v1 *= ms0; v2 *= ms1; v3 *= ms1; }
            if (RELU) {
                v0 = fmaxf(v0, 0.f); v1 = fmaxf(v1, 0.f);
                v2 = fmaxf(v2, 0.f); v3 = fmaxf(v3, 0.f);
            }
            if (HALF_OUT) {
                *reinterpret_cast<__half2*>(&Ch[(size_t)r0 * Nout + col]) = __floats2half2_rn(v0, v1);
                *reinterpret_cast<__half2*>(&Ch[(size_t)r1 * Nout + col]) = __floats2half2_rn(v2, v3);
            } else {
                *reinterpret_cast<float2*>(&Cf[(size_t)r0 * Nout + col]) = make_float2(v0, v1);
                *reinterpret_cast<float2*>(&Cf[(size_t)r1 * Nout + col]) = make_float2(v2, v3);
            }
        }
    }
}

// ============ fused GEMM + residual + LayerNorm (BM=64, BN=256, 2-stage) ============
#define LN_A_HALFS (64 * HS)
#define LN_B_HALFS (256 * HS)
#define LN_STAGE_HALFS (LN_A_HALFS + LN_B_HALFS)
#define LN_RED_FLOATS (2 * 64 * 8 + 64 * 2)
#define LN_SMEM_BYTES (2 * LN_STAGE_HALFS * 2 + LN_RED_FLOATS * 4)

template<bool WRITE_H>
__global__ __launch_bounds__(256, 2)
void hgemm_ln_k(const half_t* __restrict__ A, const half_t* __restrict__ B,
                const float* __restrict__ bias, const float* __restrict__ Res,
                const float* __restrict__ gam, const float* __restrict__ bet,
                float* __restrict__ Of, half_t* __restrict__ Oh, int K)
{
    extern __shared__ half_t sm[];
    float* red  = reinterpret_cast<float*>(sm + 2 * LN_STAGE_HALFS);
    float* stat = red + 2 * 64 * 8;

    const int tid  = threadIdx.x;
    const int brow = blockIdx.x * 64;

    const int lane = tid & 31;
    const int wid  = tid >> 5;
    const int wn   = wid * 32;
    const int gr   = lane >> 2;
    const int gc   = lane & 3;

    const uint32_t smemU = (uint32_t)__cvta_generic_to_shared(sm);
    const uint32_t aOff = (((lane & 7) + ((lane >> 3) & 1) * 8) * HS
                           + ((lane >> 4) & 1) * 8) * 2;
    const uint32_t bOff = ((wn + (lane & 7) + ((lane >> 4) & 1) * 8) * HS
                           + ((lane >> 3) & 1) * 8) * 2;

    float acc[4][4][4];
#pragma unroll
    for (int i = 0; i < 4; i++)
#pragma unroll
        for (int j = 0; j < 4; j++)
#pragma unroll
            for (int t = 0; t < 4; t++) acc[i][j][t] = 0.f;

    const int nch = K >> 6;

    auto issue = [&](int chunk, int stg) {
        const int k0 = chunk << 6;
        half_t* As = sm + stg * LN_STAGE_HALFS;
        half_t* Bs = As + LN_A_HALFS;
#pragma unroll
        for (int i = 0; i < 2; i++) {
            int t = tid + i * 256;
            int r = t >> 3, q = (t & 7) << 3;
            cp_async16(As + r * HS + q, A + (size_t)(brow + r) * K + k0 + q);
        }
#pragma unroll
        for (int i = 0; i < 8; i++) {
            int t = tid + i * 256;
            int r = t >> 3, q = (t & 7) << 3;
            cp_async16(Bs + r * HS + q, B + (size_t)r * K + k0 + q);
        }
        cp_commit();
    };

    issue(0, 0);

    for (int c = 0; c < nch; c++) {
        const int cur = c & 1;
        if (c + 1 < nch) { issue(c + 1, cur ^ 1); cp_wait<1>(); }
        else cp_wait<0>();
        __syncthreads();

        const uint32_t aBase = smemU + cur * (LN_STAGE_HALFS * 2) + aOff;
        const uint32_t bBase = smemU + cur * (LN_STAGE_HALFS * 2) + LN_A_HALFS * 2 + bOff;
#pragma unroll
        for (int kk = 0; kk < 4; kk++) {
            uint32_t af[4][4], bf[4][2];
#pragma unroll
            for (int mt = 0; mt < 4; mt++)
                ldsm4(af[mt][0], af[mt][1], af[mt][2], af[mt][3],
                      aBase + mt * (16 * HS * 2) + kk * 32);
#pragma unroll
            for (int ntp = 0; ntp < 2; ntp++)
                ldsm4(bf[2 * ntp][0], bf[2 * ntp][1], bf[2 * ntp + 1][0], bf[2 * ntp + 1][1],
                      bBase + ntp * (16 * HS * 2) + kk * 32);
#pragma unroll
            for (int mt = 0; mt < 4; mt++)
#pragma unroll
                for (int nt = 0; nt < 4; nt++)
                    mma_fp16(acc[mt][nt], af[mt], bf[nt]);
        }
        __syncthreads();
    }

#pragma unroll
    for (int mt = 0; mt < 4; mt++) {
        int r0 = mt * 16 + gr, r1 = r0 + 8;
        float s0 = 0.f, q0 = 0.f, s1 = 0.f, q1 = 0.f;
#pragma unroll
        for (int nt = 0; nt < 4; nt++) {
            int col = wn + nt * 8 + gc * 2;
            float2 bi = *reinterpret_cast<const float2*>(&bias[col]);
            float2 e0 = *reinterpret_cast<const float2*>(&Res[(size_t)(brow + r0) * 256 + col]);
            float2 e1 = *reinterpret_cast<const float2*>(&Res[(size_t)(brow + r1) * 256 + col]);
            float v0 = acc[mt][nt][0] + bi.x + e0.x;
            float v1 = acc[mt][nt][1] + bi.y + e0.y;
            float v2 = acc[mt][nt][2] + bi.x + e1.x;
            float v3 = acc[mt][nt][3] + bi.y + e1.y;
            acc[mt][nt][0] = v0; acc[mt][nt][1] = v1;
            acc[mt][nt][2] = v2; acc[mt][nt][3] = v3;
            s0 += v0 + v1; q0 += v0 * v0 + v1 * v1;
            s1 += v2 + v3; q1 += v2 * v2 + v3 * v3;
        }
#pragma unroll
        for (int o = 1; o <= 2; o <<= 1) {
            s0 += __shfl_xor_sync(0xffffffffu, s0, o);
            q0 += __shfl_xor_sync(0xffffffffu, q0, o);
            s1 += __shfl_xor_sync(0xffffffffu, s1, o);
            q1 += __shfl_xor_sync(0xffffffffu, q1, o);
        }
        if (gc == 0) {
            red[r0 * 8 + wid] = s0;  red[512 + r0 * 8 + wid] = q0;
            red[r1 * 8 + wid] = s1;  red[512 + r1 * 8 + wid] = q1;
        }
    }
    __syncthreads();
    if (tid < 64) {
        float s = 0.f, q = 0.f;
#pragma unroll
        for (int w = 0; w < 8; w++) { s += red[tid * 8 + w]; q += red[512 + tid * 8 + w]; }
        float m = s * (1.f / 256.f);
        float var = q * (1.f / 256.f) - m * m;
        stat[tid * 2 + 0] = m;
        stat[tid * 2 + 1] = rsqrtf(var + 1e-5f);
    }
    __syncthreads();

#pragma unroll
    for (int mt = 0; mt < 4; mt++) {
        int r0 = mt * 16 + gr, r1 = r0 + 8;
        float m0 = stat[r0 * 2], iv0 = stat[r0 * 2 + 1];
        float m1 = stat[r1 * 2], iv1 = stat[r1 * 2 + 1];
#pragma unroll
        for (int nt = 0; nt < 4; nt++) {
            int col = wn + nt * 8 + gc * 2;
            float2 gm = *reinterpret_cast<const float2*>(&gam[col]);
            float2 bt = *reinterpret_cast<const float2*>(&bet[col]);
            float o0 = (acc[mt][nt][0] - m0) * iv0 * gm.x + bt.x;
            float o1 = (acc[mt][nt][1] - m0) * iv0 * gm.y + bt.y;
            float o2 = (acc[mt][nt][2] - m1) * iv1 * gm.x + bt.x;
            float o3 = (acc[mt][nt][3] - m1) * iv1 * gm.y + bt.y;
            *reinterpret_cast<float2*>(&Of[(size_t)(brow + r0) * 256 + col]) = make_float2(o0, o1);
            *reinterpret_cast<float2*>(&Of[(size_t)(brow + r1) * 256 + col]) = make_float2(o2, o3);
            if (WRITE_H) {
                *reinterpret_cast<__half2*>(&Oh[(size_t)(brow + r0) * 256 + col]) = __floats2half2_rn(o0, o1);
                *reinterpret_cast<__half2*>(&Oh[(size_t)(brow + r1) * 256 + col]) = __floats2half2_rn(o2, o3);
            }
        }
    }
}

// ---------------- merged prep: all weight transposes + bias concat ----------------
__global__ void prep_k(const float* __restrict__ w_val, const float* __restrict__ w_off,
                       const float* __restrict__ w_attn, const float* __restrict__ w_out,
                       const float* __restrict__ w_ff1, const float* __restrict__ w_ff2,
                       const float* __restrict__ b_off, const float* __restrict__ b_attn,
                       half_t* __restrict__ WvT, half_t* __restrict__ WqaT,
                       half_t* __restrict__ WuT, half_t* __restrict__ W1T,
                       half_t* __restrict__ W2T, float* __restrict__ bqa)
{
    int idx = blockIdx.x * blockDim.x + threadIdx.x;
    auto tr = [](const float* w, half_t* o, int i, int K, int N) {
        int n = i / K, k = i % K;
        o[i] = __float2half_rn(w[(size_t)k * N + n]);
    };
    if (idx < 65536)                { tr(w_val,  WvT,              idx, 256,  256);  return; }
    if ((idx -= 65536) < 65536)     { tr(w_off,  WqaT,             idx, 256,  256);  return; }
    if ((idx -= 65536) < 32768)     { tr(w_attn, WqaT + 256 * CD,  idx, 256,  128);  return; }
    if ((idx -= 32768) < 65536)     { tr(w_out,  WuT,              idx, 256,  256);  return; }
    if ((idx -= 65536) < 262144)    { tr(w_ff1,  W1T,              idx, 256,  1024); return; }
    if ((idx -= 262144) < 262144)   { tr(w_ff2,  W2T,              idx, 1024, 256);  return; }
    idx -= 262144;
    if (idx < 256)      bqa[idx] = b_off[idx];
    else if (idx < 384) bqa[idx] = b_attn[idx - 256];
}

// ---------------- addvec: srcH = h(src); QH = h(src+pos) ----------------
__global__ void addvec_k(const float* __restrict__ a, const float* __restrict__ b,
                         half_t* __restrict__ sh, half_t* __restrict__ qh)
{
    int i = blockIdx.x * blockDim.x + threadIdx.x;
    float4 x = reinterpret_cast<const float4*>(a)[i];
    float4 y = reinterpret_cast<const float4*>(b)[i];
    __half2 s0 = __floats2half2_rn(x.x, x.y);
    __half2 s1 = __floats2half2_rn(x.z, x.w);
    __half2 q0 = __floats2half2_rn(x.x + y.x, x.y + y.y);
    __half2 q1 = __floats2half2_rn(x.z + y.z, x.w + y.w);
    reinterpret_cast<__half2*>(sh)[i * 2 + 0] = s0;
    reinterpret_cast<__half2*>(sh)[i * 2 + 1] = s1;
    reinterpret_cast<__half2*>(qh)[i * 2 + 0] = q0;
    reinterpret_cast<__half2*>(qh)[i * 2 + 1] = q1;
}

// ---------------- deformable sampling: 8 heads/warp, 16B gathers, fp16 OA ----------
__global__ void deform_k(const half_t* __restrict__ V, const half_t* __restrict__ OA,
                         const float* __restrict__ REF, half_t* __restrict__ OUT)
{
    const int tid  = threadIdx.x;
    const int w    = tid >> 5;
    const int lane = tid & 31;
    const int row  = blockIdx.x * 8 + w;
    const int h    = lane >> 2;
    const int co   = lane & 3;
    const int n    = row / LQN;

    const half_t* lgp = OA + (size_t)row * 384 + 256 + h * 16;
    float l0 = __half2float(lgp[co]),     l1 = __half2float(lgp[co + 4]);
    float l2 = __half2float(lgp[co + 8]), l3 = __half2float(lgp[co + 12]);
    float mx = fmaxf(fmaxf(l0, l1), fmaxf(l2, l3));
#pragma unroll
    for (int o = 2; o; o >>= 1) mx = fmaxf(mx, __shfl_xor_sync(0xffffffffu, mx, o));
    float e0 = expf(l0 - mx), e1 = expf(l1 - mx), e2 = expf(l2 - mx), e3 = expf(l3 - mx);
    float sum = e0 + e1 + e2 + e3;
#pragma unroll
    for (int o = 2; o; o >>= 1) sum += __shfl_xor_sync(0xffffffffu, sum, o);
    float inv = 1.f / sum;
    float p0 = e0 * inv, p1 = e1 * inv, p2 = e2 * inv, p3 = e3 * inv;

    float pr[16];
    const int gb = lane & 28;
#pragma unroll
    for (int s = 0; s < 16; s++) {
        float v = (s >> 2) == 0 ? p0 : (s >> 2) == 1 ? p1 : (s >> 2) == 2 ? p2 : p3;
        pr[s] = __shfl_sync(0xffffffffu, v, gb | (s & 3));
    }

    const half_t* off = OA + (size_t)row * 384 + h * 32;
    const float*  ref = REF + (size_t)row * 8;
    const half_t* Vb  = V + (size_t)n * LQN * 256 + h * 32 + 8 * co;

    const int   Wt[4]   = {64, 32, 16, 8};
    const int   St[4]   = {0, 4096, 5120, 5376};
    const float invW[4] = {1.f/64.f, 1.f/32.f, 1.f/16.f, 1.f/8.f};

    float a0 = 0.f, a1 = 0.f, a2 = 0.f, a3 = 0.f;
    float a4 = 0.f, a5 = 0.f, a6 = 0.f, a7 = 0.f;
#pragma unroll
    for (int l = 0; l < 4; l++) {
        const int W = Wt[l], H = Wt[l];
        const half_t* Vl = Vb + (size_t)St[l] * 256;
        const float rx = ref[l * 2 + 0], ry = ref[l * 2 + 1];
#pragma unroll
        for (int p = 0; p < 4; p++) {
            const int s = l * 4 + p;
            float ox = __half2float(off[s * 2 + 0]);
            float oy = __half2float(off[s * 2 + 1]);
            float lx = rx + ox * invW[l];
            float ly = ry + oy * invW[l];
            float gx = 2.f * lx - 1.f, gy = 2.f * ly - 1.f;
            float x = (gx + 1.f) * (W * 0.5f) - 0.5f;
            float y = (gy + 1.f) * (H * 0.5f) - 0.5f;
            float x0f = floorf(x), y0f = floorf(y);
            float wx = x - x0f, wy = y - y0f;
            int x0 = (int)x0f, y0 = (int)y0f;
            float a = pr[s];
            bool xv0 = (x0 >= 0)  && (x0 < W);
            bool xv1 = (x0 >= -1) && (x0 < W - 1);
            bool yv0 = (y0 >= 0)  && (y0 < H);
            bool yv1 = (y0 >= -1) && (y0 < H - 1);
            float w00 = (1.f - wx) * (1.f - wy) * a;
            float w10 = wx * (1.f - wy) * a;
            float w01 = (1.f - wx) * wy * a;
            float w11 = wx * wy * a;
            if (xv0 && yv0) {
                uint4 u = *reinterpret_cast<const uint4*>(Vl + (y0 * W + x0) * 256);
                float2 vA = __half22float2(*reinterpret_cast<__half2*>(&u.x));
                float2 vB = __half22float2(*reinterpret_cast<__half2*>(&u.y));
                float2 vC = __half22float2(*reinterpret_cast<__half2*>(&u.z));
                float2 vD = __half22float2(*reinterpret_cast<__half2*>(&u.w));
                a0 += w00 * vA.x; a1 += w00 * vA.y; a2 += w00 * vB.x; a3 += w00 * vB.y;
                a4 += w00 * vC.x; a5 += w00 * vC.y; a6 += w00 * vD.x; a7 += w00 * vD.y;
            }
            if (xv1 && yv0) {
                uint4 u = *reinterpret_cast<const uint4*>(Vl + (y0 * W + x0 + 1) * 256);
                float2 vA = __half22float2(*reinterpret_cast<__half2*>(&u.x));
                float2 vB = __half22float2(*reinterpret_cast<__half2*>(&u.y));
                float2 vC = __half22float2(*reinterpret_cast<__half2*>(&u.z));
                float2 vD = __half22float2(*reinterpret_cast<__half2*>(&u.w));
                a0 += w10 * vA.x; a1 += w10 * vA.y; a2 += w10 * vB.x; a3 += w10 * vB.y;
                a4 += w10 * vC.x; a5 += w10 * vC.y; a6 += w10 * vD.x; a7 += w10 * vD.y;
            }
            if (xv0 && yv1) {
                uint4 u = *reinterpret_cast<const uint4*>(Vl + ((y0 + 1) * W + x0) * 256);
                float2 vA = __half22float2(*reinterpret_cast<__half2*>(&u.x));
                float2 vB = __half22float2(*reinterpret_cast<__half2*>(&u.y));
                float2 vC = __half22float2(*reinterpret_cast<__half2*>(&u.z));
                float2 vD = __half22float2(*reinterpret_cast<__half2*>(&u.w));
                a0 += w01 * vA.x; a1 += w01 * vA.y; a2 += w01 * vB.x; a3 += w01 * vB.y;
                a4 += w01 * vC.x; a5 += w01 * vC.y; a6 += w01 * vD.x; a7 += w01 * vD.y;
            }
            if (xv1 && yv1) {
                uint4 u = *reinterpret_cast<const uint4*>(Vl + ((y0 + 1) * W + x0 + 1) * 256);
                float2 vA = __half22float2(*reinterpret_cast<__half2*>(&u.x));
                float2 vB = __half22float2(*reinterpret_cast<__half2*>(&u.y));
                float2 vC = __half22float2(*reinterpret_cast<__half2*>(&u.z));
                float2 vD = __half22float2(*reinterpret_cast<__half2*>(&u.w));
                a0 += w11 * vA.x; a1 += w11 * vA.y; a2 += w11 * vB.x; a3 += w11 * vB.y;
                a4 += w11 * vC.x; a5 += w11 * vC.y; a6 += w11 * vD.x; a7 += w11 * vD.y;
            }
        }
    }
    half_t* dst = &OUT[(size_t)row * 256 + h * 32 + 8 * co];
    __half2 o0 = __floats2half2_rn(a0, a1);
    __half2 o1 = __floats2half2_rn(a2, a3);
    __half2 o2 = __floats2half2_rn(a4, a5);
    __half2 o3 = __floats2half2_rn(a6, a7);
    uint4 out;
    out.x = *reinterpret_cast<uint32_t*>(&o0);
    out.y = *reinterpret_cast<uint32_t*>(&o1);
    out.z = *reinterpret_cast<uint32_t*>(&o2);
    out.w = *reinterpret_cast<uint32_t*>(&o3);
    *reinterpret_cast<uint4*>(dst) = out;
}

// ---------------- launch ----------------
extern "C" void kernel_launch(void* const* d_in, const int* in_sizes, int n_in,
                              void* d_out, int out_size)
{
    const float* src    = (const float*)d_in[0];
    const float* pos    = (const float*)d_in[1];
    const float* ref    = (const float*)d_in[2];
    const float* w_off  = (const float*)d_in[3];
    const float* b_off  = (const float*)d_in[4];
    const float* w_attn = (const float*)d_in[5];
    const float* b_attn = (const float*)d_in[6];
    const float* w_val  = (const float*)d_in[7];
    const float* b_val  = (const float*)d_in[8];
    const float* w_out  = (const float*)d_in[9];
    const float* b_out  = (const float*)d_in[10];
    const float* g1     = (const float*)d_in[11];
    const float* be1    = (const float*)d_in[12];
    const float* w_ff1  = (const float*)d_in[13];
    const float* b_ff1  = (const float*)d_in[14];
    const float* w_ff2  = (const float*)d_in[15];
    const float* b_ff2  = (const float*)d_in[16];
    const float* g2     = (const float*)d_in[17];
    const float* be2    = (const float*)d_in[18];
    const unsigned char* mask = (const unsigned char*)d_in[19];

    half_t *srcH, *QH, *VH, *ATTH, *XH, *HH, *OAH, *WvT, *WqaT, *WuT, *W1T, *W2T;
    float *pX, *pbqa;
    cudaGetSymbolAddress((void**)&srcH, g_srcH);
    cudaGetSymbolAddress((void**)&QH,   g_QH);
    cudaGetSymbolAddress((void**)&VH,   g_VH);
    cudaGetSymbolAddress((void**)&ATTH, g_ATTH);
    cudaGetSymbolAddress((void**)&XH,   g_XH);
    cudaGetSymbolAddress((void**)&HH,   g_HH);
    cudaGetSymbolAddress((void**)&OAH,  g_OAh);
    cudaGetSymbolAddress((void**)&WvT,  g_WvT);
    cudaGetSymbolAddress((void**)&WqaT, g_WqaT);
    cudaGetSymbolAddress((void**)&WuT,  g_WuT);
    cudaGetSymbolAddress((void**)&W1T,  g_W1T);
    cudaGetSymbolAddress((void**)&W2T,  g_W2T);
    cudaGetSymbolAddress((void**)&pX,   g_X);
    cudaGetSymbolAddress((void**)&pbqa, g_bqa);

    cudaFuncSetAttribute(vqa_k, cudaFuncAttributeMaxDynamicSharedMemorySize, SMEM_BYTES);
    cudaFuncSetAttribute(hgemm_k<true,  false, true >, cudaFuncAttributeMaxDynamicSharedMemorySize, SMEM_BYTES);
    cudaFuncSetAttribute(hgemm_ln_k<true >, cudaFuncAttributeMaxDynamicSharedMemorySize, LN_SMEM_BYTES);
    cudaFuncSetAttribute(hgemm_ln_k<false>, cudaFuncAttributeMaxDynamicSharedMemorySize, LN_SMEM_BYTES);

    addvec_k<<<RR * CD / 4 / 256, 256>>>(src, pos, srcH, QH);
    prep_k<<<(754048 + 255) / 256, 256>>>(w_val, w_off, w_attn, w_out, w_ff1, w_ff2,
                                          b_off, b_attn, WvT, WqaT, WuT, W1T, W2T, pbqa);

    // fused: value (y<2) + [off|attn] (y>=2), both fp16 out
    vqa_k<<<dim3(340, 5), 256, SMEM_BYTES>>>(
        srcH, QH, WvT, WqaT, b_val, pbqa, mask, VH, OAH);
    deform_k<<<RR / 8, 256>>>(VH, OAH, ref, ATTH);
    // X = LN1(src + ATT @ w_out + b_out)  -> pX fp32 + XH fp16
    hgemm_ln_k<true ><<<680, 256, LN_SMEM_BYTES>>>(
        ATTH, WuT, b_out, src, g1, be1, pX, XH, 256);
    // H = relu(X @ w_ff1 + b_ff1) -> fp16
    hgemm_k<true,  false, true ><<<dim3(340, 8), 256, SMEM_BYTES>>>(
        XH, W1T, b_ff1, nullptr, nullptr, HH, 256, 1024);
    // out = LN2(X + H @ w_ff2 + b_ff2)
    hgemm_ln_k<false><<<680, 256, LN_SMEM_BYTES>>>(
        HH, W2T, b_ff2, pX, g2, be2, (float*)d_out, nullptr, 1024);
}

// round 16
// speedup vs baseline: 6.3187x; 1.0312x over previous
#include <cuda_runtime.h>
#include <cuda_fp16.h>
#include <cstdint>

#define NB 8
#define LQN 5440
#define CD 256
#define RR 43520          // NB*LQN
#define DFFN 1024

typedef __half half_t;

// ---------------- scratch (static device arrays; no allocation) ----------------
__device__ half_t g_srcH[RR * CD];
__device__ half_t g_QH  [RR * CD];
__device__ half_t g_VH  [RR * CD];
__device__ half_t g_ATTH[RR * CD];
__device__ half_t g_XH  [RR * CD];
__device__ half_t g_HH  [RR * DFFN];
__device__ half_t g_OAh [RR * 384];          // off (256) ++ logits (128), fp16
// transposed fp16 weights [N][K]
__device__ half_t g_WvT [CD * CD];
__device__ half_t g_WqaT[384 * CD];
__device__ half_t g_WuT [CD * CD];
__device__ half_t g_W1T [DFFN * CD];
__device__ half_t g_W2T [CD * DFFN];
__device__ float  g_bqa [384];
// fp32 intermediates
__device__ float g_X  [RR * CD];             // LN1 output fp32 (residual for LN2)

// ---------------- PTX helpers ----------------
__device__ __forceinline__ void mma_fp16(float d[4], const uint32_t a[4],
                                         const uint32_t b[2]) {
    asm volatile(
        "mma.sync.aligned.m16n8k16.row.col.f32.f16.f16.f32 "
        "{%0,%1,%2,%3}, {%4,%5,%6,%7}, {%8,%9}, {%0,%1,%2,%3};\n"
        : "+f"(d[0]), "+f"(d[1]), "+f"(d[2]), "+f"(d[3])
        : "r"(a[0]), "r"(a[1]), "r"(a[2]), "r"(a[3]),
          "r"(b[0]), "r"(b[1]));
}
__device__ __forceinline__ void ldsm4(uint32_t& r0, uint32_t& r1, uint32_t& r2,
                                      uint32_t& r3, uint32_t addr) {
    asm volatile("ldmatrix.sync.aligned.m8n8.x4.shared.b16 {%0,%1,%2,%3}, [%4];"
                 : "=r"(r0), "=r"(r1), "=r"(r2), "=r"(r3) : "r"(addr));
}
__device__ __forceinline__ void cp_async16(void* s, const void* g) {
    uint32_t sa = (uint32_t)__cvta_generic_to_shared(s);
    asm volatile("cp.async.cg.shared.global [%0], [%1], 16;\n" :: "r"(sa), "l"(g));
}
__device__ __forceinline__ void cp_commit() { asm volatile("cp.async.commit_group;\n"); }
template<int N> __device__ __forceinline__ void cp_wait() {
    asm volatile("cp.async.wait_group %0;\n" :: "n"(N));
}

#define HS 72                           // half stride (64 + 8 pad)

// ================= generic FP16 GEMM (BM=BN=128, 3-stage) =================
#define TILE_HALFS (128 * HS)
#define STAGE_HALFS (2 * TILE_HALFS)
#define TILE_BYTES (TILE_HALFS * 2)
#define STAGE_BYTES (STAGE_HALFS * 2)
#define SMEM_BYTES (3 * STAGE_BYTES)    // 110,592 B

// ---- fused value + QA GEMM: grid (340, 5). y<2 -> value, y>=2 -> off|attn ----
__global__ __launch_bounds__(256, 2)
void vqa_k(const half_t* __restrict__ srcA, const half_t* __restrict__ QA,
           const half_t* __restrict__ WvT, const half_t* __restrict__ WqaT,
           const float* __restrict__ b_val, const float* __restrict__ bqa,
           const unsigned char* __restrict__ mask,
           half_t* __restrict__ VH, half_t* __restrict__ OAH)
{
    extern __shared__ half_t sm[];

    const int tid  = threadIdx.x;
    const int brow = blockIdx.x * 128;
    const int y    = blockIdx.y;
    const bool isV = y < 2;
    const half_t* A   = isV ? srcA : QA;
    const half_t* B   = isV ? WvT : WqaT;
    const float* bias = isV ? b_val : bqa;
    half_t* Out       = isV ? VH : OAH;
    const int Nout    = isV ? 256 : 384;
    const int bcol    = (isV ? y : (y - 2)) * 128;

    const int lane = tid & 31;
    const int wid  = tid >> 5;
    const int wm   = (wid >> 2) * 64;
    const int wn   = (wid & 3) * 32;
    const int gr   = lane >> 2;
    const int gc   = lane & 3;

    const uint32_t smemU = (uint32_t)__cvta_generic_to_shared(sm);
    const uint32_t aOff = ((wm + (lane & 7) + ((lane >> 3) & 1) * 8) * HS
                           + ((lane >> 4) & 1) * 8) * 2;
    const uint32_t bOff = ((wn + (lane & 7) + ((lane >> 4) & 1) * 8) * HS
                           + ((lane >> 3) & 1) * 8) * 2;

    float acc[4][4][4];
#pragma unroll
    for (int i = 0; i < 4; i++)
#pragma unroll
        for (int j = 0; j < 4; j++)
#pragma unroll
            for (int t = 0; t < 4; t++) acc[i][j][t] = 0.f;

    const int K = 256, nch = 4;

    auto issue = [&](int chunk, int stg) {
        const int k0 = chunk << 6;
        half_t* As = sm + stg * STAGE_HALFS;
        half_t* Bs = As + TILE_HALFS;
#pragma unroll
        for (int i = 0; i < 4; i++) {
            int t = tid + i * 256;
            int r = t >> 3, q = (t & 7) << 3;
            cp_async16(As + r * HS + q, A + (size_t)(brow + r) * K + k0 + q);
        }
#pragma unroll
        for (int i = 0; i < 4; i++) {
            int t = tid + i * 256;
            int r = t >> 3, q = (t & 7) << 3;
            cp_async16(Bs + r * HS + q, B + (size_t)(bcol + r) * K + k0 + q);
        }
        cp_commit();
    };

    issue(0, 0);
    issue(1, 1);

    for (int c = 0; c < nch; c++) {
        const int cur = c % 3;
        if (c + 2 < nch) issue(c + 2, (c + 2) % 3);
        else cp_commit();
        cp_wait<2>();
        __syncthreads();

        const uint32_t aBase = smemU + cur * STAGE_BYTES + aOff;
        const uint32_t bBase = smemU + cur * STAGE_BYTES + TILE_BYTES + bOff;
#pragma unroll
        for (int kk = 0; kk < 4; kk++) {
            uint32_t af[4][4], bf[4][2];
#pragma unroll
            for (int mt = 0; mt < 4; mt++)
                ldsm4(af[mt][0], af[mt][1], af[mt][2], af[mt][3],
                      aBase + mt * (16 * HS * 2) + kk * 32);
#pragma unroll
            for (int ntp = 0; ntp < 2; ntp++)
                ldsm4(bf[2 * ntp][0], bf[2 * ntp][1], bf[2 * ntp + 1][0], bf[2 * ntp + 1][1],
                      bBase + ntp * (16 * HS * 2) + kk * 32);
#pragma unroll
            for (int mt = 0; mt < 4; mt++)
#pragma unroll
                for (int nt = 0; nt < 4; nt++)
                    mma_fp16(acc[mt][nt], af[mt], bf[nt]);
        }
        __syncthreads();
    }

#pragma unroll
    for (int mt = 0; mt < 4; mt++) {
        int r0 = brow + wm + mt * 16 + gr;
        int r1 = r0 + 8;
        float ms0 = (isV && mask[r0]) ? 0.f : 1.f;
        float ms1 = (isV && mask[r1]) ? 0.f : 1.f;
#pragma unroll
        for (int nt = 0; nt < 4; nt++) {
            int col = bcol + wn + nt * 8 + gc * 2;
            float2 bi = *reinterpret_cast<const float2*>(&bias[col]);
            float v0 = (acc[mt][nt][0] + bi.x) * ms0;
            float v1 = (acc[mt][nt][1] + bi.y) * ms0;
            float v2 = (acc[mt][nt][2] + bi.x) * ms1;
            float v3 = (acc[mt][nt][3] + bi.y) * ms1;
            *reinterpret_cast<__half2*>(&Out[(size_t)r0 * Nout + col]) = __floats2half2_rn(v0, v1);
            *reinterpret_cast<__half2*>(&Out[(size_t)r1 * Nout + col]) = __floats2half2_rn(v2, v3);
        }
    }
}

// ---- plain GEMM (used for ff1: RELU, half out) ----
template<bool RELU, bool MASK, bool HALF_OUT>
__global__ __launch_bounds__(256, 2)
void hgemm_k(const half_t* __restrict__ A, const half_t* __restrict__ B,
             const float* __restrict__ bias, const unsigned char* __restrict__ mask,
             float* __restrict__ Cf, half_t* __restrict__ Ch, int K, int Nout)
{
    extern __shared__ half_t sm[];

    const int tid  = threadIdx.x;
    const int brow = blockIdx.x * 128;
    const int bcol = blockIdx.y * 128;

    const int lane = tid & 31;
    const int wid  = tid >> 5;
    const int wm   = (wid >> 2) * 64;
    const int wn   = (wid & 3) * 32;
    const int gr   = lane >> 2;
    const int gc   = lane & 3;

    const uint32_t smemU = (uint32_t)__cvta_generic_to_shared(sm);
    const uint32_t aOff = ((wm + (lane & 7) + ((lane >> 3) & 1) * 8) * HS
                           + ((lane >> 4) & 1) * 8) * 2;
    const uint32_t bOff = ((wn + (lane & 7) + ((lane >> 4) & 1) * 8) * HS
                           + ((lane >> 3) & 1) * 8) * 2;

    float acc[4][4][4];
#pragma unroll
    for (int i = 0; i < 4; i++)
#pragma unroll
        for (int j = 0; j < 4; j++)
#pragma unroll
            for (int t = 0; t < 4; t++) acc[i][j][t] = 0.f;

    const int nch = K >> 6;

    auto issue = [&](int chunk, int stg) {
        const int k0 = chunk << 6;
        half_t* As = sm + stg * STAGE_HALFS;
        half_t* Bs = As + TILE_HALFS;
#pragma unroll
        for (int i = 0; i < 4; i++) {
            int t = tid + i * 256;
            int r = t >> 3, q = (t & 7) << 3;
            cp_async16(As + r * HS + q, A + (size_t)(brow + r) * K + k0 + q);
        }
#pragma unroll
        for (int i = 0; i < 4; i++) {
            int t = tid + i * 256;
            int r = t >> 3, q = (t & 7) << 3;
            cp_async16(Bs + r * HS + q, B + (size_t)(bcol + r) * K + k0 + q);
        }
        cp_commit();
    };

    issue(0, 0);
    if (nch > 1) issue(1, 1);
    else cp_commit();

    for (int c = 0; c < nch; c++) {
        const int cur = c % 3;
        if (c + 2 < nch) issue(c + 2, (c + 2) % 3);
        else cp_commit();
        cp_wait<2>();
        __syncthreads();

        const uint32_t aBase = smemU + cur * STAGE_BYTES + aOff;
        const uint32_t bBase = smemU + cur * STAGE_BYTES + TILE_BYTES + bOff;
#pragma unroll
        for (int kk = 0; kk < 4; kk++) {
            uint32_t af[4][4], bf[4][2];
#pragma unroll
            for (int mt = 0; mt < 4; mt++)
                ldsm4(af[mt][0], af[mt][1], af[mt][2], af[mt][3],
                      aBase + mt * (16 * HS * 2) + kk * 32);
#pragma unroll
            for (int ntp = 0; ntp < 2; ntp++)
                ldsm4(bf[2 * ntp][0], bf[2 * ntp][1], bf[2 * ntp + 1][0], bf[2 * ntp + 1][1],
                      bBase + ntp * (16 * HS * 2) + kk * 32);
#pragma unroll
            for (int mt = 0; mt < 4; mt++)
#pragma unroll
                for (int nt = 0; nt < 4; nt++)
                    mma_fp16(acc[mt][nt], af[mt], bf[nt]);
        }
        __syncthreads();
    }

#pragma unroll
    for (int mt = 0; mt < 4; mt++) {
        int r0 = brow + wm + mt * 16 + gr;
        int r1 = r0 + 8;
        float ms0 = 1.f, ms1 = 1.f;
        if (MASK) { ms0 = mask[r0] ? 0.f : 1.f; ms1 = mask[r1] ? 0.f : 1.f; }
#pragma unroll
        for (int nt = 0; nt < 4; nt++) {
            int col = bcol + wn + nt * 8 + gc * 2;
            float2 bi = *reinterpret_cast<const float2*>(&bias[col]);
            float v0 = acc[mt][nt][0] + bi.x;
            float v1 = acc[mt][nt][1] + bi.y;
            float v2 = acc[mt][nt][2] + bi.x;
            float v3 = acc[mt][nt][3] + bi.y;
            if (MASK) { v0 *= ms0; v1 *= ms0; v2 *= ms1; v3 *= ms1; }
            if (RELU) {
                v0 = fmaxf(v0, 0.f); v1 = fmaxf(v1, 0.f);
                v2 = fmaxf(v2, 0.f); v3 = fmaxf(v3, 0.f);
            }
            if (HALF_OUT) {
                *reinterpret_cast<__half2*>(&Ch[(size_t)r0 * Nout + col]) = __floats2half2_rn(v0, v1);
                *reinterpret_cast<__half2*>(&Ch[(size_t)r1 * Nout + col]) = __floats2half2_rn(v2, v3);
            } else {
                *reinterpret_cast<float2*>(&Cf[(size_t)r0 * Nout + col]) = make_float2(v0, v1);
                *reinterpret_cast<float2*>(&Cf[(size_t)r1 * Nout + col]) = make_float2(v2, v3);
            }
        }
    }
}

// ============ fused GEMM + residual + LayerNorm (BM=64, BN=256, 2-stage) ============
#define LN_A_HALFS (64 * HS)
#define LN_B_HALFS (256 * HS)
#define LN_STAGE_HALFS (LN_A_HALFS + LN_B_HALFS)
#define LN_RED_FLOATS (2 * 64 * 8 + 64 * 2)
#define LN_SMEM_BYTES (2 * LN_STAGE_HALFS * 2 + LN_RED_FLOATS * 4)

template<bool WRITE_H>
__global__ __launch_bounds__(256, 2)
void hgemm_ln_k(const half_t* __restrict__ A, const half_t* __restrict__ B,
                const float* __restrict__ bias, const float* __restrict__ Res,
                const float* __restrict__ gam, const float* __restrict__ bet,
                float* __restrict__ Of, half_t* __restrict__ Oh, int K)
{
    extern __shared__ half_t sm[];
    float* red  = reinterpret_cast<float*>(sm + 2 * LN_STAGE_HALFS);
    float* stat = red + 2 * 64 * 8;

    const int tid  = threadIdx.x;
    const int brow = blockIdx.x * 64;

    const int lane = tid & 31;
    const int wid  = tid >> 5;
    const int wn   = wid * 32;
    const int gr   = lane >> 2;
    const int gc   = lane & 3;

    const uint32_t smemU = (uint32_t)__cvta_generic_to_shared(sm);
    const uint32_t aOff = (((lane & 7) + ((lane >> 3) & 1) * 8) * HS
                           + ((lane >> 4) & 1) * 8) * 2;
    const uint32_t bOff = ((wn + (lane & 7) + ((lane >> 4) & 1) * 8) * HS
                           + ((lane >> 3) & 1) * 8) * 2;

    float acc[4][4][4];
#pragma unroll
    for (int i = 0; i < 4; i++)
#pragma unroll
        for (int j = 0; j < 4; j++)
#pragma unroll
            for (int t = 0; t < 4; t++) acc[i][j][t] = 0.f;

    const int nch = K >> 6;

    auto issue = [&](int chunk, int stg) {
        const int k0 = chunk << 6;
        half_t* As = sm + stg * LN_STAGE_HALFS;
        half_t* Bs = As + LN_A_HALFS;
#pragma unroll
        for (int i = 0; i < 2; i++) {
            int t = tid + i * 256;
            int r = t >> 3, q = (t & 7) << 3;
            cp_async16(As + r * HS + q, A + (size_t)(brow + r) * K + k0 + q);
        }
#pragma unroll
        for (int i = 0; i < 8; i++) {
            int t = tid + i * 256;
            int r = t >> 3, q = (t & 7) << 3;
            cp_async16(Bs + r * HS + q, B + (size_t)r * K + k0 + q);
        }
        cp_commit();
    };

    issue(0, 0);

    for (int c = 0; c < nch; c++) {
        const int cur = c & 1;
        if (c + 1 < nch) { issue(c + 1, cur ^ 1); cp_wait<1>(); }
        else cp_wait<0>();
        __syncthreads();

        const uint32_t aBase = smemU + cur * (LN_STAGE_HALFS * 2) + aOff;
        const uint32_t bBase = smemU + cur * (LN_STAGE_HALFS * 2) + LN_A_HALFS * 2 + bOff;
#pragma unroll
        for (int kk = 0; kk < 4; kk++) {
            uint32_t af[4][4], bf[4][2];
#pragma unroll
            for (int mt = 0; mt < 4; mt++)
                ldsm4(af[mt][0], af[mt][1], af[mt][2], af[mt][3],
                      aBase + mt * (16 * HS * 2) + kk * 32);
#pragma unroll
            for (int ntp = 0; ntp < 2; ntp++)
                ldsm4(bf[2 * ntp][0], bf[2 * ntp][1], bf[2 * ntp + 1][0], bf[2 * ntp + 1][1],
                      bBase + ntp * (16 * HS * 2) + kk * 32);
#pragma unroll
            for (int mt = 0; mt < 4; mt++)
#pragma unroll
                for (int nt = 0; nt < 4; nt++)
                    mma_fp16(acc[mt][nt], af[mt], bf[nt]);
        }
        __syncthreads();
    }

#pragma unroll
    for (int mt = 0; mt < 4; mt++) {
        int r0 = mt * 16 + gr, r1 = r0 + 8;
        float s0 = 0.f, q0 = 0.f, s1 = 0.f, q1 = 0.f;
#pragma unroll
        for (int nt = 0; nt < 4; nt++) {
            int col = wn + nt * 8 + gc * 2;
            float2 bi = *reinterpret_cast<const float2*>(&bias[col]);
            float2 e0 = *reinterpret_cast<const float2*>(&Res[(size_t)(brow + r0) * 256 + col]);
            float2 e1 = *reinterpret_cast<const float2*>(&Res[(size_t)(brow + r1) * 256 + col]);
            float v0 = acc[mt][nt][0] + bi.x + e0.x;
            float v1 = acc[mt][nt][1] + bi.y + e0.y;
            float v2 = acc[mt][nt][2] + bi.x + e1.x;
            float v3 = acc[mt][nt][3] + bi.y + e1.y;
            acc[mt][nt][0] = v0; acc[mt][nt][1] = v1;
            acc[mt][nt][2] = v2; acc[mt][nt][3] = v3;
            s0 += v0 + v1; q0 += v0 * v0 + v1 * v1;
            s1 += v2 + v3; q1 += v2 * v2 + v3 * v3;
        }
#pragma unroll
        for (int o = 1; o <= 2; o <<= 1) {
            s0 += __shfl_xor_sync(0xffffffffu, s0, o);
            q0 += __shfl_xor_sync(0xffffffffu, q0, o);
            s1 += __shfl_xor_sync(0xffffffffu, s1, o);
            q1 += __shfl_xor_sync(0xffffffffu, q1, o);
        }
        if (gc == 0) {
            red[r0 * 8 + wid] = s0;  red[512 + r0 * 8 + wid] = q0;
            red[r1 * 8 + wid] = s1;  red[512 + r1 * 8 + wid] = q1;
        }
    }
    __syncthreads();
    if (tid < 64) {
        float s = 0.f, q = 0.f;
#pragma unroll
        for (int w = 0; w < 8; w++) { s += red[tid * 8 + w]; q += red[512 + tid * 8 + w]; }
        float m = s * (1.f / 256.f);
        float var = q * (1.f / 256.f) - m * m;
        stat[tid * 2 + 0] = m;
        stat[tid * 2 + 1] = rsqrtf(var + 1e-5f);
    }
    __syncthreads();

#pragma unroll
    for (int mt = 0; mt < 4; mt++) {
        int r0 = mt * 16 + gr, r1 = r0 + 8;
        float m0 = stat[r0 * 2], iv0 = stat[r0 * 2 + 1];
        float m1 = stat[r1 * 2], iv1 = stat[r1 * 2 + 1];
#pragma unroll
        for (int nt = 0; nt < 4; nt++) {
            int col = wn + nt * 8 + gc * 2;
            float2 gm = *reinterpret_cast<const float2*>(&gam[col]);
            float2 bt = *reinterpret_cast<const float2*>(&bet[col]);
            float o0 = (acc[mt][nt][0] - m0) * iv0 * gm.x + bt.x;
            float o1 = (acc[mt][nt][1] - m0) * iv0 * gm.y + bt.y;
            float o2 = (acc[mt][nt][2] - m1) * iv1 * gm.x + bt.x;
            float o3 = (acc[mt][nt][3] - m1) * iv1 * gm.y + bt.y;
            *reinterpret_cast<float2*>(&Of[(size_t)(brow + r0) * 256 + col]) = make_float2(o0, o1);
            *reinterpret_cast<float2*>(&Of[(size_t)(brow + r1) * 256 + col]) = make_float2(o2, o3);
            if (WRITE_H) {
                *reinterpret_cast<__half2*>(&Oh[(size_t)(brow + r0) * 256 + col]) = __floats2half2_rn(o0, o1);
                *reinterpret_cast<__half2*>(&Oh[(size_t)(brow + r1) * 256 + col]) = __floats2half2_rn(o2, o3);
            }
        }
    }
}

// ---------------- merged prep: all weight transposes + bias concat ----------------
__global__ void prep_k(const float* __restrict__ w_val, const float* __restrict__ w_off,
                       const float* __restrict__ w_attn, const float* __restrict__ w_out,
                       const float* __restrict__ w_ff1, const float* __restrict__ w_ff2,
                       const float* __restrict__ b_off, const float* __restrict__ b_attn,
                       half_t* __restrict__ WvT, half_t* __restrict__ WqaT,
                       half_t* __restrict__ WuT, half_t* __restrict__ W1T,
                       half_t* __restrict__ W2T, float* __restrict__ bqa)
{
    int idx = blockIdx.x * blockDim.x + threadIdx.x;
    auto tr = [](const float* w, half_t* o, int i, int K, int N) {
        int n = i / K, k = i % K;
        o[i] = __float2half_rn(w[(size_t)k * N + n]);
    };
    if (idx < 65536)                { tr(w_val,  WvT,              idx, 256,  256);  return; }
    if ((idx -= 65536) < 65536)     { tr(w_off,  WqaT,             idx, 256,  256);  return; }
    if ((idx -= 65536) < 32768)     { tr(w_attn, WqaT + 256 * CD,  idx, 256,  128);  return; }
    if ((idx -= 32768) < 65536)     { tr(w_out,  WuT,              idx, 256,  256);  return; }
    if ((idx -= 65536) < 262144)    { tr(w_ff1,  W1T,              idx, 256,  1024); return; }
    if ((idx -= 262144) < 262144)   { tr(w_ff2,  W2T,              idx, 1024, 256);  return; }
    idx -= 262144;
    if (idx < 256)      bqa[idx] = b_off[idx];
    else if (idx < 384) bqa[idx] = b_attn[idx - 256];
}

// ---------------- addvec: srcH = h(src); QH = h(src+pos) ----------------
__global__ void addvec_k(const float* __restrict__ a, const float* __restrict__ b,
                         half_t* __restrict__ sh, half_t* __restrict__ qh)
{
    int i = blockIdx.x * blockDim.x + threadIdx.x;
    float4 x = reinterpret_cast<const float4*>(a)[i];
    float4 y = reinterpret_cast<const float4*>(b)[i];
    __half2 s0 = __floats2half2_rn(x.x, x.y);
    __half2 s1 = __floats2half2_rn(x.z, x.w);
    __half2 q0 = __floats2half2_rn(x.x + y.x, x.y + y.y);
    __half2 q1 = __floats2half2_rn(x.z + y.z, x.w + y.w);
    reinterpret_cast<__half2*>(sh)[i * 2 + 0] = s0;
    reinterpret_cast<__half2*>(sh)[i * 2 + 1] = s1;
    reinterpret_cast<__half2*>(qh)[i * 2 + 0] = q0;
    reinterpret_cast<__half2*>(qh)[i * 2 + 1] = q1;
}

// ---------------- deformable sampling: owner-lane coords + half2 accumulation -----
// block = 256 threads = 8 warps = 8 rows. lane>>2 = head, co = lane&3.
// Lane co owns samples s = co + 4j (level j): computes coords/weights once,
// broadcasts (wA, wB, meta) via 3 shfls per sample.
__global__ void deform_k(const half_t* __restrict__ V, const half_t* __restrict__ OA,
                         const float* __restrict__ REF, half_t* __restrict__ OUT)
{
    const int tid  = threadIdx.x;
    const int w    = tid >> 5;
    const int lane = tid & 31;
    const int row  = blockIdx.x * 8 + w;
    const int h    = lane >> 2;
    const int co   = lane & 3;
    const int gb   = lane & 28;
    const int n    = row / LQN;

    // softmax: lane co owns logits co, co+4, co+8, co+12 (= its samples' probs)
    const half_t* lgp = OA + (size_t)row * 384 + 256 + h * 16;
    float l0 = __half2float(lgp[co]),     l1 = __half2float(lgp[co + 4]);
    float l2 = __half2float(lgp[co + 8]), l3 = __half2float(lgp[co + 12]);
    float mx = fmaxf(fmaxf(l0, l1), fmaxf(l2, l3));
#pragma unroll
    for (int o = 2; o; o >>= 1) mx = fmaxf(mx, __shfl_xor_sync(0xffffffffu, mx, o));
    float e0 = expf(l0 - mx), e1 = expf(l1 - mx), e2 = expf(l2 - mx), e3 = expf(l3 - mx);
    float sum = e0 + e1 + e2 + e3;
#pragma unroll
    for (int o = 2; o; o >>= 1) sum += __shfl_xor_sync(0xffffffffu, sum, o);
    float inv = 1.f / sum;
    float pj[4] = {e0 * inv, e1 * inv, e2 * inv, e3 * inv};

    const half_t* off = OA + (size_t)row * 384 + h * 32;
    const float*  ref = REF + (size_t)row * 8;
    const half_t* Vb  = V + (size_t)n * LQN * 256 + h * 32 + 8 * co;

    const int Wt[4] = {64, 32, 16, 8};
    const int St[4] = {0, 4096, 5120, 5376};
    const float invW[4] = {1.f/64.f, 1.f/32.f, 1.f/16.f, 1.f/8.f};

    // owner precompute: sample s = co + 4j (level j)
    uint32_t wAs[4], wBs[4];
    int metas[4];
#pragma unroll
    for (int j = 0; j < 4; j++) {
        const int W = Wt[j], H = Wt[j];
        __half2 o2 = *reinterpret_cast<const __half2*>(off + 2 * (co + 4 * j));
        float2 od = __half22float2(o2);
        float rx = ref[j * 2 + 0], ry = ref[j * 2 + 1];
        float lx = rx + od.x * invW[j];
        float ly = ry + od.y * invW[j];
        float gx = 2.f * lx - 1.f, gy = 2.f * ly - 1.f;
        float x = (gx + 1.f) * (W * 0.5f) - 0.5f;
        float y = (gy + 1.f) * (H * 0.5f) - 0.5f;
        float x0f = floorf(x), y0f = floorf(y);
        float wx = x - x0f, wy = y - y0f;
        int x0 = (int)x0f, y0 = (int)y0f;
        float a = pj[j];
        int vb = ((x0 >= 0  && x0 < W     && y0 >= 0  && y0 < H)     ? 1 : 0)
               | ((x0 >= -1 && x0 < W - 1 && y0 >= 0  && y0 < H)     ? 2 : 0)
               | ((x0 >= 0  && x0 < W     && y0 >= -1 && y0 < H - 1) ? 4 : 0)
               | ((x0 >= -1 && x0 < W - 1 && y0 >= -1 && y0 < H - 1) ? 8 : 0);
        float w00 = (1.f - wx) * (1.f - wy) * a;
        float w10 = wx * (1.f - wy) * a;
        float w01 = (1.f - wx) * wy * a;
        float w11 = wx * wy * a;
        __half2 hA = __floats2half2_rn(w00, w10);
        __half2 hB = __floats2half2_rn(w01, w11);
        wAs[j] = *reinterpret_cast<uint32_t*>(&hA);
        wBs[j] = *reinterpret_cast<uint32_t*>(&hB);
        metas[j] = ((y0 * W + x0) + 8192) | (vb << 14);
    }

    float a0 = 0.f, a1 = 0.f, a2 = 0.f, a3 = 0.f;
    float a4 = 0.f, a5 = 0.f, a6 = 0.f, a7 = 0.f;
    const __half2 hz = __floats2half2_rn(0.f, 0.f);
#pragma unroll
    for (int s = 0; s < 16; s++) {
        const int l = s >> 2;
        const int W = Wt[l];
        const half_t* Vl = Vb + (size_t)St[l] * 256;
        const int src = gb | (s & 3);
        uint32_t wa = __shfl_sync(0xffffffffu, wAs[l], src);
        uint32_t wb = __shfl_sync(0xffffffffu, wBs[l], src);
        int m = __shfl_sync(0xffffffffu, metas[l], src);
        int idx00 = (m & 0x3FFF) - 8192;
        int vb = (m >> 14) & 15;
        __half2 wav = *reinterpret_cast<__half2*>(&wa);
        __half2 wbv = *reinterpret_cast<__half2*>(&wb);
        __half2 h00 = __half2half2(__low2half(wav));
        __half2 h10 = __half2half2(__high2half(wav));
        __half2 h01 = __half2half2(__low2half(wbv));
        __half2 h11 = __half2half2(__high2half(wbv));
        __half2 s0 = hz, s1 = hz, s2 = hz, s3 = hz;
        if (vb & 1) {
            uint4 u = *reinterpret_cast<const uint4*>(Vl + (size_t)idx00 * 256);
            s0 = __hfma2(h00, *reinterpret_cast<__half2*>(&u.x), s0);
            s1 = __hfma2(h00, *reinterpret_cast<__half2*>(&u.y), s1);
            s2 = __hfma2(h00, *reinterpret_cast<__half2*>(&u.z), s2);
            s3 = __hfma2(h00, *reinterpret_cast<__half2*>(&u.w), s3);
        }
        if (vb & 2) {
            uint4 u = *reinterpret_cast<const uint4*>(Vl + (size_t)(idx00 + 1) * 256);
            s0 = __hfma2(h10, *reinterpret_cast<__half2*>(&u.x), s0);
            s1 = __hfma2(h10, *reinterpret_cast<__half2*>(&u.y), s1);
            s2 = __hfma2(h10, *reinterpret_cast<__half2*>(&u.z), s2);
            s3 = __hfma2(h10, *reinterpret_cast<__half2*>(&u.w), s3);
        }
        if (vb & 4) {
            uint4 u = *reinterpret_cast<const uint4*>(Vl + (size_t)(idx00 + W) * 256);
            s0 = __hfma2(h01, *reinterpret_cast<__half2*>(&u.x), s0);
            s1 = __hfma2(h01, *reinterpret_cast<__half2*>(&u.y), s1);
            s2 = __hfma2(h01, *reinterpret_cast<__half2*>(&u.z), s2);
            s3 = __hfma2(h01, *reinterpret_cast<__half2*>(&u.w), s3);
        }
        if (vb & 8) {
            uint4 u = *reinterpret_cast<const uint4*>(Vl + (size_t)(idx00 + W + 1) * 256);
            s0 = __hfma2(h11, *reinterpret_cast<__half2*>(&u.x), s0);
            s1 = __hfma2(h11, *reinterpret_cast<__half2*>(&u.y), s1);
            s2 = __hfma2(h11, *reinterpret_cast<__half2*>(&u.z), s2);
            s3 = __hfma2(h11, *reinterpret_cast<__half2*>(&u.w), s3);
        }
        float2 f;
        f = __half22float2(s0); a0 += f.x; a1 += f.y;
        f = __half22float2(s1); a2 += f.x; a3 += f.y;
        f = __half22float2(s2); a4 += f.x; a5 += f.y;
        f = __half22float2(s3); a6 += f.x; a7 += f.y;
    }

    half_t* dst = &OUT[(size_t)row * 256 + h * 32 + 8 * co];
    __half2 o0 = __floats2half2_rn(a0, a1);
    __half2 o1 = __floats2half2_rn(a2, a3);
    __half2 o2 = __floats2half2_rn(a4, a5);
    __half2 o3 = __floats2half2_rn(a6, a7);
    uint4 outv;
    outv.x = *reinterpret_cast<uint32_t*>(&o0);
    outv.y = *reinterpret_cast<uint32_t*>(&o1);
    outv.z = *reinterpret_cast<uint32_t*>(&o2);
    outv.w = *reinterpret_cast<uint32_t*>(&o3);
    *reinterpret_cast<uint4*>(dst) = outv;
}

// ---------------- launch ----------------
extern "C" void kernel_launch(void* const* d_in, const int* in_sizes, int n_in,
                              void* d_out, int out_size)
{
    const float* src    = (const float*)d_in[0];
    const float* pos    = (const float*)d_in[1];
    const float* ref    = (const float*)d_in[2];
    const float* w_off  = (const float*)d_in[3];
    const float* b_off  = (const float*)d_in[4];
    const float* w_attn = (const float*)d_in[5];
    const float* b_attn = (const float*)d_in[6];
    const float* w_val  = (const float*)d_in[7];
    const float* b_val  = (const float*)d_in[8];
    const float* w_out  = (const float*)d_in[9];
    const float* b_out  = (const float*)d_in[10];
    const float* g1     = (const float*)d_in[11];
    const float* be1    = (const float*)d_in[12];
    const float* w_ff1  = (const float*)d_in[13];
    const float* b_ff1  = (const float*)d_in[14];
    const float* w_ff2  = (const float*)d_in[15];
    const float* b_ff2  = (const float*)d_in[16];
    const float* g2     = (const float*)d_in[17];
    const float* be2    = (const float*)d_in[18];
    const unsigned char* mask = (const unsigned char*)d_in[19];

    half_t *srcH, *QH, *VH, *ATTH, *XH, *HH, *OAH, *WvT, *WqaT, *WuT, *W1T, *W2T;
    float *pX, *pbqa;
    cudaGetSymbolAddress((void**)&srcH, g_srcH);
    cudaGetSymbolAddress((void**)&QH,   g_QH);
    cudaGetSymbolAddress((void**)&VH,   g_VH);
    cudaGetSymbolAddress((void**)&ATTH, g_ATTH);
    cudaGetSymbolAddress((void**)&XH,   g_XH);
    cudaGetSymbolAddress((void**)&HH,   g_HH);
    cudaGetSymbolAddress((void**)&OAH,  g_OAh);
    cudaGetSymbolAddress((void**)&WvT,  g_WvT);
    cudaGetSymbolAddress((void**)&WqaT, g_WqaT);
    cudaGetSymbolAddress((void**)&WuT,  g_WuT);
    cudaGetSymbolAddress((void**)&W1T,  g_W1T);
    cudaGetSymbolAddress((void**)&W2T,  g_W2T);
    cudaGetSymbolAddress((void**)&pX,   g_X);
    cudaGetSymbolAddress((void**)&pbqa, g_bqa);

    cudaFuncSetAttribute(vqa_k, cudaFuncAttributeMaxDynamicSharedMemorySize, SMEM_BYTES);
    cudaFuncSetAttribute(hgemm_k<true,  false, true >, cudaFuncAttributeMaxDynamicSharedMemorySize, SMEM_BYTES);
    cudaFuncSetAttribute(hgemm_ln_k<true >, cudaFuncAttributeMaxDynamicSharedMemorySize, LN_SMEM_BYTES);
    cudaFuncSetAttribute(hgemm_ln_k<false>, cudaFuncAttributeMaxDynamicSharedMemorySize, LN_SMEM_BYTES);

    addvec_k<<<RR * CD / 4 / 256, 256>>>(src, pos, srcH, QH);
    prep_k<<<(754048 + 255) / 256, 256>>>(w_val, w_off, w_attn, w_out, w_ff1, w_ff2,
                                          b_off, b_attn, WvT, WqaT, WuT, W1T, W2T, pbqa);

    // fused: value (y<2) + [off|attn] (y>=2), both fp16 out
    vqa_k<<<dim3(340, 5), 256, SMEM_BYTES>>>(
        srcH, QH, WvT, WqaT, b_val, pbqa, mask, VH, OAH);
    deform_k<<<RR / 8, 256>>>(VH, OAH, ref, ATTH);
    // X = LN1(src + ATT @ w_out + b_out)  -> pX fp32 + XH fp16
    hgemm_ln_k<true ><<<680, 256, LN_SMEM_BYTES>>>(
        ATTH, WuT, b_out, src, g1, be1, pX, XH, 256);
    // H = relu(X @ w_ff1 + b_ff1) -> fp16
    hgemm_k<true,  false, true ><<<dim3(340, 8), 256, SMEM_BYTES>>>(
        XH, W1T, b_ff1, nullptr, nullptr, HH, 256, 1024);
    // out = LN2(X + H @ w_ff2 + b_ff2)
    hgemm_ln_k<false><<<680, 256, LN_SMEM_BYTES>>>(
        HH, W2T, b_ff2, pX, g2, be2, (float*)d_out, nullptr, 1024);
}